// round 1
// baseline (speedup 1.0000x reference)
#include <cuda_runtime.h>
#include <math.h>

// Problem constants (fixed by the dataset)
#define NDT 30000
#define NOD 10000
#define EL_MAX 200000

static inline int cdiv(long long a, long long b) { return (int)((a + b - 1) / b); }

// ---------------- device scratch (allocation-free rule: __device__ globals) ----
__device__ float g_acc1[NDT * 128];
__device__ float g_acc2[NOD * 128];
__device__ float g_acc3[NDT * 128];
__device__ float g_cnt_dt[NDT];
__device__ float g_inv_dt[NDT];
__device__ float g_cnt_od[NOD];
__device__ float g_inv_od[NOD];
__device__ float g_h [NDT * 128];
__device__ float g_d1[NDT * 128];
__device__ float g_od2[NOD * 128];
__device__ float g_od3[NOD * 128];
__device__ float g_zod[NOD * 64];
__device__ float g_d2[NDT * 128];
__device__ float g_zdt[NDT * 64];
__device__ float g_u[EL_MAX * 128];
__device__ float g_v[EL_MAX * 64];

// ---------------- utility kernels ---------------------------------------------
__global__ void k_zero(float* __restrict__ p, int n) {
    int i = blockIdx.x * blockDim.x + threadIdx.x;
    if (i < n) p[i] = 0.f;
}

__global__ void k_inv(const float* __restrict__ cnt, float* __restrict__ inv, int n) {
    int i = blockIdx.x * blockDim.x + threadIdx.x;
    if (i < n) inv[i] = 1.f / fmaxf(cnt[i], 1.f);
}

// Scatter-add rows of X (width 128) into acc via (src -> dst) edges; one warp/edge.
__global__ void k_scatter(const float* __restrict__ X,
                          const int* __restrict__ src, const int* __restrict__ dst,
                          int E, float* __restrict__ acc, float* __restrict__ cnt) {
    long long gid = (long long)blockIdx.x * blockDim.x + threadIdx.x;
    int e = (int)(gid >> 5);
    if (e >= E) return;
    int lane = (int)(gid & 31);
    int s = __ldg(src + e);
    int d = __ldg(dst + e);
    float4 v = *(const float4*)(X + (size_t)s * 128 + lane * 4);
    float* o = acc + (size_t)d * 128 + lane * 4;
    atomicAdd(o + 0, v.x);
    atomicAdd(o + 1, v.y);
    atomicAdd(o + 2, v.z);
    atomicAdd(o + 3, v.w);
    if (cnt != nullptr && lane == 0) atomicAdd(cnt + d, 1.f);
}

// Gather-concat decoder inputs: u[e] = [zod[el_src[e]] (64) | zdt[el_dst[e]] (64)]
__global__ void k_gather(const float* __restrict__ zod, const float* __restrict__ zdt,
                         const int* __restrict__ esrc, const int* __restrict__ edst,
                         float* __restrict__ U, int E) {
    long long gid = (long long)blockIdx.x * blockDim.x + threadIdx.x;
    int e = (int)(gid >> 5);
    if (e >= E) return;
    int lane = (int)(gid & 31);
    float4 val;
    if (lane < 16) {
        int si = __ldg(esrc + e);
        val = ((const float4*)(zod + (size_t)si * 64))[lane];
    } else {
        int di = __ldg(edst + e);
        val = ((const float4*)(zdt + (size_t)di * 64))[lane - 16];
    }
    ((float4*)(U + (size_t)e * 128))[lane] = val;
}

// out[e] = sigmoid(dot(v[e], w2) + b2); one warp per edge.
__global__ void k_final(const float* __restrict__ V, const float* __restrict__ w2,
                        const float* __restrict__ b2p, float* __restrict__ out, int E) {
    long long gid = (long long)blockIdx.x * blockDim.x + threadIdx.x;
    int e = (int)(gid >> 5);
    if (e >= E) return;
    int lane = (int)(gid & 31);
    const float* v = V + (size_t)e * 64;
    float s = v[lane] * __ldg(w2 + lane) + v[lane + 32] * __ldg(w2 + lane + 32);
#pragma unroll
    for (int o = 16; o > 0; o >>= 1) s += __shfl_down_sync(0xffffffffu, s, o);
    if (lane == 0) out[e] = 1.f / (1.f + expf(-(s + b2p[0])));
}

// ---------------- fused dual GEMM:  Y = act( diag(rowscale)*A @ W1 + B @ W2 + bias )
// A: [M,K1], B: [M,K2] (optional), W: [K,NCOLS], Y: [M,NCOLS]
// Tile: 128 rows x NCOLS cols, 256 threads, micro-tile 8 x (NCOLS/16) per thread.
template <int NCOLS>
__global__ __launch_bounds__(256)
void gemm_dual(int M,
               const float* __restrict__ A, const float* __restrict__ rowscale, int K1,
               const float* __restrict__ B, int K2,
               const float* __restrict__ W1, const float* __restrict__ W2,
               const float* __restrict__ bias, float* __restrict__ Y, int do_relu) {
    constexpr int BR = 128;
    constexpr int KC = 16;
    constexpr int TN = NCOLS / 16;  // 8 for N=128, 4 for N=64
    __shared__ __align__(16) float As[KC][BR];
    __shared__ __align__(16) float Ws[KC][NCOLS];

    const int t = threadIdx.x;
    const int ti = t >> 4;          // 0..15 (row group of 8)
    const int tj = t & 15;          // 0..15 (col group of TN)
    const int row0 = blockIdx.x * BR;
    const int lr = t >> 1;          // A-load: row within tile (0..127)
    const int lk = (t & 1) * 8;     // A-load: k offset (0 or 8)
    const int grow = row0 + lr;

    float acc[8][TN];
#pragma unroll
    for (int i = 0; i < 8; i++)
#pragma unroll
        for (int j = 0; j < TN; j++) acc[i][j] = 0.f;

#pragma unroll 1
    for (int phase = 0; phase < 2; ++phase) {
        const float* Xp = phase ? B : A;
        const float* Wp = phase ? W2 : W1;
        const int K = phase ? K2 : K1;
        if (K == 0 || Xp == nullptr) continue;
        const float sc = (phase == 0 && rowscale != nullptr && grow < M) ? rowscale[grow] : 1.f;

        for (int k0 = 0; k0 < K; k0 += KC) {
            __syncthreads();  // previous chunk's compute done before overwrite
            // stage A chunk (transposed: As[k][r]), with optional row scale
            float4 v0 = make_float4(0.f, 0.f, 0.f, 0.f), v1 = v0;
            if (grow < M) {
                const float* base = Xp + (size_t)grow * K + k0 + lk;
                v0 = *(const float4*)(base);
                v1 = *(const float4*)(base + 4);
            }
            As[lk + 0][lr] = v0.x * sc;
            As[lk + 1][lr] = v0.y * sc;
            As[lk + 2][lr] = v0.z * sc;
            As[lk + 3][lr] = v0.w * sc;
            As[lk + 4][lr] = v1.x * sc;
            As[lk + 5][lr] = v1.y * sc;
            As[lk + 6][lr] = v1.z * sc;
            As[lk + 7][lr] = v1.w * sc;
            // stage W chunk
            {
                const int kk = t >> 4;
                const int c = (t & 15) * TN;
#pragma unroll
                for (int j = 0; j < TN; j += 4) {
                    float4 w = *(const float4*)(Wp + (size_t)(k0 + kk) * NCOLS + c + j);
                    *(float4*)&Ws[kk][c + j] = w;
                }
            }
            __syncthreads();
            // compute
#pragma unroll
            for (int kk = 0; kk < KC; kk++) {
                float a[8];
                *(float4*)&a[0] = *(const float4*)&As[kk][ti * 8];
                *(float4*)&a[4] = *(const float4*)&As[kk][ti * 8 + 4];
                float w[TN];
#pragma unroll
                for (int j = 0; j < TN; j += 4)
                    *(float4*)&w[j] = *(const float4*)&Ws[kk][tj * TN + j];
#pragma unroll
                for (int i = 0; i < 8; i++)
#pragma unroll
                    for (int j = 0; j < TN; j++) acc[i][j] += a[i] * w[j];
            }
        }
    }

    // epilogue: bias + activation + store
    float bb[TN];
#pragma unroll
    for (int j = 0; j < TN; j++) bb[j] = (bias != nullptr) ? bias[tj * TN + j] : 0.f;
#pragma unroll
    for (int i = 0; i < 8; i++) {
        int r = row0 + ti * 8 + i;
        if (r < M) {
            float o[TN];
#pragma unroll
            for (int j = 0; j < TN; j++) {
                float y = acc[i][j] + bb[j];
                o[j] = do_relu ? fmaxf(y, 0.f) : y;
            }
#pragma unroll
            for (int j = 0; j < TN; j += 4)
                *(float4*)(Y + (size_t)r * NCOLS + tj * TN + j) = *(const float4*)&o[j];
        }
    }
}

// ---------------- host orchestration ------------------------------------------
extern "C" void kernel_launch(void* const* d_in, const int* in_sizes, int n_in,
                              void* d_out, int out_size) {
    const float* x_dt   = (const float*)d_in[0];
    const float* x_od   = (const float*)d_in[1];
    const int*   ei_dt  = (const int*)  d_in[2];
    const int*   rsrc   = (const int*)  d_in[3];
    const int*   rdst   = (const int*)  d_in[4];
    const int*   elsrc  = (const int*)  d_in[5];
    const int*   eldst  = (const int*)  d_in[6];
    const float* od1_wl = (const float*)d_in[7];
    const float* od1_wr = (const float*)d_in[8];
    const float* od1_b  = (const float*)d_in[9];
    const float* od2_wl = (const float*)d_in[10];
    const float* od2_wr = (const float*)d_in[11];
    const float* od2_b  = (const float*)d_in[12];
    const float* od3_wl = (const float*)d_in[13];
    const float* od3_wr = (const float*)d_in[14];
    const float* od3_b  = (const float*)d_in[15];
    const float* od_lw  = (const float*)d_in[16];
    const float* od_lb  = (const float*)d_in[17];
    const float* dt1_wl = (const float*)d_in[18];
    const float* dt1_wr = (const float*)d_in[19];
    const float* dt1_b  = (const float*)d_in[20];
    const float* dt2_wl = (const float*)d_in[21];
    const float* dt2_wr = (const float*)d_in[22];
    const float* dt2_b  = (const float*)d_in[23];
    const float* dt_lw  = (const float*)d_in[24];
    const float* dt_lb  = (const float*)d_in[25];
    const float* dec_w1 = (const float*)d_in[26];
    const float* dec_b1 = (const float*)d_in[27];
    const float* dec_w2 = (const float*)d_in[28];
    const float* dec_b2 = (const float*)d_in[29];
    float* out = (float*)d_out;

    const int E1 = in_sizes[2] / 2;
    const int E2 = in_sizes[3];
    const int EL = in_sizes[5];
    const int* r1 = ei_dt;
    const int* c1 = ei_dt + E1;

    float *acc1, *acc2, *acc3, *cntdt, *invdt, *cntod, *invod;
    float *h, *d1, *od2b, *od3b, *zod, *d2, *zdt, *u, *v;
    cudaGetSymbolAddress((void**)&acc1, g_acc1);
    cudaGetSymbolAddress((void**)&acc2, g_acc2);
    cudaGetSymbolAddress((void**)&acc3, g_acc3);
    cudaGetSymbolAddress((void**)&cntdt, g_cnt_dt);
    cudaGetSymbolAddress((void**)&invdt, g_inv_dt);
    cudaGetSymbolAddress((void**)&cntod, g_cnt_od);
    cudaGetSymbolAddress((void**)&invod, g_inv_od);
    cudaGetSymbolAddress((void**)&h,   g_h);
    cudaGetSymbolAddress((void**)&d1,  g_d1);
    cudaGetSymbolAddress((void**)&od2b, g_od2);
    cudaGetSymbolAddress((void**)&od3b, g_od3);
    cudaGetSymbolAddress((void**)&zod, g_zod);
    cudaGetSymbolAddress((void**)&d2,  g_d2);
    cudaGetSymbolAddress((void**)&zdt, g_zdt);
    cudaGetSymbolAddress((void**)&u,   g_u);
    cudaGetSymbolAddress((void**)&v,   g_v);

    const int TB = 256;

    // zero accumulators + counts
    k_zero<<<cdiv(NDT * 128, TB), TB>>>(acc1, NDT * 128);
    k_zero<<<cdiv(NOD * 128, TB), TB>>>(acc2, NOD * 128);
    k_zero<<<cdiv(NDT * 128, TB), TB>>>(acc3, NDT * 128);
    k_zero<<<cdiv(NDT, TB), TB>>>(cntdt, NDT);
    k_zero<<<cdiv(NOD, TB), TB>>>(cntod, NOD);

    // agg(x_dt) over dt graph (shared by od1 and dt1), plus degree counts
    k_scatter<<<cdiv((long long)E1 * 32, TB), TB>>>(x_dt, r1, c1, E1, acc1, cntdt);
    k_inv<<<cdiv(NDT, TB), TB>>>(cntdt, invdt, NDT);

    // h = relu(agg @ od1_wl + x_dt @ od1_wr + b) ; d1 = relu(agg @ dt1_wl + x_dt @ dt1_wr + b)
    gemm_dual<128><<<cdiv(NDT, 128), 256>>>(NDT, acc1, invdt, 128, x_dt, 128,
                                            od1_wl, od1_wr, od1_b, h, 1);
    gemm_dual<128><<<cdiv(NDT, 128), 256>>>(NDT, acc1, invdt, 128, x_dt, 128,
                                            dt1_wl, dt1_wr, dt1_b, d1, 1);

    // agg(h) over rev edges (shared by od2 and od3)
    k_scatter<<<cdiv((long long)E2 * 32, TB), TB>>>(h, rsrc, rdst, E2, acc2, cntod);
    k_inv<<<cdiv(NOD, TB), TB>>>(cntod, invod, NOD);

    gemm_dual<128><<<cdiv(NOD, 128), 256>>>(NOD, acc2, invod, 128, x_od, 64,
                                            od2_wl, od2_wr, od2_b, od2b, 1);
    gemm_dual<128><<<cdiv(NOD, 128), 256>>>(NOD, acc2, invod, 128, od2b, 128,
                                            od3_wl, od3_wr, od3_b, od3b, 1);
    gemm_dual<64><<<cdiv(NOD, 128), 256>>>(NOD, od3b, nullptr, 128, nullptr, 0,
                                           od_lw, nullptr, od_lb, zod, 0);

    // agg(d1) over dt graph (same degree counts as before)
    k_scatter<<<cdiv((long long)E1 * 32, TB), TB>>>(d1, r1, c1, E1, acc3, nullptr);
    gemm_dual<128><<<cdiv(NDT, 128), 256>>>(NDT, acc3, invdt, 128, d1, 128,
                                            dt2_wl, dt2_wr, dt2_b, d2, 1);
    gemm_dual<64><<<cdiv(NDT, 128), 256>>>(NDT, d2, nullptr, 128, nullptr, 0,
                                           dt_lw, nullptr, dt_lb, zdt, 0);

    // edge decoder
    k_gather<<<cdiv((long long)EL * 32, TB), TB>>>(zod, zdt, elsrc, eldst, u, EL);
    gemm_dual<64><<<cdiv(EL, 128), 256>>>(EL, u, nullptr, 128, nullptr, 0,
                                          dec_w1, nullptr, dec_b1, v, 1);
    k_final<<<cdiv((long long)EL * 32, TB), TB>>>(v, dec_w2, dec_b2, out, EL);
}

// round 2
// speedup vs baseline: 1.5056x; 1.5056x over previous
#include <cuda_runtime.h>
#include <math.h>

// Problem constants (fixed by the dataset)
#define NDT 30000
#define NOD 10000

static inline int cdiv(long long a, long long b) { return (int)((a + b - 1) / b); }

// ---------------- packed f32x2 helpers (sm_103a FFMA2) -------------------------
#define FMA2(acc, a, b) \
    asm("fma.rn.f32x2 %0, %1, %2, %0;" : "+l"(acc) : "l"(a), "l"(b))
#define PACK2_DUP(d, x) \
    asm("mov.b64 %0, {%1, %1};" : "=l"(d) : "r"(__float_as_uint(x)))
#define UNPACK2(lo, hi, v) \
    asm("mov.b64 {%0, %1}, %2;" : "=r"(lo), "=r"(hi) : "l"(v))

// ---------------- device scratch (allocation-free rule: __device__ globals) ----
__device__ float g_acc1[NDT * 128];
__device__ float g_acc2[NOD * 128];
__device__ float g_acc3[NDT * 128];
__device__ float g_cnt_dt[NDT];
__device__ float g_inv_dt[NDT];
__device__ float g_cnt_od[NOD];
__device__ float g_inv_od[NOD];
__device__ float g_h [NDT * 128];
__device__ float g_d1[NDT * 128];
__device__ float g_od2[NOD * 128];
__device__ float g_od3[NOD * 128];
__device__ float g_zod[NOD * 64];
__device__ float g_d2[NDT * 128];
__device__ float g_zdt[NDT * 64];

// ---------------- utility kernels ---------------------------------------------
__global__ void k_inv(const float* __restrict__ cnt, float* __restrict__ inv, int n) {
    int i = blockIdx.x * blockDim.x + threadIdx.x;
    if (i < n) inv[i] = 1.f / fmaxf(cnt[i], 1.f);
}

// Scatter-add rows of X (width 128) into acc via (src -> dst); one warp/edge,
// vector red.global.add.v4.f32 (1 instr per 16B instead of 4 scalar atomics).
__global__ void k_scatter(const float* __restrict__ X,
                          const int* __restrict__ src, const int* __restrict__ dst,
                          int E, float* __restrict__ acc, float* __restrict__ cnt) {
    long long gid = (long long)blockIdx.x * blockDim.x + threadIdx.x;
    int e = (int)(gid >> 5);
    if (e >= E) return;
    int lane = (int)(gid & 31);
    int s = __ldg(src + e);
    int d = __ldg(dst + e);
    float4 v = *(const float4*)(X + (size_t)s * 128 + lane * 4);
    float* o = acc + (size_t)d * 128 + lane * 4;
    asm volatile("red.global.add.v4.f32 [%0], {%1, %2, %3, %4};"
                 :: "l"(o), "f"(v.x), "f"(v.y), "f"(v.z), "f"(v.w) : "memory");
    if (cnt != nullptr && lane == 0) atomicAdd(cnt + d, 1.f);
}

// ---------------- fused dual GEMM:  Y = act( diag(rowscale)*A @ W1 + B @ W2 + bias )
// A:[M,K1], B:[M,K2] (optional), W:[K,NCOLS], Y:[M,NCOLS]. FFMA2 inner loop.
template <int NCOLS>
__global__ __launch_bounds__(256)
void gemm_dual(int M,
               const float* __restrict__ A, const float* __restrict__ rowscale, int K1,
               const float* __restrict__ B, int K2,
               const float* __restrict__ W1, const float* __restrict__ W2,
               const float* __restrict__ bias, float* __restrict__ Y, int do_relu) {
    constexpr int BR = 128;
    constexpr int KC = 16;
    constexpr int TN = NCOLS / 16;   // 8 for N=128, 4 for N=64
    constexpr int TN2 = TN / 2;
    __shared__ __align__(16) float As[KC][BR];
    __shared__ __align__(16) float Ws[KC][NCOLS];

    const int t = threadIdx.x;
    const int ti = t >> 4;
    const int tj = t & 15;
    const int row0 = blockIdx.x * BR;
    const int lr = t >> 1;
    const int lk = (t & 1) * 8;
    const int grow = row0 + lr;

    unsigned long long acc[8][TN2];
#pragma unroll
    for (int i = 0; i < 8; i++)
#pragma unroll
        for (int j = 0; j < TN2; j++) acc[i][j] = 0ull;

#pragma unroll 1
    for (int phase = 0; phase < 2; ++phase) {
        const float* Xp = phase ? B : A;
        const float* Wp = phase ? W2 : W1;
        const int K = phase ? K2 : K1;
        if (K == 0 || Xp == nullptr) continue;
        const float sc = (phase == 0 && rowscale != nullptr && grow < M) ? rowscale[grow] : 1.f;

        for (int k0 = 0; k0 < K; k0 += KC) {
            __syncthreads();
            float4 v0 = make_float4(0.f, 0.f, 0.f, 0.f), v1 = v0;
            if (grow < M) {
                const float* base = Xp + (size_t)grow * K + k0 + lk;
                v0 = *(const float4*)(base);
                v1 = *(const float4*)(base + 4);
            }
            As[lk + 0][lr] = v0.x * sc;
            As[lk + 1][lr] = v0.y * sc;
            As[lk + 2][lr] = v0.z * sc;
            As[lk + 3][lr] = v0.w * sc;
            As[lk + 4][lr] = v1.x * sc;
            As[lk + 5][lr] = v1.y * sc;
            As[lk + 6][lr] = v1.z * sc;
            As[lk + 7][lr] = v1.w * sc;
            {
                const int kk = t >> 4;
                const int c = (t & 15) * TN;
#pragma unroll
                for (int j = 0; j < TN; j += 4) {
                    float4 w = *(const float4*)(Wp + (size_t)(k0 + kk) * NCOLS + c + j);
                    *(float4*)&Ws[kk][c + j] = w;
                }
            }
            __syncthreads();
#pragma unroll
            for (int kk = 0; kk < KC; kk++) {
                float a[8];
                *(float4*)&a[0] = *(const float4*)&As[kk][ti * 8];
                *(float4*)&a[4] = *(const float4*)&As[kk][ti * 8 + 4];
                unsigned long long a2[8];
#pragma unroll
                for (int i = 0; i < 8; i++) PACK2_DUP(a2[i], a[i]);
                unsigned long long w2[TN2];
                const unsigned long long* wsp =
                    (const unsigned long long*)&Ws[kk][tj * TN];
#pragma unroll
                for (int j = 0; j < TN2; j++) w2[j] = wsp[j];
#pragma unroll
                for (int i = 0; i < 8; i++)
#pragma unroll
                    for (int j = 0; j < TN2; j++) FMA2(acc[i][j], a2[i], w2[j]);
            }
        }
    }

    // epilogue
    float bb[TN];
#pragma unroll
    for (int j = 0; j < TN; j++) bb[j] = (bias != nullptr) ? bias[tj * TN + j] : 0.f;
#pragma unroll
    for (int i = 0; i < 8; i++) {
        int r = row0 + ti * 8 + i;
        if (r < M) {
            float o[TN];
#pragma unroll
            for (int j = 0; j < TN2; j++) {
                unsigned int lo, hi;
                UNPACK2(lo, hi, acc[i][j]);
                float ylo = __uint_as_float(lo) + bb[2 * j];
                float yhi = __uint_as_float(hi) + bb[2 * j + 1];
                o[2 * j]     = do_relu ? fmaxf(ylo, 0.f) : ylo;
                o[2 * j + 1] = do_relu ? fmaxf(yhi, 0.f) : yhi;
            }
#pragma unroll
            for (int j = 0; j < TN; j += 4)
                *(float4*)(Y + (size_t)r * NCOLS + tj * TN + j) = *(const float4*)&o[j];
        }
    }
}

// ---------------- fully fused edge decoder -------------------------------------
// out[e] = sigmoid( relu([zod[esrc[e]] | zdt[edst[e]]] @ W1 + b1) . w2 + b2 )
// Gather fused into A staging; final dot + sigmoid fused into epilogue.
__global__ __launch_bounds__(256)
void dec_fused(int M, const float* __restrict__ zod, const float* __restrict__ zdt,
               const int* __restrict__ esrc, const int* __restrict__ edst,
               const float* __restrict__ W1, const float* __restrict__ b1,
               const float* __restrict__ w2, const float* __restrict__ b2p,
               float* __restrict__ out) {
    constexpr int NC = 64;
    constexpr int BR = 128;
    constexpr int KC = 16;
    constexpr int TN = 4;
    constexpr int TN2 = 2;
    __shared__ __align__(16) float As[KC][BR];
    __shared__ __align__(16) float Ws[KC][NC];
    __shared__ float Red[BR][17];   // padded: stride 17 -> conflict-free column reduce

    const int t = threadIdx.x;
    const int ti = t >> 4;
    const int tj = t & 15;
    const int row0 = blockIdx.x * BR;
    const int lr = t >> 1;
    const int lk = (t & 1) * 8;
    const int grow = row0 + lr;

    int si = 0, di = 0;
    if (grow < M) { si = __ldg(esrc + grow); di = __ldg(edst + grow); }

    unsigned long long acc[8][TN2];
#pragma unroll
    for (int i = 0; i < 8; i++)
#pragma unroll
        for (int j = 0; j < TN2; j++) acc[i][j] = 0ull;

    for (int k0 = 0; k0 < 128; k0 += KC) {
        __syncthreads();
        // gather-stage A: cols [0,64) from zod[si], [64,128) from zdt[di].
        // each 8-wide load (lk in {0,8}, KC=16) never crosses the 64 boundary.
        float4 v0 = make_float4(0.f, 0.f, 0.f, 0.f), v1 = v0;
        if (grow < M) {
            int k = k0 + lk;
            const float* base = (k < 64) ? (zod + (size_t)si * 64 + k)
                                         : (zdt + (size_t)di * 64 + (k - 64));
            v0 = *(const float4*)(base);
            v1 = *(const float4*)(base + 4);
        }
        As[lk + 0][lr] = v0.x;  As[lk + 1][lr] = v0.y;
        As[lk + 2][lr] = v0.z;  As[lk + 3][lr] = v0.w;
        As[lk + 4][lr] = v1.x;  As[lk + 5][lr] = v1.y;
        As[lk + 6][lr] = v1.z;  As[lk + 7][lr] = v1.w;
        {
            const int kk = t >> 4;
            const int c = (t & 15) * TN;
            float4 w = *(const float4*)(W1 + (size_t)(k0 + kk) * NC + c);
            *(float4*)&Ws[kk][c] = w;
        }
        __syncthreads();
#pragma unroll
        for (int kk = 0; kk < KC; kk++) {
            float a[8];
            *(float4*)&a[0] = *(const float4*)&As[kk][ti * 8];
            *(float4*)&a[4] = *(const float4*)&As[kk][ti * 8 + 4];
            unsigned long long a2[8];
#pragma unroll
            for (int i = 0; i < 8; i++) PACK2_DUP(a2[i], a[i]);
            unsigned long long w2r[TN2];
            const unsigned long long* wsp = (const unsigned long long*)&Ws[kk][tj * TN];
#pragma unroll
            for (int j = 0; j < TN2; j++) w2r[j] = wsp[j];
#pragma unroll
            for (int i = 0; i < 8; i++)
#pragma unroll
                for (int j = 0; j < TN2; j++) FMA2(acc[i][j], a2[i], w2r[j]);
        }
    }

    // epilogue: bias + relu + partial dot with w2, then cross-thread reduce
    float bb[TN], ww[TN];
#pragma unroll
    for (int j = 0; j < TN; j++) {
        bb[j] = b1[tj * TN + j];
        ww[j] = __ldg(w2 + tj * TN + j);
    }
#pragma unroll
    for (int i = 0; i < 8; i++) {
        float p = 0.f;
#pragma unroll
        for (int j = 0; j < TN2; j++) {
            unsigned int lo, hi;
            UNPACK2(lo, hi, acc[i][j]);
            p += fmaxf(__uint_as_float(lo) + bb[2 * j], 0.f) * ww[2 * j];
            p += fmaxf(__uint_as_float(hi) + bb[2 * j + 1], 0.f) * ww[2 * j + 1];
        }
        Red[ti * 8 + i][tj] = p;
    }
    __syncthreads();
    if (t < BR) {
        int r = row0 + t;
        if (r < M) {
            float s = 0.f;
#pragma unroll
            for (int j = 0; j < 16; j++) s += Red[t][j];
            out[r] = 1.f / (1.f + expf(-(s + b2p[0])));
        }
    }
}

// ---------------- host orchestration ------------------------------------------
extern "C" void kernel_launch(void* const* d_in, const int* in_sizes, int n_in,
                              void* d_out, int out_size) {
    const float* x_dt   = (const float*)d_in[0];
    const float* x_od   = (const float*)d_in[1];
    const int*   ei_dt  = (const int*)  d_in[2];
    const int*   rsrc   = (const int*)  d_in[3];
    const int*   rdst   = (const int*)  d_in[4];
    const int*   elsrc  = (const int*)  d_in[5];
    const int*   eldst  = (const int*)  d_in[6];
    const float* od1_wl = (const float*)d_in[7];
    const float* od1_wr = (const float*)d_in[8];
    const float* od1_b  = (const float*)d_in[9];
    const float* od2_wl = (const float*)d_in[10];
    const float* od2_wr = (const float*)d_in[11];
    const float* od2_b  = (const float*)d_in[12];
    const float* od3_wl = (const float*)d_in[13];
    const float* od3_wr = (const float*)d_in[14];
    const float* od3_b  = (const float*)d_in[15];
    const float* od_lw  = (const float*)d_in[16];
    const float* od_lb  = (const float*)d_in[17];
    const float* dt1_wl = (const float*)d_in[18];
    const float* dt1_wr = (const float*)d_in[19];
    const float* dt1_b  = (const float*)d_in[20];
    const float* dt2_wl = (const float*)d_in[21];
    const float* dt2_wr = (const float*)d_in[22];
    const float* dt2_b  = (const float*)d_in[23];
    const float* dt_lw  = (const float*)d_in[24];
    const float* dt_lb  = (const float*)d_in[25];
    const float* dec_w1 = (const float*)d_in[26];
    const float* dec_b1 = (const float*)d_in[27];
    const float* dec_w2 = (const float*)d_in[28];
    const float* dec_b2 = (const float*)d_in[29];
    float* out = (float*)d_out;

    const int E1 = in_sizes[2] / 2;
    const int E2 = in_sizes[3];
    const int EL = in_sizes[5];
    const int* r1 = ei_dt;
    const int* c1 = ei_dt + E1;

    float *acc1, *acc2, *acc3, *cntdt, *invdt, *cntod, *invod;
    float *h, *d1, *od2b, *od3b, *zod, *d2, *zdt;
    cudaGetSymbolAddress((void**)&acc1, g_acc1);
    cudaGetSymbolAddress((void**)&acc2, g_acc2);
    cudaGetSymbolAddress((void**)&acc3, g_acc3);
    cudaGetSymbolAddress((void**)&cntdt, g_cnt_dt);
    cudaGetSymbolAddress((void**)&invdt, g_inv_dt);
    cudaGetSymbolAddress((void**)&cntod, g_cnt_od);
    cudaGetSymbolAddress((void**)&invod, g_inv_od);
    cudaGetSymbolAddress((void**)&h,   g_h);
    cudaGetSymbolAddress((void**)&d1,  g_d1);
    cudaGetSymbolAddress((void**)&od2b, g_od2);
    cudaGetSymbolAddress((void**)&od3b, g_od3);
    cudaGetSymbolAddress((void**)&zod, g_zod);
    cudaGetSymbolAddress((void**)&d2,  g_d2);
    cudaGetSymbolAddress((void**)&zdt, g_zdt);

    const int TB = 256;

    // zero accumulators + counts (memset is graph-capturable, not an alloc)
    cudaMemsetAsync(acc1, 0, (size_t)NDT * 128 * sizeof(float));
    cudaMemsetAsync(acc2, 0, (size_t)NOD * 128 * sizeof(float));
    cudaMemsetAsync(acc3, 0, (size_t)NDT * 128 * sizeof(float));
    cudaMemsetAsync(cntdt, 0, (size_t)NDT * sizeof(float));
    cudaMemsetAsync(cntod, 0, (size_t)NOD * sizeof(float));

    // agg(x_dt) over dt graph (shared by od1 and dt1), plus degree counts
    k_scatter<<<cdiv((long long)E1 * 32, TB), TB>>>(x_dt, r1, c1, E1, acc1, cntdt);
    k_inv<<<cdiv(NDT, TB), TB>>>(cntdt, invdt, NDT);

    // h = relu(agg@od1_wl + x_dt@od1_wr + b) ; d1 = relu(agg@dt1_wl + x_dt@dt1_wr + b)
    gemm_dual<128><<<cdiv(NDT, 128), 256>>>(NDT, acc1, invdt, 128, x_dt, 128,
                                            od1_wl, od1_wr, od1_b, h, 1);
    gemm_dual<128><<<cdiv(NDT, 128), 256>>>(NDT, acc1, invdt, 128, x_dt, 128,
                                            dt1_wl, dt1_wr, dt1_b, d1, 1);

    // agg(h) over rev edges (shared by od2 and od3)
    k_scatter<<<cdiv((long long)E2 * 32, TB), TB>>>(h, rsrc, rdst, E2, acc2, cntod);
    k_inv<<<cdiv(NOD, TB), TB>>>(cntod, invod, NOD);

    gemm_dual<128><<<cdiv(NOD, 128), 256>>>(NOD, acc2, invod, 128, x_od, 64,
                                            od2_wl, od2_wr, od2_b, od2b, 1);
    gemm_dual<128><<<cdiv(NOD, 128), 256>>>(NOD, acc2, invod, 128, od2b, 128,
                                            od3_wl, od3_wr, od3_b, od3b, 1);
    gemm_dual<64><<<cdiv(NOD, 128), 256>>>(NOD, od3b, nullptr, 128, nullptr, 0,
                                           od_lw, nullptr, od_lb, zod, 0);

    // agg(d1) over dt graph (same degree counts as before)
    k_scatter<<<cdiv((long long)E1 * 32, TB), TB>>>(d1, r1, c1, E1, acc3, nullptr);
    gemm_dual<128><<<cdiv(NDT, 128), 256>>>(NDT, acc3, invdt, 128, d1, 128,
                                            dt2_wl, dt2_wr, dt2_b, d2, 1);
    gemm_dual<64><<<cdiv(NDT, 128), 256>>>(NDT, d2, nullptr, 128, nullptr, 0,
                                           dt_lw, nullptr, dt_lb, zdt, 0);

    // fused edge decoder (gather + GEMM + relu + dot + sigmoid, one kernel)
    dec_fused<<<cdiv(EL, 128), 256>>>(EL, zod, zdt, elsrc, eldst,
                                      dec_w1, dec_b1, dec_w2, dec_b2, out);
}

// round 3
// speedup vs baseline: 1.5552x; 1.0330x over previous
#include <cuda_runtime.h>
#include <math.h>

#define NDT 30000
#define NOD 10000

static inline int cdiv(long long a, long long b) { return (int)((a + b - 1) / b); }

// ---------------- packed f32x2 helpers (sm_103a FFMA2) -------------------------
#define FMA2(acc, a, b) \
    asm("fma.rn.f32x2 %0, %1, %2, %0;" : "+l"(acc) : "l"(a), "l"(b))
#define PACK2_DUP(d, x) \
    asm("mov.b64 %0, {%1, %1};" : "=l"(d) : "r"(__float_as_uint(x)))
#define UNPACK2(lo, hi, v) \
    asm("mov.b64 {%0, %1}, %2;" : "=r"(lo), "=r"(hi) : "l"(v))

// ---------------- device scratch ----------------------------------------------
__device__ float g_acc1[NDT * 128];
__device__ float g_acc2[NOD * 128];
__device__ float g_acc3[NDT * 128];
__device__ float g_cnt_dt[NDT];
__device__ float g_inv_dt[NDT];
__device__ float g_cnt_od[NOD];
__device__ float g_inv_od[NOD];
__device__ float g_h [NDT * 128];
__device__ float g_d1[NDT * 128];
__device__ float g_od2[NOD * 128];
__device__ float g_od3[NOD * 128];
__device__ float g_zod[NOD * 64];
__device__ float g_d2[NDT * 128];
__device__ float g_zdt[NDT * 64];

// ---------------- utility kernels ---------------------------------------------
__global__ void k_inv(const float* __restrict__ cnt, float* __restrict__ inv, int n) {
    int i = blockIdx.x * blockDim.x + threadIdx.x;
    if (i < n) inv[i] = 1.f / fmaxf(cnt[i], 1.f);
}

// Scatter-add rows of X (width 128) via (src -> dst); one warp/edge, red.v4.f32.
__global__ void k_scatter(const float* __restrict__ X,
                          const int* __restrict__ src, const int* __restrict__ dst,
                          int E, float* __restrict__ acc, float* __restrict__ cnt) {
    long long gid = (long long)blockIdx.x * blockDim.x + threadIdx.x;
    int e = (int)(gid >> 5);
    if (e >= E) return;
    int lane = (int)(gid & 31);
    int s = __ldg(src + e);
    int d = __ldg(dst + e);
    float4 v = *(const float4*)(X + (size_t)s * 128 + lane * 4);
    float* o = acc + (size_t)d * 128 + lane * 4;
    asm volatile("red.global.add.v4.f32 [%0], {%1, %2, %3, %4};"
                 :: "l"(o), "f"(v.x), "f"(v.y), "f"(v.z), "f"(v.w) : "memory");
    if (cnt != nullptr && lane == 0) atomicAdd(cnt + d, 1.f);
}

// ---------------- dual-input GEMM, f32x2 inner loop, double-buffered -----------
// Y = act( diag(rowscale)*A @ W1 + B @ W2 + bias ).  Optional second weight set
// (W1b/W2b/biasb -> Yb) selected by blockIdx.y (same A/B staged).
// Tile 128 rows x NCOLS cols, 256 threads; thread tile = 16 rows x NCOLS/32 cols.
template <int NCOLS>
__global__ __launch_bounds__(256, 2)
void gemm_dual(int M,
               const float* __restrict__ A, const float* __restrict__ rowscale, int K1,
               const float* __restrict__ B, int K2,
               const float* __restrict__ W1, const float* __restrict__ W2,
               const float* __restrict__ W1b, const float* __restrict__ W2b,
               const float* __restrict__ bias, const float* __restrict__ biasb,
               float* __restrict__ Y, float* __restrict__ Yb, int do_relu) {
    constexpr int BR = 128;
    constexpr int KC = 16;
    constexpr int AST = 132;            // padded stride: 16B-aligned rows, cheap staging
    constexpr int CT = NCOLS / 32;      // cols per thread (4 or 2)
    constexpr int WLD = NCOLS * KC / 256;  // W floats per thread per chunk (8 or 4)
    __shared__ __align__(16) float As[2][KC][AST];
    __shared__ __align__(16) float Ws[2][KC][NCOLS];

    const float* w1 = blockIdx.y ? W1b : W1;
    const float* w2 = blockIdx.y ? W2b : W2;
    const float* bs = blockIdx.y ? biasb : bias;
    float* y        = blockIdx.y ? Yb : Y;

    const int t = threadIdx.x;
    const int tj = t & 31;              // col group
    const int ti = t >> 5;              // row group (warp id)
    const int row0 = blockIdx.x * BR;
    const int lr = t >> 1;              // staging row
    const int lk = (t & 1) * 8;         // staging k offset
    const int grow = row0 + lr;
    const int wkk = t >> 4;             // W staging k
    const int wc = (t & 15) * WLD;      // W staging col
    const float sc = (rowscale != nullptr && grow < M) ? rowscale[grow] : 1.f;

    const int n1 = K1 / KC;
    const int n2 = (B != nullptr) ? (K2 / KC) : 0;
    const int nch = n1 + n2;

    float pa[8];
    float pw[WLD];

    auto loadX = [&](int cc) {
        const float* Xp; int stride, k0; float s;
        if (cc < n1) { Xp = A; stride = K1; k0 = cc * KC; s = sc; }
        else         { Xp = B; stride = K2; k0 = (cc - n1) * KC; s = 1.f; }
#pragma unroll
        for (int i = 0; i < 8; i++) pa[i] = 0.f;
        if (grow < M) {
            const float* base = Xp + (size_t)grow * stride + k0 + lk;
            float4 v0 = *(const float4*)(base);
            float4 v1 = *(const float4*)(base + 4);
            pa[0] = v0.x * s; pa[1] = v0.y * s; pa[2] = v0.z * s; pa[3] = v0.w * s;
            pa[4] = v1.x * s; pa[5] = v1.y * s; pa[6] = v1.z * s; pa[7] = v1.w * s;
        }
    };
    auto loadW = [&](int cc) {
        const float* Wp; int k0;
        if (cc < n1) { Wp = w1; k0 = cc * KC; }
        else         { Wp = w2; k0 = (cc - n1) * KC; }
        const float* base = Wp + (size_t)(k0 + wkk) * NCOLS + wc;
#pragma unroll
        for (int j = 0; j < WLD; j += 4)
            *(float4*)&pw[j] = *(const float4*)(base + j);
    };
    auto stage = [&](int buf) {
#pragma unroll
        for (int i = 0; i < 8; i++) As[buf][lk + i][lr] = pa[i];
#pragma unroll
        for (int j = 0; j < WLD; j += 4)
            *(float4*)&Ws[buf][wkk][wc + j] = *(const float4*)&pw[j];
    };

    unsigned long long acc[8][CT];
#pragma unroll
    for (int p = 0; p < 8; p++)
#pragma unroll
        for (int c = 0; c < CT; c++) acc[p][c] = 0ull;

    loadX(0); loadW(0); stage(0);

    for (int cc = 0; cc < nch; ++cc) {
        const int buf = cc & 1;
        __syncthreads();
        if (cc + 1 < nch) { loadX(cc + 1); loadW(cc + 1); }
#pragma unroll
        for (int kk = 0; kk < KC; kk++) {
            const unsigned long long* ap =
                (const unsigned long long*)&As[buf][kk][ti * 16];
            unsigned long long a2[8];
#pragma unroll
            for (int p = 0; p < 8; p++) a2[p] = ap[p];   // natural row pairs
            float wv[CT];
#pragma unroll
            for (int c = 0; c < CT; c++) wv[c] = Ws[buf][kk][tj * CT + c];
            unsigned long long wd[CT];
#pragma unroll
            for (int c = 0; c < CT; c++) PACK2_DUP(wd[c], wv[c]);
#pragma unroll
            for (int p = 0; p < 8; p++)
#pragma unroll
                for (int c = 0; c < CT; c++) FMA2(acc[p][c], a2[p], wd[c]);
        }
        if (cc + 1 < nch) stage(buf ^ 1);
    }

    // epilogue: bias + activation + store (rows ti*16+2p / +1, cols tj*CT..)
    float bb[CT];
#pragma unroll
    for (int c = 0; c < CT; c++) bb[c] = (bs != nullptr) ? bs[tj * CT + c] : 0.f;
#pragma unroll
    for (int p = 0; p < 8; p++) {
        float o0[CT], o1[CT];
#pragma unroll
        for (int c = 0; c < CT; c++) {
            unsigned int lo, hi;
            UNPACK2(lo, hi, acc[p][c]);
            float ylo = __uint_as_float(lo) + bb[c];
            float yhi = __uint_as_float(hi) + bb[c];
            o0[c] = do_relu ? fmaxf(ylo, 0.f) : ylo;
            o1[c] = do_relu ? fmaxf(yhi, 0.f) : yhi;
        }
        int r0 = row0 + ti * 16 + 2 * p;
        if (r0 < M) {
            if (CT == 4) *(float4*)(y + (size_t)r0 * NCOLS + tj * CT) = *(const float4*)o0;
            else         *(float2*)(y + (size_t)r0 * NCOLS + tj * CT) = *(const float2*)o0;
        }
        if (r0 + 1 < M) {
            if (CT == 4) *(float4*)(y + (size_t)(r0 + 1) * NCOLS + tj * CT) = *(const float4*)o1;
            else         *(float2*)(y + (size_t)(r0 + 1) * NCOLS + tj * CT) = *(const float2*)o1;
        }
    }
}

// ---------------- fused edge decoder -------------------------------------------
// out[e] = sigmoid( relu([zod[esrc[e]] | zdt[edst[e]]] @ W1 + b1) . w2 + b2 )
__global__ __launch_bounds__(256, 2)
void dec_fused(int M, const float* __restrict__ zod, const float* __restrict__ zdt,
               const int* __restrict__ esrc, const int* __restrict__ edst,
               const float* __restrict__ W1, const float* __restrict__ b1,
               const float* __restrict__ w2, const float* __restrict__ b2p,
               float* __restrict__ out) {
    constexpr int NC = 64;
    constexpr int BR = 128;
    constexpr int KC = 16;
    constexpr int AST = 132;
    constexpr int CT = 2;
    constexpr int WLD = 4;
    constexpr int NCH = 8;              // K = 128
    __shared__ __align__(16) float As[2][KC][AST];
    __shared__ __align__(16) float Ws[2][KC][NC];
    __shared__ __align__(16) float Red[BR][36];

    const int t = threadIdx.x;
    const int tj = t & 31;
    const int ti = t >> 5;
    const int row0 = blockIdx.x * BR;
    const int lr = t >> 1;
    const int lk = (t & 1) * 8;
    const int grow = row0 + lr;
    const int wkk = t >> 4;
    const int wc = (t & 15) * WLD;

    int si = 0, di = 0;
    if (grow < M) { si = __ldg(esrc + grow); di = __ldg(edst + grow); }

    float pa[8];
    float pw[WLD];

    auto loadX = [&](int cc) {
#pragma unroll
        for (int i = 0; i < 8; i++) pa[i] = 0.f;
        if (grow < M) {
            int k = cc * KC + lk;
            const float* base = (k < 64) ? (zod + (size_t)si * 64 + k)
                                         : (zdt + (size_t)di * 64 + (k - 64));
            float4 v0 = *(const float4*)(base);
            float4 v1 = *(const float4*)(base + 4);
            pa[0] = v0.x; pa[1] = v0.y; pa[2] = v0.z; pa[3] = v0.w;
            pa[4] = v1.x; pa[5] = v1.y; pa[6] = v1.z; pa[7] = v1.w;
        }
    };
    auto loadW = [&](int cc) {
        const float* base = W1 + (size_t)(cc * KC + wkk) * NC + wc;
        *(float4*)&pw[0] = *(const float4*)(base);
    };
    auto stage = [&](int buf) {
#pragma unroll
        for (int i = 0; i < 8; i++) As[buf][lk + i][lr] = pa[i];
        *(float4*)&Ws[buf][wkk][wc] = *(const float4*)&pw[0];
    };

    unsigned long long acc[8][CT];
#pragma unroll
    for (int p = 0; p < 8; p++)
#pragma unroll
        for (int c = 0; c < CT; c++) acc[p][c] = 0ull;

    loadX(0); loadW(0); stage(0);

#pragma unroll 1
    for (int cc = 0; cc < NCH; ++cc) {
        const int buf = cc & 1;
        __syncthreads();
        if (cc + 1 < NCH) { loadX(cc + 1); loadW(cc + 1); }
#pragma unroll
        for (int kk = 0; kk < KC; kk++) {
            const unsigned long long* ap =
                (const unsigned long long*)&As[buf][kk][ti * 16];
            unsigned long long a2[8];
#pragma unroll
            for (int p = 0; p < 8; p++) a2[p] = ap[p];
            unsigned long long wd[CT];
#pragma unroll
            for (int c = 0; c < CT; c++) PACK2_DUP(wd[c], Ws[buf][kk][tj * CT + c]);
#pragma unroll
            for (int p = 0; p < 8; p++)
#pragma unroll
                for (int c = 0; c < CT; c++) FMA2(acc[p][c], a2[p], wd[c]);
        }
        if (cc + 1 < NCH) stage(buf ^ 1);
    }

    // epilogue: bias + relu + partial dot with w2, transpose-reduce in smem
    float bb[CT], ww[CT];
#pragma unroll
    for (int c = 0; c < CT; c++) {
        bb[c] = b1[tj * CT + c];
        ww[c] = __ldg(w2 + tj * CT + c);
    }
#pragma unroll
    for (int p = 0; p < 8; p++) {
        float plo = 0.f, phi = 0.f;
#pragma unroll
        for (int c = 0; c < CT; c++) {
            unsigned int lo, hi;
            UNPACK2(lo, hi, acc[p][c]);
            plo += fmaxf(__uint_as_float(lo) + bb[c], 0.f) * ww[c];
            phi += fmaxf(__uint_as_float(hi) + bb[c], 0.f) * ww[c];
        }
        Red[ti * 16 + 2 * p][tj] = plo;
        Red[ti * 16 + 2 * p + 1][tj] = phi;
    }
    __syncthreads();
    if (t < BR) {
        int r = row0 + t;
        if (r < M) {
            float s = 0.f;
#pragma unroll
            for (int j = 0; j < 32; j += 4) {
                float4 v = *(const float4*)&Red[t][j];
                s += v.x + v.y + v.z + v.w;
            }
            out[r] = 1.f / (1.f + expf(-(s + b2p[0])));
        }
    }
}

// ---------------- host orchestration ------------------------------------------
extern "C" void kernel_launch(void* const* d_in, const int* in_sizes, int n_in,
                              void* d_out, int out_size) {
    const float* x_dt   = (const float*)d_in[0];
    const float* x_od   = (const float*)d_in[1];
    const int*   ei_dt  = (const int*)  d_in[2];
    const int*   rsrc   = (const int*)  d_in[3];
    const int*   rdst   = (const int*)  d_in[4];
    const int*   elsrc  = (const int*)  d_in[5];
    const int*   eldst  = (const int*)  d_in[6];
    const float* od1_wl = (const float*)d_in[7];
    const float* od1_wr = (const float*)d_in[8];
    const float* od1_b  = (const float*)d_in[9];
    const float* od2_wl = (const float*)d_in[10];
    const float* od2_wr = (const float*)d_in[11];
    const float* od2_b  = (const float*)d_in[12];
    const float* od3_wl = (const float*)d_in[13];
    const float* od3_wr = (const float*)d_in[14];
    const float* od3_b  = (const float*)d_in[15];
    const float* od_lw  = (const float*)d_in[16];
    const float* od_lb  = (const float*)d_in[17];
    const float* dt1_wl = (const float*)d_in[18];
    const float* dt1_wr = (const float*)d_in[19];
    const float* dt1_b  = (const float*)d_in[20];
    const float* dt2_wl = (const float*)d_in[21];
    const float* dt2_wr = (const float*)d_in[22];
    const float* dt2_b  = (const float*)d_in[23];
    const float* dt_lw  = (const float*)d_in[24];
    const float* dt_lb  = (const float*)d_in[25];
    const float* dec_w1 = (const float*)d_in[26];
    const float* dec_b1 = (const float*)d_in[27];
    const float* dec_w2 = (const float*)d_in[28];
    const float* dec_b2 = (const float*)d_in[29];
    float* out = (float*)d_out;

    const int E1 = in_sizes[2] / 2;
    const int E2 = in_sizes[3];
    const int EL = in_sizes[5];
    const int* r1 = ei_dt;
    const int* c1 = ei_dt + E1;

    float *acc1, *acc2, *acc3, *cntdt, *invdt, *cntod, *invod;
    float *h, *d1, *od2b, *od3b, *zod, *d2, *zdt;
    cudaGetSymbolAddress((void**)&acc1, g_acc1);
    cudaGetSymbolAddress((void**)&acc2, g_acc2);
    cudaGetSymbolAddress((void**)&acc3, g_acc3);
    cudaGetSymbolAddress((void**)&cntdt, g_cnt_dt);
    cudaGetSymbolAddress((void**)&invdt, g_inv_dt);
    cudaGetSymbolAddress((void**)&cntod, g_cnt_od);
    cudaGetSymbolAddress((void**)&invod, g_inv_od);
    cudaGetSymbolAddress((void**)&h,   g_h);
    cudaGetSymbolAddress((void**)&d1,  g_d1);
    cudaGetSymbolAddress((void**)&od2b, g_od2);
    cudaGetSymbolAddress((void**)&od3b, g_od3);
    cudaGetSymbolAddress((void**)&zod, g_zod);
    cudaGetSymbolAddress((void**)&d2,  g_d2);
    cudaGetSymbolAddress((void**)&zdt, g_zdt);

    const int TB = 256;

    cudaMemsetAsync(acc1, 0, (size_t)NDT * 128 * sizeof(float));
    cudaMemsetAsync(acc2, 0, (size_t)NOD * 128 * sizeof(float));
    cudaMemsetAsync(acc3, 0, (size_t)NDT * 128 * sizeof(float));
    cudaMemsetAsync(cntdt, 0, (size_t)NDT * sizeof(float));
    cudaMemsetAsync(cntod, 0, (size_t)NOD * sizeof(float));

    // agg(x_dt) over dt graph (shared by od1 and dt1), plus degree counts
    k_scatter<<<cdiv((long long)E1 * 32, TB), TB>>>(x_dt, r1, c1, E1, acc1, cntdt);
    k_inv<<<cdiv(NDT, TB), TB>>>(cntdt, invdt, NDT);

    // merged: h = relu(agg@od1_wl + x_dt@od1_wr + b); d1 = same with dt1 weights
    {
        dim3 grid(cdiv(NDT, 128), 2);
        gemm_dual<128><<<grid, 256>>>(NDT, acc1, invdt, 128, x_dt, 128,
                                      od1_wl, od1_wr, dt1_wl, dt1_wr,
                                      od1_b, dt1_b, h, d1, 1);
    }

    // agg(h) over rev edges (shared by od2 and od3)
    k_scatter<<<cdiv((long long)E2 * 32, TB), TB>>>(h, rsrc, rdst, E2, acc2, cntod);
    k_inv<<<cdiv(NOD, TB), TB>>>(cntod, invod, NOD);

    gemm_dual<128><<<dim3(cdiv(NOD, 128), 1), 256>>>(NOD, acc2, invod, 128, x_od, 64,
                                                     od2_wl, od2_wr, nullptr, nullptr,
                                                     od2_b, nullptr, od2b, nullptr, 1);
    gemm_dual<128><<<dim3(cdiv(NOD, 128), 1), 256>>>(NOD, acc2, invod, 128, od2b, 128,
                                                     od3_wl, od3_wr, nullptr, nullptr,
                                                     od3_b, nullptr, od3b, nullptr, 1);
    gemm_dual<64><<<dim3(cdiv(NOD, 128), 1), 256>>>(NOD, od3b, nullptr, 128, nullptr, 0,
                                                    od_lw, nullptr, nullptr, nullptr,
                                                    od_lb, nullptr, zod, nullptr, 0);

    // agg(d1) over dt graph (reuse invdt)
    k_scatter<<<cdiv((long long)E1 * 32, TB), TB>>>(d1, r1, c1, E1, acc3, nullptr);
    gemm_dual<128><<<dim3(cdiv(NDT, 128), 1), 256>>>(NDT, acc3, invdt, 128, d1, 128,
                                                     dt2_wl, dt2_wr, nullptr, nullptr,
                                                     dt2_b, nullptr, d2, nullptr, 1);
    gemm_dual<64><<<dim3(cdiv(NDT, 128), 1), 256>>>(NDT, d2, nullptr, 128, nullptr, 0,
                                                    dt_lw, nullptr, nullptr, nullptr,
                                                    dt_lb, nullptr, zdt, nullptr, 0);

    // fused edge decoder
    dec_fused<<<cdiv(EL, 128), 256>>>(EL, zod, zdt, elsrc, eldst,
                                      dec_w1, dec_b1, dec_w2, dec_b2, out);
}

// round 4
// speedup vs baseline: 2.3158x; 1.4890x over previous
#include <cuda_runtime.h>
#include <math.h>

#define NDT 30000
#define NOD 10000

static inline int cdiv(long long a, long long b) { return (int)((a + b - 1) / b); }

// ---------------- tf32 mma helpers ---------------------------------------------
__device__ __forceinline__ float to_tf32(float x) {
    unsigned u;
    asm("cvt.rna.tf32.f32 %0, %1;" : "=r"(u) : "f"(x));
    return __uint_as_float(u);
}
#define MMA_TF32(d, a, b0, b1)                                          \
    asm volatile("mma.sync.aligned.m16n8k8.row.col.f32.tf32.tf32.f32 "  \
                 "{%0,%1,%2,%3}, {%4,%5,%6,%7}, {%8,%9}, {%0,%1,%2,%3};" \
                 : "+f"((d)[0]), "+f"((d)[1]), "+f"((d)[2]), "+f"((d)[3]) \
                 : "r"((a)[0]), "r"((a)[1]), "r"((a)[2]), "r"((a)[3]),  \
                   "r"(b0), "r"(b1))

// ---------------- device scratch ----------------------------------------------
__device__ float g_acc1[NDT * 128];
__device__ float g_acc2[NOD * 128];
__device__ float g_acc3[NDT * 128];
__device__ float g_cnt_dt[NDT];
__device__ float g_inv_dt[NDT];
__device__ float g_cnt_od[NOD];
__device__ float g_inv_od[NOD];
__device__ float g_h [NDT * 128];
__device__ float g_d1[NDT * 128];
__device__ float g_od2[NOD * 128];
__device__ float g_od3[NOD * 128];
__device__ float g_zod[NOD * 64];
__device__ float g_d2[NDT * 128];
__device__ float g_zdt[NDT * 64];

// ---------------- utility kernels ---------------------------------------------
__global__ void k_inv(const float* __restrict__ cnt, float* __restrict__ inv, int n) {
    int i = blockIdx.x * blockDim.x + threadIdx.x;
    if (i < n) inv[i] = 1.f / fmaxf(cnt[i], 1.f);
}

// Scatter-add rows of X (width 128) via (src -> dst); one warp/edge, red.v4.f32.
__global__ void k_scatter(const float* __restrict__ X,
                          const int* __restrict__ src, const int* __restrict__ dst,
                          int E, float* __restrict__ acc, float* __restrict__ cnt) {
    long long gid = (long long)blockIdx.x * blockDim.x + threadIdx.x;
    int e = (int)(gid >> 5);
    if (e >= E) return;
    int lane = (int)(gid & 31);
    int s = __ldg(src + e);
    int d = __ldg(dst + e);
    float4 v = *(const float4*)(X + (size_t)s * 128 + lane * 4);
    float* o = acc + (size_t)d * 128 + lane * 4;
    asm volatile("red.global.add.v4.f32 [%0], {%1, %2, %3, %4};"
                 :: "l"(o), "f"(v.x), "f"(v.y), "f"(v.z), "f"(v.w) : "memory");
    if (cnt != nullptr && lane == 0) atomicAdd(cnt + d, 1.f);
}

// ---------------- tf32 tensor-core GEMM ----------------------------------------
// Y = act( diag(rowscale)*A @ W1 + B @ W2 + bias ); optional 2nd weight set via
// blockIdx.y.  Tile 128 x NCOLS, 256 thr = 8 warps (4 M-groups x 2 N-groups),
// warp tile 32 x NCOLS/2, mma.m16n8k8 tf32, double-buffered KC=16 chunks.
template <int NCOLS>
__global__ __launch_bounds__(256, 2)
void gemm_mma(int M,
              const float* __restrict__ A, const float* __restrict__ rowscale, int K1,
              const float* __restrict__ B, int K2,
              const float* __restrict__ W1, const float* __restrict__ W2,
              const float* __restrict__ W1b, const float* __restrict__ W2b,
              const float* __restrict__ bias, const float* __restrict__ biasb,
              float* __restrict__ Y, float* __restrict__ Yb, int do_relu) {
    constexpr int BR = 128;
    constexpr int KC = 16;
    constexpr int AST = 20;                   // As stride: conflict-free frag loads
    constexpr int WST = NCOLS + 8;            // Ws stride: 8 mod 32 -> conflict-free
    constexpr int WLD = NCOLS * KC / 256;     // W floats staged per thread
    constexpr int NT = NCOLS / 16;            // n-frags per warp
    __shared__ float As[2][BR][AST];
    __shared__ float Ws[2][KC][WST];

    const float* w1 = blockIdx.y ? W1b : W1;
    const float* w2 = blockIdx.y ? W2b : W2;
    const float* bs = blockIdx.y ? biasb : bias;
    float* y        = blockIdx.y ? Yb : Y;

    const int t = threadIdx.x;
    const int lane = t & 31;
    const int wid = t >> 5;
    const int warp_m = wid >> 1;
    const int warp_n = wid & 1;
    const int grp = lane >> 2;
    const int qid = lane & 3;
    const int row0 = blockIdx.x * BR;
    const int lr = t >> 1;
    const int lk = (t & 1) * 8;
    const int grow = row0 + lr;
    const int wkk = t >> 4;
    const int wc = (t & 15) * WLD;
    const float sc = (rowscale != nullptr && grow < M) ? rowscale[grow] : 1.f;

    const int n1 = K1 / KC;
    const int n2 = (B != nullptr) ? (K2 / KC) : 0;
    const int nch = n1 + n2;

    float pa[8];
    float pw[WLD];

    auto loadX = [&](int cc) {
        const float* Xp; int stride, k0; float s;
        if (cc < n1) { Xp = A; stride = K1; k0 = cc * KC; s = sc; }
        else         { Xp = B; stride = K2; k0 = (cc - n1) * KC; s = 1.f; }
#pragma unroll
        for (int i = 0; i < 8; i++) pa[i] = 0.f;
        if (grow < M) {
            const float* base = Xp + (size_t)grow * stride + k0 + lk;
            float4 v0 = *(const float4*)(base);
            float4 v1 = *(const float4*)(base + 4);
            pa[0] = v0.x * s; pa[1] = v0.y * s; pa[2] = v0.z * s; pa[3] = v0.w * s;
            pa[4] = v1.x * s; pa[5] = v1.y * s; pa[6] = v1.z * s; pa[7] = v1.w * s;
        }
    };
    auto loadW = [&](int cc) {
        const float* Wp; int k0;
        if (cc < n1) { Wp = w1; k0 = cc * KC; }
        else         { Wp = w2; k0 = (cc - n1) * KC; }
        const float* base = Wp + (size_t)(k0 + wkk) * NCOLS + wc;
#pragma unroll
        for (int j = 0; j < WLD; j += 4)
            *(float4*)&pw[j] = *(const float4*)(base + j);
    };
    auto stage = [&](int buf) {
#pragma unroll
        for (int i = 0; i < 8; i++) As[buf][lr][lk + i] = to_tf32(pa[i]);
#pragma unroll
        for (int j = 0; j < WLD; j++) Ws[buf][wkk][wc + j] = to_tf32(pw[j]);
    };

    float acc[2][NT][4];
#pragma unroll
    for (int mi = 0; mi < 2; mi++)
#pragma unroll
        for (int ni = 0; ni < NT; ni++)
#pragma unroll
            for (int c = 0; c < 4; c++) acc[mi][ni][c] = 0.f;

    loadX(0); loadW(0); stage(0);

    for (int cc = 0; cc < nch; ++cc) {
        const int buf = cc & 1;
        __syncthreads();
        if (cc + 1 < nch) { loadX(cc + 1); loadW(cc + 1); }
#pragma unroll
        for (int ks = 0; ks < KC; ks += 8) {
            unsigned af[2][4];
#pragma unroll
            for (int mi = 0; mi < 2; mi++) {
                int r = warp_m * 32 + mi * 16 + grp;
                af[mi][0] = __float_as_uint(As[buf][r    ][ks + qid]);
                af[mi][1] = __float_as_uint(As[buf][r + 8][ks + qid]);
                af[mi][2] = __float_as_uint(As[buf][r    ][ks + qid + 4]);
                af[mi][3] = __float_as_uint(As[buf][r + 8][ks + qid + 4]);
            }
#pragma unroll
            for (int ni = 0; ni < NT; ni++) {
                int c = warp_n * (NCOLS / 2) + ni * 8 + grp;
                unsigned b0 = __float_as_uint(Ws[buf][ks + qid    ][c]);
                unsigned b1 = __float_as_uint(Ws[buf][ks + qid + 4][c]);
                MMA_TF32(acc[0][ni], af[0], b0, b1);
                MMA_TF32(acc[1][ni], af[1], b0, b1);
            }
        }
        if (cc + 1 < nch) stage(buf ^ 1);
    }

    // epilogue: bias + activation + float2 stores
#pragma unroll
    for (int ni = 0; ni < NT; ni++) {
        int cb = warp_n * (NCOLS / 2) + ni * 8 + 2 * qid;
        float2 bv = make_float2(0.f, 0.f);
        if (bs != nullptr) bv = *(const float2*)(bs + cb);
#pragma unroll
        for (int mi = 0; mi < 2; mi++) {
            int r0 = row0 + warp_m * 32 + mi * 16 + grp;
            float v0 = acc[mi][ni][0] + bv.x;
            float v1 = acc[mi][ni][1] + bv.y;
            float v2 = acc[mi][ni][2] + bv.x;
            float v3 = acc[mi][ni][3] + bv.y;
            if (do_relu) {
                v0 = fmaxf(v0, 0.f); v1 = fmaxf(v1, 0.f);
                v2 = fmaxf(v2, 0.f); v3 = fmaxf(v3, 0.f);
            }
            if (r0 < M)     *(float2*)(y + (size_t)r0 * NCOLS + cb) = make_float2(v0, v1);
            if (r0 + 8 < M) *(float2*)(y + (size_t)(r0 + 8) * NCOLS + cb) = make_float2(v2, v3);
        }
    }
}

// ---------------- fused edge decoder (tf32 mma) --------------------------------
// out[e] = sigmoid( relu([zod[esrc[e]] | zdt[edst[e]]] @ W1 + b1) . w2 + b2 )
__global__ __launch_bounds__(256, 2)
void dec_mma(int M, const float* __restrict__ zod, const float* __restrict__ zdt,
             const int* __restrict__ esrc, const int* __restrict__ edst,
             const float* __restrict__ W1, const float* __restrict__ b1,
             const float* __restrict__ w2, const float* __restrict__ b2p,
             float* __restrict__ out) {
    constexpr int NC = 64;
    constexpr int BR = 128;
    constexpr int KC = 16;
    constexpr int AST = 20;
    constexpr int WST = NC + 8;
    constexpr int WLD = 4;
    constexpr int NT = 4;
    constexpr int NCH = 8;   // K=128
    __shared__ float As[2][BR][AST];
    __shared__ float Ws[2][KC][WST];
    __shared__ float Red[BR][9];

    const int t = threadIdx.x;
    const int lane = t & 31;
    const int wid = t >> 5;
    const int warp_m = wid >> 1;
    const int warp_n = wid & 1;
    const int grp = lane >> 2;
    const int qid = lane & 3;
    const int row0 = blockIdx.x * BR;
    const int lr = t >> 1;
    const int lk = (t & 1) * 8;
    const int grow = row0 + lr;
    const int wkk = t >> 4;
    const int wc = (t & 15) * WLD;

    int si = 0, di = 0;
    if (grow < M) { si = __ldg(esrc + grow); di = __ldg(edst + grow); }

    float pa[8];
    float pw[WLD];

    auto loadX = [&](int cc) {
#pragma unroll
        for (int i = 0; i < 8; i++) pa[i] = 0.f;
        if (grow < M) {
            int k = cc * KC + lk;
            const float* base = (k < 64) ? (zod + (size_t)si * 64 + k)
                                         : (zdt + (size_t)di * 64 + (k - 64));
            float4 v0 = *(const float4*)(base);
            float4 v1 = *(const float4*)(base + 4);
            pa[0] = v0.x; pa[1] = v0.y; pa[2] = v0.z; pa[3] = v0.w;
            pa[4] = v1.x; pa[5] = v1.y; pa[6] = v1.z; pa[7] = v1.w;
        }
    };
    auto loadW = [&](int cc) {
        const float* base = W1 + (size_t)(cc * KC + wkk) * NC + wc;
        *(float4*)&pw[0] = *(const float4*)(base);
    };
    auto stage = [&](int buf) {
#pragma unroll
        for (int i = 0; i < 8; i++) As[buf][lr][lk + i] = to_tf32(pa[i]);
#pragma unroll
        for (int j = 0; j < WLD; j++) Ws[buf][wkk][wc + j] = to_tf32(pw[j]);
    };

    float acc[2][NT][4];
#pragma unroll
    for (int mi = 0; mi < 2; mi++)
#pragma unroll
        for (int ni = 0; ni < NT; ni++)
#pragma unroll
            for (int c = 0; c < 4; c++) acc[mi][ni][c] = 0.f;

    loadX(0); loadW(0); stage(0);

#pragma unroll 1
    for (int cc = 0; cc < NCH; ++cc) {
        const int buf = cc & 1;
        __syncthreads();
        if (cc + 1 < NCH) { loadX(cc + 1); loadW(cc + 1); }
#pragma unroll
        for (int ks = 0; ks < KC; ks += 8) {
            unsigned af[2][4];
#pragma unroll
            for (int mi = 0; mi < 2; mi++) {
                int r = warp_m * 32 + mi * 16 + grp;
                af[mi][0] = __float_as_uint(As[buf][r    ][ks + qid]);
                af[mi][1] = __float_as_uint(As[buf][r + 8][ks + qid]);
                af[mi][2] = __float_as_uint(As[buf][r    ][ks + qid + 4]);
                af[mi][3] = __float_as_uint(As[buf][r + 8][ks + qid + 4]);
            }
#pragma unroll
            for (int ni = 0; ni < NT; ni++) {
                int c = warp_n * 32 + ni * 8 + grp;
                unsigned b0 = __float_as_uint(Ws[buf][ks + qid    ][c]);
                unsigned b1 = __float_as_uint(Ws[buf][ks + qid + 4][c]);
                MMA_TF32(acc[0][ni], af[0], b0, b1);
                MMA_TF32(acc[1][ni], af[1], b0, b1);
            }
        }
        if (cc + 1 < NCH) stage(buf ^ 1);
    }

    // epilogue: bias + relu + partial dot with w2 per row-half
    float p[2][2] = {{0.f, 0.f}, {0.f, 0.f}};
#pragma unroll
    for (int ni = 0; ni < NT; ni++) {
        int cb = warp_n * 32 + ni * 8 + 2 * qid;
        float2 bv = *(const float2*)(b1 + cb);
        float2 wv = *(const float2*)(w2 + cb);
#pragma unroll
        for (int mi = 0; mi < 2; mi++) {
            p[mi][0] += fmaxf(acc[mi][ni][0] + bv.x, 0.f) * wv.x
                      + fmaxf(acc[mi][ni][1] + bv.y, 0.f) * wv.y;
            p[mi][1] += fmaxf(acc[mi][ni][2] + bv.x, 0.f) * wv.x
                      + fmaxf(acc[mi][ni][3] + bv.y, 0.f) * wv.y;
        }
    }
    __syncthreads();
#pragma unroll
    for (int mi = 0; mi < 2; mi++) {
        Red[warp_m * 32 + mi * 16 + grp    ][warp_n * 4 + qid] = p[mi][0];
        Red[warp_m * 32 + mi * 16 + grp + 8][warp_n * 4 + qid] = p[mi][1];
    }
    __syncthreads();
    if (t < BR) {
        int r = row0 + t;
        if (r < M) {
            float s = 0.f;
#pragma unroll
            for (int j = 0; j < 8; j++) s += Red[t][j];
            out[r] = 1.f / (1.f + expf(-(s + b2p[0])));
        }
    }
}

// ---------------- host orchestration ------------------------------------------
extern "C" void kernel_launch(void* const* d_in, const int* in_sizes, int n_in,
                              void* d_out, int out_size) {
    const float* x_dt   = (const float*)d_in[0];
    const float* x_od   = (const float*)d_in[1];
    const int*   ei_dt  = (const int*)  d_in[2];
    const int*   rsrc   = (const int*)  d_in[3];
    const int*   rdst   = (const int*)  d_in[4];
    const int*   elsrc  = (const int*)  d_in[5];
    const int*   eldst  = (const int*)  d_in[6];
    const float* od1_wl = (const float*)d_in[7];
    const float* od1_wr = (const float*)d_in[8];
    const float* od1_b  = (const float*)d_in[9];
    const float* od2_wl = (const float*)d_in[10];
    const float* od2_wr = (const float*)d_in[11];
    const float* od2_b  = (const float*)d_in[12];
    const float* od3_wl = (const float*)d_in[13];
    const float* od3_wr = (const float*)d_in[14];
    const float* od3_b  = (const float*)d_in[15];
    const float* od_lw  = (const float*)d_in[16];
    const float* od_lb  = (const float*)d_in[17];
    const float* dt1_wl = (const float*)d_in[18];
    const float* dt1_wr = (const float*)d_in[19];
    const float* dt1_b  = (const float*)d_in[20];
    const float* dt2_wl = (const float*)d_in[21];
    const float* dt2_wr = (const float*)d_in[22];
    const float* dt2_b  = (const float*)d_in[23];
    const float* dt_lw  = (const float*)d_in[24];
    const float* dt_lb  = (const float*)d_in[25];
    const float* dec_w1 = (const float*)d_in[26];
    const float* dec_b1 = (const float*)d_in[27];
    const float* dec_w2 = (const float*)d_in[28];
    const float* dec_b2 = (const float*)d_in[29];
    float* out = (float*)d_out;

    const int E1 = in_sizes[2] / 2;
    const int E2 = in_sizes[3];
    const int EL = in_sizes[5];
    const int* r1 = ei_dt;
    const int* c1 = ei_dt + E1;

    float *acc1, *acc2, *acc3, *cntdt, *invdt, *cntod, *invod;
    float *h, *d1, *od2b, *od3b, *zod, *d2, *zdt;
    cudaGetSymbolAddress((void**)&acc1, g_acc1);
    cudaGetSymbolAddress((void**)&acc2, g_acc2);
    cudaGetSymbolAddress((void**)&acc3, g_acc3);
    cudaGetSymbolAddress((void**)&cntdt, g_cnt_dt);
    cudaGetSymbolAddress((void**)&invdt, g_inv_dt);
    cudaGetSymbolAddress((void**)&cntod, g_cnt_od);
    cudaGetSymbolAddress((void**)&invod, g_inv_od);
    cudaGetSymbolAddress((void**)&h,   g_h);
    cudaGetSymbolAddress((void**)&d1,  g_d1);
    cudaGetSymbolAddress((void**)&od2b, g_od2);
    cudaGetSymbolAddress((void**)&od3b, g_od3);
    cudaGetSymbolAddress((void**)&zod, g_zod);
    cudaGetSymbolAddress((void**)&d2,  g_d2);
    cudaGetSymbolAddress((void**)&zdt, g_zdt);

    const int TB = 256;

    cudaMemsetAsync(acc1, 0, (size_t)NDT * 128 * sizeof(float));
    cudaMemsetAsync(acc2, 0, (size_t)NOD * 128 * sizeof(float));
    cudaMemsetAsync(acc3, 0, (size_t)NDT * 128 * sizeof(float));
    cudaMemsetAsync(cntdt, 0, (size_t)NDT * sizeof(float));
    cudaMemsetAsync(cntod, 0, (size_t)NOD * sizeof(float));

    // agg(x_dt) over dt graph (shared by od1 and dt1), plus degree counts
    k_scatter<<<cdiv((long long)E1 * 32, TB), TB>>>(x_dt, r1, c1, E1, acc1, cntdt);
    k_inv<<<cdiv(NDT, TB), TB>>>(cntdt, invdt, NDT);

    // merged: h = relu(agg@od1_wl + x_dt@od1_wr + b); d1 = same with dt1 weights
    gemm_mma<128><<<dim3(cdiv(NDT, 128), 2), 256>>>(NDT, acc1, invdt, 128, x_dt, 128,
                                                    od1_wl, od1_wr, dt1_wl, dt1_wr,
                                                    od1_b, dt1_b, h, d1, 1);

    // agg(h) over rev edges (shared by od2 and od3)
    k_scatter<<<cdiv((long long)E2 * 32, TB), TB>>>(h, rsrc, rdst, E2, acc2, cntod);
    k_inv<<<cdiv(NOD, TB), TB>>>(cntod, invod, NOD);

    gemm_mma<128><<<dim3(cdiv(NOD, 128), 1), 256>>>(NOD, acc2, invod, 128, x_od, 64,
                                                    od2_wl, od2_wr, nullptr, nullptr,
                                                    od2_b, nullptr, od2b, nullptr, 1);
    gemm_mma<128><<<dim3(cdiv(NOD, 128), 1), 256>>>(NOD, acc2, invod, 128, od2b, 128,
                                                    od3_wl, od3_wr, nullptr, nullptr,
                                                    od3_b, nullptr, od3b, nullptr, 1);
    gemm_mma<64><<<dim3(cdiv(NOD, 128), 1), 256>>>(NOD, od3b, nullptr, 128, nullptr, 0,
                                                   od_lw, nullptr, nullptr, nullptr,
                                                   od_lb, nullptr, zod, nullptr, 0);

    // agg(d1) over dt graph (reuse invdt)
    k_scatter<<<cdiv((long long)E1 * 32, TB), TB>>>(d1, r1, c1, E1, acc3, nullptr);
    gemm_mma<128><<<dim3(cdiv(NDT, 128), 1), 256>>>(NDT, acc3, invdt, 128, d1, 128,
                                                    dt2_wl, dt2_wr, nullptr, nullptr,
                                                    dt2_b, nullptr, d2, nullptr, 1);
    gemm_mma<64><<<dim3(cdiv(NDT, 128), 1), 256>>>(NDT, d2, nullptr, 128, nullptr, 0,
                                                   dt_lw, nullptr, nullptr, nullptr,
                                                   dt_lb, nullptr, zdt, nullptr, 0);

    // fused edge decoder
    dec_mma<<<cdiv(EL, 128), 256>>>(EL, zod, zdt, elsrc, eldst,
                                    dec_w1, dec_b1, dec_w2, dec_b2, out);
}

// round 5
// speedup vs baseline: 2.4851x; 1.0731x over previous
#include <cuda_runtime.h>
#include <math.h>

#define NDT 30000
#define NOD 10000
#define E1MAX 500000
#define E2MAX 300000

static inline int cdiv(long long a, long long b) { return (int)((a + b - 1) / b); }

// ---------------- tf32 mma helpers ---------------------------------------------
__device__ __forceinline__ float to_tf32(float x) {
    unsigned u;
    asm("cvt.rna.tf32.f32 %0, %1;" : "=r"(u) : "f"(x));
    return __uint_as_float(u);
}
#define MMA_TF32(d, a, b0, b1)                                          \
    asm volatile("mma.sync.aligned.m16n8k8.row.col.f32.tf32.tf32.f32 "  \
                 "{%0,%1,%2,%3}, {%4,%5,%6,%7}, {%8,%9}, {%0,%1,%2,%3};" \
                 : "+f"((d)[0]), "+f"((d)[1]), "+f"((d)[2]), "+f"((d)[3]) \
                 : "r"((a)[0]), "r"((a)[1]), "r"((a)[2]), "r"((a)[3]),  \
                   "r"(b0), "r"(b1))

// ---------------- device scratch ----------------------------------------------
__device__ float g_acc1[NDT * 128];
__device__ float g_acc2[NOD * 128];
__device__ float g_acc3[NDT * 128];
__device__ float g_h [NDT * 128];
__device__ float g_d1[NDT * 128];
__device__ float g_od2[NOD * 128];
__device__ float g_od3[NOD * 128];
__device__ float g_zod[NOD * 64];
__device__ float g_d2[NDT * 128];
__device__ float g_zdt[NDT * 64];
// CSR scratch
__device__ int g_deg1[NDT];
__device__ int g_rp1[NDT + 1];
__device__ int g_fill1[NDT];
__device__ int g_es1[E1MAX];
__device__ int g_deg2[NOD];
__device__ int g_rp2[NOD + 1];
__device__ int g_fill2[NOD];
__device__ int g_es2[E2MAX];

// ---------------- CSR build kernels --------------------------------------------
__global__ void k_degree(const int* __restrict__ dst, int E, int* __restrict__ deg) {
    int i = blockIdx.x * blockDim.x + threadIdx.x;
    if (i < E) atomicAdd(deg + __ldg(dst + i), 1);
}

// single-block exclusive prefix over n degrees -> rowptr[n+1]; also zero fill[].
__global__ void k_prefix(const int* __restrict__ deg, int n,
                         int* __restrict__ rowptr, int* __restrict__ fill) {
    __shared__ int part[256];
    int t = threadIdx.x;
    int chunk = (n + 255) / 256;
    int beg = t * chunk;
    int end = min(beg + chunk, n);
    int s = 0;
    for (int i = beg; i < end; i++) s += deg[i];
    part[t] = s;
    __syncthreads();
    if (t == 0) {
        int a = 0;
        for (int i = 0; i < 256; i++) { int v = part[i]; part[i] = a; a += v; }
        rowptr[n] = a;
    }
    __syncthreads();
    int a = part[t];
    for (int i = beg; i < end; i++) {
        rowptr[i] = a;
        fill[i] = 0;
        a += deg[i];
    }
}

__global__ void k_reorder(const int* __restrict__ src, const int* __restrict__ dst, int E,
                          const int* __restrict__ rowptr, int* __restrict__ fill,
                          int* __restrict__ es) {
    int i = blockIdx.x * blockDim.x + threadIdx.x;
    if (i >= E) return;
    int d = __ldg(dst + i);
    int pos = atomicAdd(fill + d, 1);
    es[rowptr[d] + pos] = __ldg(src + i);
}

// ---------------- mean aggregation: one warp per dst row -----------------------
// acc[d] = mean over edges(src->d) of X[src], X width 128. Plain stores only.
__global__ __launch_bounds__(256)
void k_agg(const float* __restrict__ X, const int* __restrict__ es,
           const int* __restrict__ rowptr, float* __restrict__ acc, int n) {
    int w = (blockIdx.x * blockDim.x + threadIdx.x) >> 5;
    if (w >= n) return;
    int lane = threadIdx.x & 31;
    int beg = __ldg(rowptr + w);
    int end = __ldg(rowptr + w + 1);
    float4 s = make_float4(0.f, 0.f, 0.f, 0.f);
    for (int base = beg; base < end; base += 32) {
        int p = 0;
        if (base + lane < end) p = __ldg(es + base + lane);
        int cnt = min(32, end - base);
        for (int j = 0; j < cnt; j++) {
            int sr = __shfl_sync(0xffffffffu, p, j);
            float4 v = *(const float4*)(X + (size_t)sr * 128 + lane * 4);
            s.x += v.x; s.y += v.y; s.z += v.z; s.w += v.w;
        }
    }
    float inv = 1.f / fmaxf((float)(end - beg), 1.f);
    s.x *= inv; s.y *= inv; s.z *= inv; s.w *= inv;
    *(float4*)(acc + (size_t)w * 128 + lane * 4) = s;
}

// ---------------- tf32 tensor-core GEMM ----------------------------------------
// Y = act( A @ W1 + B @ W2 + bias ); optional 2nd weight set via blockIdx.y.
// 512 threads, warp grid 4m x 4n; BR in {128, 64}; warp tile (16*MI) x (NCOLS/4).
template <int NCOLS, int BR>
__global__ __launch_bounds__(512, 2)
void gemm_mma(int M,
              const float* __restrict__ A, int K1,
              const float* __restrict__ B, int K2,
              const float* __restrict__ W1, const float* __restrict__ W2,
              const float* __restrict__ W1b, const float* __restrict__ W2b,
              const float* __restrict__ bias, const float* __restrict__ biasb,
              float* __restrict__ Y, float* __restrict__ Yb, int do_relu) {
    constexpr int KC = 16;
    constexpr int AST = 20;
    constexpr int WST = NCOLS + 8;
    constexpr int MI = BR / 64;           // m16 frags per warp
    constexpr int NCW = NCOLS / 4;        // cols per warp
    constexpr int NT = NCW / 8;           // n8 frags per warp
    constexpr int APT = BR * KC / 512;    // A floats staged per thread (4 or 2)
    constexpr int WPT = NCOLS * KC / 512; // W floats staged per thread (4 or 2)
    __shared__ float As[2][BR][AST];
    __shared__ float Ws[2][KC][WST];

    const float* w1 = blockIdx.y ? W1b : W1;
    const float* w2 = blockIdx.y ? W2b : W2;
    const float* bs = blockIdx.y ? biasb : bias;
    float* y        = blockIdx.y ? Yb : Y;

    const int t = threadIdx.x;
    const int lane = t & 31;
    const int wid = t >> 5;
    const int warp_m = wid >> 2;
    const int warp_n = wid & 3;
    const int grp = lane >> 2;
    const int qid = lane & 3;
    const int row0 = blockIdx.x * BR;
    // A staging coords
    const int lr = (BR == 128) ? (t >> 2) : (t >> 3);
    const int lk = (BR == 128) ? ((t & 3) * 4) : ((t & 7) * 2);
    const int grow = row0 + lr;
    // W staging coords
    const int wkk = t >> 5;                      // 16 k-rows
    const int wc = (lane) * WPT;

    const int n1 = K1 / KC;
    const int n2 = (B != nullptr) ? (K2 / KC) : 0;
    const int nch = n1 + n2;

    float pa[APT];
    float pw[WPT];

    auto loadX = [&](int cc) {
        const float* Xp; int stride, k0;
        if (cc < n1) { Xp = A; stride = K1; k0 = cc * KC; }
        else         { Xp = B; stride = K2; k0 = (cc - n1) * KC; }
#pragma unroll
        for (int i = 0; i < APT; i++) pa[i] = 0.f;
        if (grow < M) {
            const float* base = Xp + (size_t)grow * stride + k0 + lk;
            if (APT == 4) {
                float4 v = *(const float4*)base;
                pa[0] = v.x; pa[1] = v.y; pa[2] = v.z; pa[3] = v.w;
            } else {
                float2 v = *(const float2*)base;
                pa[0] = v.x; pa[1] = v.y;
            }
        }
    };
    auto loadW = [&](int cc) {
        const float* Wp; int k0;
        if (cc < n1) { Wp = w1; k0 = cc * KC; }
        else         { Wp = w2; k0 = (cc - n1) * KC; }
        const float* base = Wp + (size_t)(k0 + wkk) * NCOLS + wc;
        if (WPT == 4) *(float4*)&pw[0] = *(const float4*)base;
        else          *(float2*)&pw[0] = *(const float2*)base;
    };
    auto stage = [&](int buf) {
#pragma unroll
        for (int i = 0; i < APT; i++) As[buf][lr][lk + i] = to_tf32(pa[i]);
#pragma unroll
        for (int j = 0; j < WPT; j++) Ws[buf][wkk][wc + j] = to_tf32(pw[j]);
    };

    float acc[MI][NT][4];
#pragma unroll
    for (int mi = 0; mi < MI; mi++)
#pragma unroll
        for (int ni = 0; ni < NT; ni++)
#pragma unroll
            for (int c = 0; c < 4; c++) acc[mi][ni][c] = 0.f;

    loadX(0); loadW(0); stage(0);

    for (int cc = 0; cc < nch; ++cc) {
        const int buf = cc & 1;
        __syncthreads();
        if (cc + 1 < nch) { loadX(cc + 1); loadW(cc + 1); }
#pragma unroll
        for (int ks = 0; ks < KC; ks += 8) {
            unsigned af[MI][4];
#pragma unroll
            for (int mi = 0; mi < MI; mi++) {
                int r = warp_m * (16 * MI) + mi * 16 + grp;
                af[mi][0] = __float_as_uint(As[buf][r    ][ks + qid]);
                af[mi][1] = __float_as_uint(As[buf][r + 8][ks + qid]);
                af[mi][2] = __float_as_uint(As[buf][r    ][ks + qid + 4]);
                af[mi][3] = __float_as_uint(As[buf][r + 8][ks + qid + 4]);
            }
#pragma unroll
            for (int ni = 0; ni < NT; ni++) {
                int c = warp_n * NCW + ni * 8 + grp;
                unsigned b0 = __float_as_uint(Ws[buf][ks + qid    ][c]);
                unsigned b1 = __float_as_uint(Ws[buf][ks + qid + 4][c]);
#pragma unroll
                for (int mi = 0; mi < MI; mi++) MMA_TF32(acc[mi][ni], af[mi], b0, b1);
            }
        }
        if (cc + 1 < nch) stage(buf ^ 1);
    }

    // epilogue
#pragma unroll
    for (int ni = 0; ni < NT; ni++) {
        int cb = warp_n * NCW + ni * 8 + 2 * qid;
        float2 bv = make_float2(0.f, 0.f);
        if (bs != nullptr) bv = *(const float2*)(bs + cb);
#pragma unroll
        for (int mi = 0; mi < MI; mi++) {
            int r0 = row0 + warp_m * (16 * MI) + mi * 16 + grp;
            float v0 = acc[mi][ni][0] + bv.x;
            float v1 = acc[mi][ni][1] + bv.y;
            float v2 = acc[mi][ni][2] + bv.x;
            float v3 = acc[mi][ni][3] + bv.y;
            if (do_relu) {
                v0 = fmaxf(v0, 0.f); v1 = fmaxf(v1, 0.f);
                v2 = fmaxf(v2, 0.f); v3 = fmaxf(v3, 0.f);
            }
            if (r0 < M)     *(float2*)(y + (size_t)r0 * NCOLS + cb) = make_float2(v0, v1);
            if (r0 + 8 < M) *(float2*)(y + (size_t)(r0 + 8) * NCOLS + cb) = make_float2(v2, v3);
        }
    }
}

// ---------------- fused edge decoder (tf32 mma, 512 thr) -----------------------
// out[e] = sigmoid( relu([zod[esrc[e]] | zdt[edst[e]]] @ W1 + b1) . w2 + b2 )
__global__ __launch_bounds__(512, 2)
void dec_mma(int M, const float* __restrict__ zod, const float* __restrict__ zdt,
             const int* __restrict__ esrc, const int* __restrict__ edst,
             const float* __restrict__ W1, const float* __restrict__ b1,
             const float* __restrict__ w2, const float* __restrict__ b2p,
             float* __restrict__ out) {
    constexpr int NC = 64;
    constexpr int BR = 128;
    constexpr int KC = 16;
    constexpr int AST = 20;
    constexpr int WST = NC + 8;
    constexpr int NCW = 16;
    constexpr int NT = 2;
    constexpr int NCH = 8;   // K=128
    __shared__ float As[2][BR][AST];
    __shared__ float Ws[2][KC][WST];
    __shared__ float Red[BR][17];

    const int t = threadIdx.x;
    const int lane = t & 31;
    const int wid = t >> 5;
    const int warp_m = wid >> 2;
    const int warp_n = wid & 3;
    const int grp = lane >> 2;
    const int qid = lane & 3;
    const int row0 = blockIdx.x * BR;
    const int lr = t >> 2;
    const int lk = (t & 3) * 4;
    const int grow = row0 + lr;
    const int wkk = t >> 5;
    const int wc = lane * 2;

    int si = 0, di = 0;
    if (grow < M) { si = __ldg(esrc + grow); di = __ldg(edst + grow); }

    float pa[4];
    float pw[2];

    auto loadX = [&](int cc) {
#pragma unroll
        for (int i = 0; i < 4; i++) pa[i] = 0.f;
        if (grow < M) {
            int k = cc * KC + lk;
            const float* base = (k < 64) ? (zod + (size_t)si * 64 + k)
                                         : (zdt + (size_t)di * 64 + (k - 64));
            float4 v = *(const float4*)base;
            pa[0] = v.x; pa[1] = v.y; pa[2] = v.z; pa[3] = v.w;
        }
    };
    auto loadW = [&](int cc) {
        const float* base = W1 + (size_t)(cc * KC + wkk) * NC + wc;
        *(float2*)&pw[0] = *(const float2*)base;
    };
    auto stage = [&](int buf) {
#pragma unroll
        for (int i = 0; i < 4; i++) As[buf][lr][lk + i] = to_tf32(pa[i]);
        Ws[buf][wkk][wc] = to_tf32(pw[0]);
        Ws[buf][wkk][wc + 1] = to_tf32(pw[1]);
    };

    float acc[2][NT][4];
#pragma unroll
    for (int mi = 0; mi < 2; mi++)
#pragma unroll
        for (int ni = 0; ni < NT; ni++)
#pragma unroll
            for (int c = 0; c < 4; c++) acc[mi][ni][c] = 0.f;

    loadX(0); loadW(0); stage(0);

#pragma unroll 1
    for (int cc = 0; cc < NCH; ++cc) {
        const int buf = cc & 1;
        __syncthreads();
        if (cc + 1 < NCH) { loadX(cc + 1); loadW(cc + 1); }
#pragma unroll
        for (int ks = 0; ks < KC; ks += 8) {
            unsigned af[2][4];
#pragma unroll
            for (int mi = 0; mi < 2; mi++) {
                int r = warp_m * 32 + mi * 16 + grp;
                af[mi][0] = __float_as_uint(As[buf][r    ][ks + qid]);
                af[mi][1] = __float_as_uint(As[buf][r + 8][ks + qid]);
                af[mi][2] = __float_as_uint(As[buf][r    ][ks + qid + 4]);
                af[mi][3] = __float_as_uint(As[buf][r + 8][ks + qid + 4]);
            }
#pragma unroll
            for (int ni = 0; ni < NT; ni++) {
                int c = warp_n * NCW + ni * 8 + grp;
                unsigned b0 = __float_as_uint(Ws[buf][ks + qid    ][c]);
                unsigned b1 = __float_as_uint(Ws[buf][ks + qid + 4][c]);
                MMA_TF32(acc[0][ni], af[0], b0, b1);
                MMA_TF32(acc[1][ni], af[1], b0, b1);
            }
        }
        if (cc + 1 < NCH) stage(buf ^ 1);
    }

    // epilogue: bias + relu + partial dot with w2 -> smem transpose reduce
    float p[2][2] = {{0.f, 0.f}, {0.f, 0.f}};
#pragma unroll
    for (int ni = 0; ni < NT; ni++) {
        int cb = warp_n * NCW + ni * 8 + 2 * qid;
        float2 bv = *(const float2*)(b1 + cb);
        float2 wv = *(const float2*)(w2 + cb);
#pragma unroll
        for (int mi = 0; mi < 2; mi++) {
            p[mi][0] += fmaxf(acc[mi][ni][0] + bv.x, 0.f) * wv.x
                      + fmaxf(acc[mi][ni][1] + bv.y, 0.f) * wv.y;
            p[mi][1] += fmaxf(acc[mi][ni][2] + bv.x, 0.f) * wv.x
                      + fmaxf(acc[mi][ni][3] + bv.y, 0.f) * wv.y;
        }
    }
    __syncthreads();
#pragma unroll
    for (int mi = 0; mi < 2; mi++) {
        Red[warp_m * 32 + mi * 16 + grp    ][warp_n * 4 + qid] = p[mi][0];
        Red[warp_m * 32 + mi * 16 + grp + 8][warp_n * 4 + qid] = p[mi][1];
    }
    __syncthreads();
    if (t < BR) {
        int r = row0 + t;
        if (r < M) {
            float s = 0.f;
#pragma unroll
            for (int j = 0; j < 16; j++) s += Red[t][j];
            out[r] = 1.f / (1.f + expf(-(s + b2p[0])));
        }
    }
}

// ---------------- host orchestration ------------------------------------------
extern "C" void kernel_launch(void* const* d_in, const int* in_sizes, int n_in,
                              void* d_out, int out_size) {
    const float* x_dt   = (const float*)d_in[0];
    const float* x_od   = (const float*)d_in[1];
    const int*   ei_dt  = (const int*)  d_in[2];
    const int*   rsrc   = (const int*)  d_in[3];
    const int*   rdst   = (const int*)  d_in[4];
    const int*   elsrc  = (const int*)  d_in[5];
    const int*   eldst  = (const int*)  d_in[6];
    const float* od1_wl = (const float*)d_in[7];
    const float* od1_wr = (const float*)d_in[8];
    const float* od1_b  = (const float*)d_in[9];
    const float* od2_wl = (const float*)d_in[10];
    const float* od2_wr = (const float*)d_in[11];
    const float* od2_b  = (const float*)d_in[12];
    const float* od3_wl = (const float*)d_in[13];
    const float* od3_wr = (const float*)d_in[14];
    const float* od3_b  = (const float*)d_in[15];
    const float* od_lw  = (const float*)d_in[16];
    const float* od_lb  = (const float*)d_in[17];
    const float* dt1_wl = (const float*)d_in[18];
    const float* dt1_wr = (const float*)d_in[19];
    const float* dt1_b  = (const float*)d_in[20];
    const float* dt2_wl = (const float*)d_in[21];
    const float* dt2_wr = (const float*)d_in[22];
    const float* dt2_b  = (const float*)d_in[23];
    const float* dt_lw  = (const float*)d_in[24];
    const float* dt_lb  = (const float*)d_in[25];
    const float* dec_w1 = (const float*)d_in[26];
    const float* dec_b1 = (const float*)d_in[27];
    const float* dec_w2 = (const float*)d_in[28];
    const float* dec_b2 = (const float*)d_in[29];
    float* out = (float*)d_out;

    const int E1 = in_sizes[2] / 2;
    const int E2 = in_sizes[3];
    const int EL = in_sizes[5];
    const int* r1 = ei_dt;
    const int* c1 = ei_dt + E1;

    float *acc1, *acc2, *acc3, *h, *d1, *od2b, *od3b, *zod, *d2, *zdt;
    int *deg1, *rp1, *fill1, *es1, *deg2, *rp2, *fill2, *es2;
    cudaGetSymbolAddress((void**)&acc1, g_acc1);
    cudaGetSymbolAddress((void**)&acc2, g_acc2);
    cudaGetSymbolAddress((void**)&acc3, g_acc3);
    cudaGetSymbolAddress((void**)&h,   g_h);
    cudaGetSymbolAddress((void**)&d1,  g_d1);
    cudaGetSymbolAddress((void**)&od2b, g_od2);
    cudaGetSymbolAddress((void**)&od3b, g_od3);
    cudaGetSymbolAddress((void**)&zod, g_zod);
    cudaGetSymbolAddress((void**)&d2,  g_d2);
    cudaGetSymbolAddress((void**)&zdt, g_zdt);
    cudaGetSymbolAddress((void**)&deg1, g_deg1);
    cudaGetSymbolAddress((void**)&rp1, g_rp1);
    cudaGetSymbolAddress((void**)&fill1, g_fill1);
    cudaGetSymbolAddress((void**)&es1, g_es1);
    cudaGetSymbolAddress((void**)&deg2, g_deg2);
    cudaGetSymbolAddress((void**)&rp2, g_rp2);
    cudaGetSymbolAddress((void**)&fill2, g_fill2);
    cudaGetSymbolAddress((void**)&es2, g_es2);

    const int TB = 256;

    // ---- CSR build for both graphs (E1 CSR reused twice) ----
    cudaMemsetAsync(deg1, 0, NDT * sizeof(int));
    cudaMemsetAsync(deg2, 0, NOD * sizeof(int));
    k_degree<<<cdiv(E1, TB), TB>>>(c1, E1, deg1);
    k_degree<<<cdiv(E2, TB), TB>>>(rdst, E2, deg2);
    k_prefix<<<1, 256>>>(deg1, NDT, rp1, fill1);
    k_prefix<<<1, 256>>>(deg2, NOD, rp2, fill2);
    k_reorder<<<cdiv(E1, TB), TB>>>(r1, c1, E1, rp1, fill1, es1);
    k_reorder<<<cdiv(E2, TB), TB>>>(rsrc, rdst, E2, rp2, fill2, es2);

    // ---- pipeline ----
    k_agg<<<cdiv((long long)NDT * 32, TB), TB>>>(x_dt, es1, rp1, acc1, NDT);
    gemm_mma<128, 128><<<dim3(cdiv(NDT, 128), 2), 512>>>(
        NDT, acc1, 128, x_dt, 128, od1_wl, od1_wr, dt1_wl, dt1_wr,
        od1_b, dt1_b, h, d1, 1);

    k_agg<<<cdiv((long long)NOD * 32, TB), TB>>>(h, es2, rp2, acc2, NOD);
    gemm_mma<128, 64><<<dim3(cdiv(NOD, 64), 1), 512>>>(
        NOD, acc2, 128, x_od, 64, od2_wl, od2_wr, nullptr, nullptr,
        od2_b, nullptr, od2b, nullptr, 1);
    gemm_mma<128, 64><<<dim3(cdiv(NOD, 64), 1), 512>>>(
        NOD, acc2, 128, od2b, 128, od3_wl, od3_wr, nullptr, nullptr,
        od3_b, nullptr, od3b, nullptr, 1);
    gemm_mma<64, 64><<<dim3(cdiv(NOD, 64), 1), 512>>>(
        NOD, od3b, 128, nullptr, 0, od_lw, nullptr, nullptr, nullptr,
        od_lb, nullptr, zod, nullptr, 0);

    k_agg<<<cdiv((long long)NDT * 32, TB), TB>>>(d1, es1, rp1, acc3, NDT);
    gemm_mma<128, 128><<<dim3(cdiv(NDT, 128), 1), 512>>>(
        NDT, acc3, 128, d1, 128, dt2_wl, dt2_wr, nullptr, nullptr,
        dt2_b, nullptr, d2, nullptr, 1);
    gemm_mma<64, 128><<<dim3(cdiv(NDT, 128), 1), 512>>>(
        NDT, d2, 128, nullptr, 0, dt_lw, nullptr, nullptr, nullptr,
        dt_lb, nullptr, zdt, nullptr, 0);

    dec_mma<<<cdiv(EL, 128), 512>>>(EL, zod, zdt, elsrc, eldst,
                                    dec_w1, dec_b1, dec_w2, dec_b2, out);
}

// round 6
// speedup vs baseline: 2.9633x; 1.1924x over previous
#include <cuda_runtime.h>
#include <cuda_fp16.h>
#include <math.h>

#define NDT 30000
#define NOD 10000
#define E1MAX 500000
#define E2MAX 300000
#define WSLOT 16384

static inline int cdiv(long long a, long long b) { return (int)((a + b - 1) / b); }

// ---------------- fp16 mma helper ----------------------------------------------
#define MMA_F16(d, a, b0, b1)                                              \
    asm volatile("mma.sync.aligned.m16n8k16.row.col.f32.f16.f16.f32 "      \
                 "{%0,%1,%2,%3}, {%4,%5,%6,%7}, {%8,%9}, {%0,%1,%2,%3};"   \
                 : "+f"((d)[0]), "+f"((d)[1]), "+f"((d)[2]), "+f"((d)[3])  \
                 : "r"((a)[0]), "r"((a)[1]), "r"((a)[2]), "r"((a)[3]),     \
                   "r"(b0), "r"(b1))

// ---------------- device scratch ----------------------------------------------
__device__ float g_acc1[NDT * 128];
__device__ float g_acc2[NOD * 128];
__device__ float g_acc3[NDT * 128];
__device__ float g_h [NDT * 128];
__device__ float g_d1[NDT * 128];
__device__ float g_od2[NOD * 128];
__device__ float g_od3[NOD * 128];
__device__ float g_d2[NDT * 128];
__device__ __half g_zodh[NOD * 64];
__device__ __half g_zdth[NDT * 64];
__device__ __half g_wh[13 * WSLOT];
// CSR scratch
__device__ int g_deg1[NDT];
__device__ int g_rp1[NDT + 1];
__device__ int g_fill1[NDT];
__device__ int g_es1[E1MAX];
__device__ int g_deg2[NOD];
__device__ int g_rp2[NOD + 1];
__device__ int g_fill2[NOD];
__device__ int g_es2[E2MAX];

// ---------------- weight transpose+convert: W[K][N] f32 -> Wt[N][K] f16 --------
struct WTList {
    const float* src[13];
    int K[13];
    int N[13];
};
__global__ void k_wt(WTList L, __half* __restrict__ dst) {
    int w = blockIdx.y;
    int K = L.K[w], N = L.N[w];
    const float* s = L.src[w];
    __half* d = dst + (size_t)w * WSLOT;
    int total = K * N;
    for (int i = blockIdx.x * blockDim.x + threadIdx.x; i < total;
         i += gridDim.x * blockDim.x) {
        int n = i / K, k = i - n * K;
        d[i] = __float2half(s[k * N + n]);
    }
}

// ---------------- CSR build ----------------------------------------------------
__global__ void k_degree(const int* __restrict__ dst, int E, int* __restrict__ deg) {
    int i = blockIdx.x * blockDim.x + threadIdx.x;
    if (i < E) atomicAdd(deg + __ldg(dst + i), 1);
}

// parallel exclusive scan: block 0 -> graph1, block 1 -> graph2. 1024 threads.
__global__ void k_scan2(const int* __restrict__ deg1, int n1, int* __restrict__ rp1,
                        int* __restrict__ fill1,
                        const int* __restrict__ deg2, int n2, int* __restrict__ rp2,
                        int* __restrict__ fill2) {
    const int* deg; int n; int* rp; int* fill;
    if (blockIdx.x == 0) { deg = deg1; n = n1; rp = rp1; fill = fill1; }
    else                 { deg = deg2; n = n2; rp = rp2; fill = fill2; }
    __shared__ int wsum[32];
    int t = threadIdx.x, lane = t & 31, w = t >> 5;
    int chunk = (n + 1023) >> 10;
    int beg = min(t * chunk, n), end = min(beg + chunk, n);
    int s = 0;
    for (int i = beg; i < end; i++) s += deg[i];
    int own = s;
#pragma unroll
    for (int o = 1; o < 32; o <<= 1) {
        int v = __shfl_up_sync(0xffffffffu, s, o);
        if (lane >= o) s += v;
    }
    if (lane == 31) wsum[w] = s;
    __syncthreads();
    if (w == 0) {
        int v = wsum[lane];
        int sv = v;
#pragma unroll
        for (int o = 1; o < 32; o <<= 1) {
            int u = __shfl_up_sync(0xffffffffu, sv, o);
            if (lane >= o) sv += u;
        }
        wsum[lane] = sv - v;
        if (lane == 31) rp[n] = sv;
    }
    __syncthreads();
    int base = wsum[w] + s - own;
    for (int i = beg; i < end; i++) { rp[i] = base; fill[i] = 0; base += deg[i]; }
}

__global__ void k_reorder(const int* __restrict__ src, const int* __restrict__ dst, int E,
                          const int* __restrict__ rowptr, int* __restrict__ fill,
                          int* __restrict__ es) {
    int i = blockIdx.x * blockDim.x + threadIdx.x;
    if (i >= E) return;
    int d = __ldg(dst + i);
    int pos = atomicAdd(fill + d, 1);
    es[rowptr[d] + pos] = __ldg(src + i);
}

// ---------------- mean aggregation: one warp per dst row -----------------------
__global__ __launch_bounds__(256)
void k_agg(const float* __restrict__ X, const int* __restrict__ es,
           const int* __restrict__ rowptr, float* __restrict__ acc, int n) {
    int w = (blockIdx.x * blockDim.x + threadIdx.x) >> 5;
    if (w >= n) return;
    int lane = threadIdx.x & 31;
    int beg = __ldg(rowptr + w);
    int end = __ldg(rowptr + w + 1);
    float4 s = make_float4(0.f, 0.f, 0.f, 0.f);
    for (int base = beg; base < end; base += 32) {
        int p = 0;
        if (base + lane < end) p = __ldg(es + base + lane);
        int cnt = min(32, end - base);
        for (int j = 0; j < cnt; j++) {
            int sr = __shfl_sync(0xffffffffu, p, j);
            float4 v = *(const float4*)(X + (size_t)sr * 128 + lane * 4);
            s.x += v.x; s.y += v.y; s.z += v.z; s.w += v.w;
        }
    }
    float inv = 1.f / fmaxf((float)(end - beg), 1.f);
    s.x *= inv; s.y *= inv; s.z *= inv; s.w *= inv;
    *(float4*)(acc + (size_t)w * 128 + lane * 4) = s;
}

// ---------------- fp16 tensor-core GEMM ----------------------------------------
// Y = act( A @ W1 + B @ W2 + bias ), weights pre-transposed f16 [N][K].
// 512 threads, warps 4m x 4n; outputs f32 (Y) or f16 (Yh).
template <int NCOLS, int BR>
__global__ __launch_bounds__(512, 2)
void gemm_h(int M,
            const float* __restrict__ A, int K1,
            const float* __restrict__ B, int K2,
            const __half* __restrict__ Wt1, const __half* __restrict__ Wt2,
            const __half* __restrict__ Wt1b, const __half* __restrict__ Wt2b,
            const float* __restrict__ bias, const float* __restrict__ biasb,
            float* __restrict__ Y, float* __restrict__ Yb,
            __half* __restrict__ Yh, int do_relu) {
    constexpr int KC = 16;
    constexpr int AST = 24;               // half stride, conflict-free frags
    constexpr int MI = BR / 64;
    constexpr int NCW = NCOLS / 4;
    constexpr int NT = NCW / 8;
    constexpr int APT = BR * KC / 512;    // floats per thread (4 or 2)
    __shared__ __half As[2][BR][AST];
    __shared__ __half Ws[2][NCOLS][AST];

    const __half* w1 = blockIdx.y ? Wt1b : Wt1;
    const __half* w2 = blockIdx.y ? Wt2b : Wt2;
    const float* bs  = blockIdx.y ? biasb : bias;
    float* y         = blockIdx.y ? Yb : Y;

    const int t = threadIdx.x;
    const int lane = t & 31;
    const int wid = t >> 5;
    const int warp_m = wid >> 2;
    const int warp_n = wid & 3;
    const int grp = lane >> 2;
    const int qid = lane & 3;
    const int row0 = blockIdx.x * BR;
    const int lr = (BR == 128) ? (t >> 2) : (t >> 3);
    const int lk = (BR == 128) ? ((t & 3) * 4) : ((t & 7) * 2);
    const int grow = row0 + lr;
    const int wn = (NCOLS == 128) ? (t >> 2) : (t >> 3);
    const int wk = (NCOLS == 128) ? ((t & 3) * 4) : ((t & 7) * 2);

    const int n1 = K1 / KC;
    const int n2 = (B != nullptr) ? (K2 / KC) : 0;
    const int nch = n1 + n2;

    float pa[APT];
    uint2 pw;

    auto loadX = [&](int cc) {
        const float* Xp; int stride, k0;
        if (cc < n1) { Xp = A; stride = K1; k0 = cc * KC; }
        else         { Xp = B; stride = K2; k0 = (cc - n1) * KC; }
#pragma unroll
        for (int i = 0; i < APT; i++) pa[i] = 0.f;
        if (grow < M) {
            const float* base = Xp + (size_t)grow * stride + k0 + lk;
            if (APT == 4) {
                float4 v = *(const float4*)base;
                pa[0] = v.x; pa[1] = v.y; pa[2] = v.z; pa[3] = v.w;
            } else {
                float2 v = *(const float2*)base;
                pa[0] = v.x; pa[1] = v.y;
            }
        }
    };
    auto loadW = [&](int cc) {
        const __half* Wp; int stride, k0;
        if (cc < n1) { Wp = w1; stride = K1; k0 = cc * KC; }
        else         { Wp = w2; stride = K2; k0 = (cc - n1) * KC; }
        const __half* base = Wp + (size_t)wn * stride + k0 + wk;
        if (NCOLS == 128) pw = *(const uint2*)base;
        else              pw.x = *(const unsigned*)base;
    };
    auto stage = [&](int buf) {
        if (APT == 4) {
            __half2 h0 = __floats2half2_rn(pa[0], pa[1]);
            __half2 h1 = __floats2half2_rn(pa[2], pa[3]);
            *(uint2*)&As[buf][lr][lk] =
                make_uint2(*(unsigned*)&h0, *(unsigned*)&h1);
        } else {
            __half2 h0 = __floats2half2_rn(pa[0], pa[1]);
            *(unsigned*)&As[buf][lr][lk] = *(unsigned*)&h0;
        }
        if (NCOLS == 128) *(uint2*)&Ws[buf][wn][wk] = pw;
        else              *(unsigned*)&Ws[buf][wn][wk] = pw.x;
    };

    float acc[MI][NT][4];
#pragma unroll
    for (int mi = 0; mi < MI; mi++)
#pragma unroll
        for (int ni = 0; ni < NT; ni++)
#pragma unroll
            for (int c = 0; c < 4; c++) acc[mi][ni][c] = 0.f;

    loadX(0); loadW(0); stage(0);

    for (int cc = 0; cc < nch; ++cc) {
        const int buf = cc & 1;
        __syncthreads();
        if (cc + 1 < nch) { loadX(cc + 1); loadW(cc + 1); }
        unsigned af[MI][4];
#pragma unroll
        for (int mi = 0; mi < MI; mi++) {
            int r = warp_m * (16 * MI) + mi * 16 + grp;
            af[mi][0] = *(const unsigned*)&As[buf][r    ][2 * qid];
            af[mi][1] = *(const unsigned*)&As[buf][r + 8][2 * qid];
            af[mi][2] = *(const unsigned*)&As[buf][r    ][2 * qid + 8];
            af[mi][3] = *(const unsigned*)&As[buf][r + 8][2 * qid + 8];
        }
#pragma unroll
        for (int ni = 0; ni < NT; ni++) {
            int c = warp_n * NCW + ni * 8 + grp;
            unsigned b0 = *(const unsigned*)&Ws[buf][c][2 * qid];
            unsigned b1 = *(const unsigned*)&Ws[buf][c][2 * qid + 8];
#pragma unroll
            for (int mi = 0; mi < MI; mi++) MMA_F16(acc[mi][ni], af[mi], b0, b1);
        }
        if (cc + 1 < nch) stage(buf ^ 1);
    }

    // epilogue
#pragma unroll
    for (int ni = 0; ni < NT; ni++) {
        int cb = warp_n * NCW + ni * 8 + 2 * qid;
        float2 bv = make_float2(0.f, 0.f);
        if (bs != nullptr) bv = *(const float2*)(bs + cb);
#pragma unroll
        for (int mi = 0; mi < MI; mi++) {
            int r0 = row0 + warp_m * (16 * MI) + mi * 16 + grp;
            float v0 = acc[mi][ni][0] + bv.x;
            float v1 = acc[mi][ni][1] + bv.y;
            float v2 = acc[mi][ni][2] + bv.x;
            float v3 = acc[mi][ni][3] + bv.y;
            if (do_relu) {
                v0 = fmaxf(v0, 0.f); v1 = fmaxf(v1, 0.f);
                v2 = fmaxf(v2, 0.f); v3 = fmaxf(v3, 0.f);
            }
            if (Yh != nullptr) {
                __half2 h0 = __floats2half2_rn(v0, v1);
                __half2 h1 = __floats2half2_rn(v2, v3);
                if (r0 < M)     *(__half2*)(Yh + (size_t)r0 * NCOLS + cb) = h0;
                if (r0 + 8 < M) *(__half2*)(Yh + (size_t)(r0 + 8) * NCOLS + cb) = h1;
            } else {
                if (r0 < M)     *(float2*)(y + (size_t)r0 * NCOLS + cb) = make_float2(v0, v1);
                if (r0 + 8 < M) *(float2*)(y + (size_t)(r0 + 8) * NCOLS + cb) = make_float2(v2, v3);
            }
        }
    }
}

// ---------------- fused edge decoder (fp16 mma) --------------------------------
__global__ __launch_bounds__(512, 2)
void dec_h(int M, const __half* __restrict__ zod, const __half* __restrict__ zdt,
           const int* __restrict__ esrc, const int* __restrict__ edst,
           const __half* __restrict__ Wt, const float* __restrict__ b1,
           const float* __restrict__ w2, const float* __restrict__ b2p,
           float* __restrict__ out) {
    constexpr int NC = 64;
    constexpr int BR = 128;
    constexpr int K = 128;
    constexpr int KC = 16;
    constexpr int AST = 24;
    constexpr int NCW = 16;
    constexpr int NT = 2;
    constexpr int NCH = K / KC;   // 8
    __shared__ __half As[2][BR][AST];
    __shared__ __half Ws[2][NC][AST];
    __shared__ float Red[BR][17];

    const int t = threadIdx.x;
    const int lane = t & 31;
    const int wid = t >> 5;
    const int warp_m = wid >> 2;
    const int warp_n = wid & 3;
    const int grp = lane >> 2;
    const int qid = lane & 3;
    const int row0 = blockIdx.x * BR;
    const int lr = t >> 2;
    const int lk = (t & 3) * 4;
    const int grow = row0 + lr;
    const int wn = t >> 3;
    const int wk = (t & 7) * 2;

    int si = 0, di = 0;
    if (grow < M) { si = __ldg(esrc + grow); di = __ldg(edst + grow); }

    uint2 pa;
    unsigned pwv;

    auto loadX = [&](int cc) {
        pa = make_uint2(0u, 0u);
        if (grow < M) {
            int k = cc * KC + lk;
            const __half* base = (k < 64) ? (zod + (size_t)si * 64 + k)
                                          : (zdt + (size_t)di * 64 + (k - 64));
            pa = *(const uint2*)base;
        }
    };
    auto loadW = [&](int cc) {
        pwv = *(const unsigned*)(Wt + (size_t)wn * K + cc * KC + wk);
    };
    auto stage = [&](int buf) {
        *(uint2*)&As[buf][lr][lk] = pa;
        *(unsigned*)&Ws[buf][wn][wk] = pwv;
    };

    float acc[2][NT][4];
#pragma unroll
    for (int mi = 0; mi < 2; mi++)
#pragma unroll
        for (int ni = 0; ni < NT; ni++)
#pragma unroll
            for (int c = 0; c < 4; c++) acc[mi][ni][c] = 0.f;

    loadX(0); loadW(0); stage(0);

#pragma unroll 1
    for (int cc = 0; cc < NCH; ++cc) {
        const int buf = cc & 1;
        __syncthreads();
        if (cc + 1 < NCH) { loadX(cc + 1); loadW(cc + 1); }
        unsigned af[2][4];
#pragma unroll
        for (int mi = 0; mi < 2; mi++) {
            int r = warp_m * 32 + mi * 16 + grp;
            af[mi][0] = *(const unsigned*)&As[buf][r    ][2 * qid];
            af[mi][1] = *(const unsigned*)&As[buf][r + 8][2 * qid];
            af[mi][2] = *(const unsigned*)&As[buf][r    ][2 * qid + 8];
            af[mi][3] = *(const unsigned*)&As[buf][r + 8][2 * qid + 8];
        }
#pragma unroll
        for (int ni = 0; ni < NT; ni++) {
            int c = warp_n * NCW + ni * 8 + grp;
            unsigned b0 = *(const unsigned*)&Ws[buf][c][2 * qid];
            unsigned b1 = *(const unsigned*)&Ws[buf][c][2 * qid + 8];
            MMA_F16(acc[0][ni], af[0], b0, b1);
            MMA_F16(acc[1][ni], af[1], b0, b1);
        }
        if (cc + 1 < NCH) stage(buf ^ 1);
    }

    // epilogue: bias + relu + partial dot with w2 -> smem transpose reduce
    float p[2][2] = {{0.f, 0.f}, {0.f, 0.f}};
#pragma unroll
    for (int ni = 0; ni < NT; ni++) {
        int cb = warp_n * NCW + ni * 8 + 2 * qid;
        float2 bv = *(const float2*)(b1 + cb);
        float2 wv = *(const float2*)(w2 + cb);
#pragma unroll
        for (int mi = 0; mi < 2; mi++) {
            p[mi][0] += fmaxf(acc[mi][ni][0] + bv.x, 0.f) * wv.x
                      + fmaxf(acc[mi][ni][1] + bv.y, 0.f) * wv.y;
            p[mi][1] += fmaxf(acc[mi][ni][2] + bv.x, 0.f) * wv.x
                      + fmaxf(acc[mi][ni][3] + bv.y, 0.f) * wv.y;
        }
    }
    __syncthreads();
#pragma unroll
    for (int mi = 0; mi < 2; mi++) {
        Red[warp_m * 32 + mi * 16 + grp    ][warp_n * 4 + qid] = p[mi][0];
        Red[warp_m * 32 + mi * 16 + grp + 8][warp_n * 4 + qid] = p[mi][1];
    }
    __syncthreads();
    if (t < BR) {
        int r = row0 + t;
        if (r < M) {
            float s = 0.f;
#pragma unroll
            for (int j = 0; j < 16; j++) s += Red[t][j];
            out[r] = 1.f / (1.f + expf(-(s + b2p[0])));
        }
    }
}

// ---------------- host orchestration ------------------------------------------
extern "C" void kernel_launch(void* const* d_in, const int* in_sizes, int n_in,
                              void* d_out, int out_size) {
    const float* x_dt   = (const float*)d_in[0];
    const float* x_od   = (const float*)d_in[1];
    const int*   ei_dt  = (const int*)  d_in[2];
    const int*   rsrc   = (const int*)  d_in[3];
    const int*   rdst   = (const int*)  d_in[4];
    const int*   elsrc  = (const int*)  d_in[5];
    const int*   eldst  = (const int*)  d_in[6];
    const float* od1_wl = (const float*)d_in[7];
    const float* od1_wr = (const float*)d_in[8];
    const float* od1_b  = (const float*)d_in[9];
    const float* od2_wl = (const float*)d_in[10];
    const float* od2_wr = (const float*)d_in[11];
    const float* od2_b  = (const float*)d_in[12];
    const float* od3_wl = (const float*)d_in[13];
    const float* od3_wr = (const float*)d_in[14];
    const float* od3_b  = (const float*)d_in[15];
    const float* od_lw  = (const float*)d_in[16];
    const float* od_lb  = (const float*)d_in[17];
    const float* dt1_wl = (const float*)d_in[18];
    const float* dt1_wr = (const float*)d_in[19];
    const float* dt1_b  = (const float*)d_in[20];
    const float* dt2_wl = (const float*)d_in[21];
    const float* dt2_wr = (const float*)d_in[22];
    const float* dt2_b  = (const float*)d_in[23];
    const float* dt_lw  = (const float*)d_in[24];
    const float* dt_lb  = (const float*)d_in[25];
    const float* dec_w1 = (const float*)d_in[26];
    const float* dec_b1 = (const float*)d_in[27];
    const float* dec_w2 = (const float*)d_in[28];
    const float* dec_b2 = (const float*)d_in[29];
    float* out = (float*)d_out;

    const int E1 = in_sizes[2] / 2;
    const int E2 = in_sizes[3];
    const int EL = in_sizes[5];
    const int* r1 = ei_dt;
    const int* c1 = ei_dt + E1;

    float *acc1, *acc2, *acc3, *h, *d1, *od2b, *od3b, *d2;
    __half *zodh, *zdth, *wh;
    int *deg1, *rp1, *fill1, *es1, *deg2, *rp2, *fill2, *es2;
    cudaGetSymbolAddress((void**)&acc1, g_acc1);
    cudaGetSymbolAddress((void**)&acc2, g_acc2);
    cudaGetSymbolAddress((void**)&acc3, g_acc3);
    cudaGetSymbolAddress((void**)&h,   g_h);
    cudaGetSymbolAddress((void**)&d1,  g_d1);
    cudaGetSymbolAddress((void**)&od2b, g_od2);
    cudaGetSymbolAddress((void**)&od3b, g_od3);
    cudaGetSymbolAddress((void**)&d2,  g_d2);
    cudaGetSymbolAddress((void**)&zodh, g_zodh);
    cudaGetSymbolAddress((void**)&zdth, g_zdth);
    cudaGetSymbolAddress((void**)&wh,  g_wh);
    cudaGetSymbolAddress((void**)&deg1, g_deg1);
    cudaGetSymbolAddress((void**)&rp1, g_rp1);
    cudaGetSymbolAddress((void**)&fill1, g_fill1);
    cudaGetSymbolAddress((void**)&es1, g_es1);
    cudaGetSymbolAddress((void**)&deg2, g_deg2);
    cudaGetSymbolAddress((void**)&rp2, g_rp2);
    cudaGetSymbolAddress((void**)&fill2, g_fill2);
    cudaGetSymbolAddress((void**)&es2, g_es2);

    const int TB = 256;

    // ---- weight transpose/convert (13 weights, one launch) ----
    WTList L;
    const float* ws[13] = {od1_wl, od1_wr, dt1_wl, dt1_wr, od2_wl, od2_wr,
                           od3_wl, od3_wr, od_lw, dt2_wl, dt2_wr, dt_lw, dec_w1};
    int Ks[13] = {128, 128, 128, 128, 128, 64, 128, 128, 128, 128, 128, 128, 128};
    int Ns[13] = {128, 128, 128, 128, 128, 128, 128, 128, 64, 128, 128, 64, 64};
    for (int i = 0; i < 13; i++) { L.src[i] = ws[i]; L.K[i] = Ks[i]; L.N[i] = Ns[i]; }
    k_wt<<<dim3(8, 13), 256>>>(L, wh);
#define WT(i) (wh + (size_t)(i) * WSLOT)

    // ---- CSR build (E1 CSR reused twice) ----
    cudaMemsetAsync(deg1, 0, NDT * sizeof(int));
    cudaMemsetAsync(deg2, 0, NOD * sizeof(int));
    k_degree<<<cdiv(E1, TB), TB>>>(c1, E1, deg1);
    k_degree<<<cdiv(E2, TB), TB>>>(rdst, E2, deg2);
    k_scan2<<<2, 1024>>>(deg1, NDT, rp1, fill1, deg2, NOD, rp2, fill2);
    k_reorder<<<cdiv(E1, TB), TB>>>(r1, c1, E1, rp1, fill1, es1);
    k_reorder<<<cdiv(E2, TB), TB>>>(rsrc, rdst, E2, rp2, fill2, es2);

    // ---- pipeline ----
    k_agg<<<cdiv((long long)NDT * 32, TB), TB>>>(x_dt, es1, rp1, acc1, NDT);
    gemm_h<128, 128><<<dim3(cdiv(NDT, 128), 2), 512>>>(
        NDT, acc1, 128, x_dt, 128, WT(0), WT(1), WT(2), WT(3),
        od1_b, dt1_b, h, d1, nullptr, 1);

    k_agg<<<cdiv((long long)NOD * 32, TB), TB>>>(h, es2, rp2, acc2, NOD);
    gemm_h<128, 64><<<dim3(cdiv(NOD, 64), 1), 512>>>(
        NOD, acc2, 128, x_od, 64, WT(4), WT(5), nullptr, nullptr,
        od2_b, nullptr, od2b, nullptr, nullptr, 1);
    gemm_h<128, 64><<<dim3(cdiv(NOD, 64), 1), 512>>>(
        NOD, acc2, 128, od2b, 128, WT(6), WT(7), nullptr, nullptr,
        od3_b, nullptr, od3b, nullptr, nullptr, 1);
    gemm_h<64, 64><<<dim3(cdiv(NOD, 64), 1), 512>>>(
        NOD, od3b, 128, nullptr, 0, WT(8), nullptr, nullptr, nullptr,
        od_lb, nullptr, nullptr, nullptr, zodh, 0);

    k_agg<<<cdiv((long long)NDT * 32, TB), TB>>>(d1, es1, rp1, acc3, NDT);
    gemm_h<128, 128><<<dim3(cdiv(NDT, 128), 1), 512>>>(
        NDT, acc3, 128, d1, 128, WT(9), WT(10), nullptr, nullptr,
        dt2_b, nullptr, d2, nullptr, nullptr, 1);
    gemm_h<64, 128><<<dim3(cdiv(NDT, 128), 1), 512>>>(
        NDT, d2, 128, nullptr, 0, WT(11), nullptr, nullptr, nullptr,
        dt_lb, nullptr, nullptr, nullptr, zdth, 0);

    dec_h<<<cdiv(EL, 128), 512>>>(EL, zodh, zdth, elsrc, eldst,
                                  WT(12), dec_b1, dec_w2, dec_b2, out);
}

// round 7
// speedup vs baseline: 3.2004x; 1.0800x over previous
#include <cuda_runtime.h>
#include <cuda_fp16.h>
#include <math.h>

#define NDT 30000
#define NOD 10000
#define E1MAX 500000
#define E2MAX 300000
#define WSLOT 16384

static inline int cdiv(long long a, long long b) { return (int)((a + b - 1) / b); }

// ---------------- fp16 mma helper ----------------------------------------------
#define MMA_F16(d, a, b0, b1)                                              \
    asm volatile("mma.sync.aligned.m16n8k16.row.col.f32.f16.f16.f32 "      \
                 "{%0,%1,%2,%3}, {%4,%5,%6,%7}, {%8,%9}, {%0,%1,%2,%3};"   \
                 : "+f"((d)[0]), "+f"((d)[1]), "+f"((d)[2]), "+f"((d)[3])  \
                 : "r"((a)[0]), "r"((a)[1]), "r"((a)[2]), "r"((a)[3]),     \
                   "r"(b0), "r"(b1))

// ---------------- device scratch (all activations fp16) ------------------------
__device__ __half g_xdth[NDT * 128];
__device__ __half g_xodh[NOD * 64];
__device__ __half g_acc1[NDT * 128];
__device__ __half g_acc2[NOD * 128];
__device__ __half g_acc3[NDT * 128];
__device__ __half g_h [NDT * 128];
__device__ __half g_d1[NDT * 128];
__device__ __half g_od2[NOD * 128];
__device__ __half g_od3[NOD * 128];
__device__ __half g_d2[NDT * 128];
__device__ __half g_zodh[NOD * 64];
__device__ __half g_zdth[NDT * 64];
__device__ __half g_wh[13 * WSLOT];
// CSR scratch
__device__ int g_deg1[NDT];
__device__ int g_rp1[NDT + 1];
__device__ int g_fill1[NDT];
__device__ int g_es1[E1MAX];
__device__ int g_deg2[NOD];
__device__ int g_rp2[NOD + 1];
__device__ int g_fill2[NOD];
__device__ int g_es2[E2MAX];

// ---------------- input convert (x_dt, x_od -> half, one launch) ---------------
__global__ void k_cvt(const float* __restrict__ x_dt, __half* __restrict__ xdh,
                      const float* __restrict__ x_od, __half* __restrict__ xoh) {
    const int n1 = NDT * 128 / 4, n2 = NOD * 64 / 4;
    int i = blockIdx.x * blockDim.x + threadIdx.x;
    if (i < n1) {
        float4 v = *(const float4*)(x_dt + i * 4);
        __half2 h0 = __floats2half2_rn(v.x, v.y);
        __half2 h1 = __floats2half2_rn(v.z, v.w);
        *(uint2*)(xdh + i * 4) = make_uint2(*(unsigned*)&h0, *(unsigned*)&h1);
    } else if (i < n1 + n2) {
        int j = i - n1;
        float4 v = *(const float4*)(x_od + j * 4);
        __half2 h0 = __floats2half2_rn(v.x, v.y);
        __half2 h1 = __floats2half2_rn(v.z, v.w);
        *(uint2*)(xoh + j * 4) = make_uint2(*(unsigned*)&h0, *(unsigned*)&h1);
    }
}

// ---------------- weight transpose+convert: W[K][N] f32 -> Wt[N][K] f16 --------
struct WTList {
    const float* src[13];
    int K[13];
    int N[13];
};
__global__ void k_wt(WTList L, __half* __restrict__ dst) {
    int w = blockIdx.y;
    int K = L.K[w], N = L.N[w];
    const float* s = L.src[w];
    __half* d = dst + (size_t)w * WSLOT;
    int total = K * N;
    for (int i = blockIdx.x * blockDim.x + threadIdx.x; i < total;
         i += gridDim.x * blockDim.x) {
        int n = i / K, k = i - n * K;
        d[i] = __float2half(s[k * N + n]);
    }
}

// ---------------- CSR build ----------------------------------------------------
__global__ void k_degree2(const int* __restrict__ c1, int E1, int* __restrict__ deg1,
                          const int* __restrict__ rdst, int E2, int* __restrict__ deg2) {
    int i = blockIdx.x * blockDim.x + threadIdx.x;
    if (i < E1) atomicAdd(deg1 + __ldg(c1 + i), 1);
    else if (i < E1 + E2) atomicAdd(deg2 + __ldg(rdst + (i - E1)), 1);
}

// parallel exclusive scan, 4-way unrolled: block 0 -> graph1, block 1 -> graph2.
__global__ void k_scan2(const int* __restrict__ deg1, int n1, int* __restrict__ rp1,
                        int* __restrict__ fill1,
                        const int* __restrict__ deg2, int n2, int* __restrict__ rp2,
                        int* __restrict__ fill2) {
    const int* deg; int n; int* rp; int* fill;
    if (blockIdx.x == 0) { deg = deg1; n = n1; rp = rp1; fill = fill1; }
    else                 { deg = deg2; n = n2; rp = rp2; fill = fill2; }
    __shared__ int wsum[32];
    int t = threadIdx.x, lane = t & 31, w = t >> 5;
    int chunk = (n + 1023) >> 10;
    int beg = min(t * chunk, n), end = min(beg + chunk, n);
    int s0 = 0, s1 = 0, s2 = 0, s3 = 0;
    int i = beg;
    for (; i + 4 <= end; i += 4) {
        s0 += deg[i]; s1 += deg[i + 1]; s2 += deg[i + 2]; s3 += deg[i + 3];
    }
    for (; i < end; i++) s0 += deg[i];
    int s = s0 + s1 + s2 + s3;
    int own = s;
#pragma unroll
    for (int o = 1; o < 32; o <<= 1) {
        int v = __shfl_up_sync(0xffffffffu, s, o);
        if (lane >= o) s += v;
    }
    if (lane == 31) wsum[w] = s;
    __syncthreads();
    if (w == 0) {
        int v = wsum[lane];
        int sv = v;
#pragma unroll
        for (int o = 1; o < 32; o <<= 1) {
            int u = __shfl_up_sync(0xffffffffu, sv, o);
            if (lane >= o) sv += u;
        }
        wsum[lane] = sv - v;
        if (lane == 31) rp[n] = sv;
    }
    __syncthreads();
    int base = wsum[w] + s - own;
    i = beg;
    for (; i + 4 <= end; i += 4) {
        int d0 = deg[i], d1 = deg[i + 1], d2 = deg[i + 2], d3 = deg[i + 3];
        rp[i] = base; rp[i + 1] = base + d0;
        rp[i + 2] = base + d0 + d1; rp[i + 3] = base + d0 + d1 + d2;
        fill[i] = 0; fill[i + 1] = 0; fill[i + 2] = 0; fill[i + 3] = 0;
        base += d0 + d1 + d2 + d3;
    }
    for (; i < end; i++) { rp[i] = base; fill[i] = 0; base += deg[i]; }
}

__global__ void k_reorder2(const int* __restrict__ s1, const int* __restrict__ t1, int E1,
                           const int* __restrict__ rp1, int* __restrict__ f1,
                           int* __restrict__ e1,
                           const int* __restrict__ s2, const int* __restrict__ t2, int E2,
                           const int* __restrict__ rp2, int* __restrict__ f2,
                           int* __restrict__ e2) {
    int i = blockIdx.x * blockDim.x + threadIdx.x;
    if (i < E1) {
        int d = __ldg(t1 + i);
        int pos = atomicAdd(f1 + d, 1);
        e1[rp1[d] + pos] = __ldg(s1 + i);
    } else if (i < E1 + E2) {
        int j = i - E1;
        int d = __ldg(t2 + j);
        int pos = atomicAdd(f2 + d, 1);
        e2[rp2[d] + pos] = __ldg(s2 + j);
    }
}

// ---------------- mean aggregation (half in, half out): one warp per dst -------
// X rows are 128 halves (256B); lane handles 4 cols via uint2 (8B).
__global__ __launch_bounds__(256)
void k_aggh(const __half* __restrict__ X, const int* __restrict__ es,
            const int* __restrict__ rowptr, __half* __restrict__ acc, int n) {
    int w = (blockIdx.x * blockDim.x + threadIdx.x) >> 5;
    if (w >= n) return;
    int lane = threadIdx.x & 31;
    int beg = __ldg(rowptr + w);
    int end = __ldg(rowptr + w + 1);
    float4 s = make_float4(0.f, 0.f, 0.f, 0.f);
    for (int base = beg; base < end; base += 32) {
        int p = 0;
        if (base + lane < end) p = __ldg(es + base + lane);
        int cnt = min(32, end - base);
        for (int j = 0; j < cnt; j++) {
            int sr = __shfl_sync(0xffffffffu, p, j);
            uint2 v = *(const uint2*)(X + (size_t)sr * 128 + lane * 4);
            float2 f0 = __half22float2(*(__half2*)&v.x);
            float2 f1 = __half22float2(*(__half2*)&v.y);
            s.x += f0.x; s.y += f0.y; s.z += f1.x; s.w += f1.y;
        }
    }
    float inv = 1.f / fmaxf((float)(end - beg), 1.f);
    __half2 h0 = __floats2half2_rn(s.x * inv, s.y * inv);
    __half2 h1 = __floats2half2_rn(s.z * inv, s.w * inv);
    *(uint2*)(acc + (size_t)w * 128 + lane * 4) = make_uint2(*(unsigned*)&h0, *(unsigned*)&h1);
}

// ---------------- fp16 tensor-core GEMM (half in / half out) -------------------
// Y = act( A @ W1 + B @ W2 + bias ); A,B half [M,K]; Wt pre-transposed f16 [N][K].
// Optional second weight set via blockIdx.y. 512 threads, warps 4m x 4n.
template <int NCOLS, int BR>
__global__ __launch_bounds__(512, 2)
void gemm_h(int M,
            const __half* __restrict__ A, int K1,
            const __half* __restrict__ B, int K2,
            const __half* __restrict__ Wt1, const __half* __restrict__ Wt2,
            const __half* __restrict__ Wt1b, const __half* __restrict__ Wt2b,
            const float* __restrict__ bias, const float* __restrict__ biasb,
            __half* __restrict__ Y, __half* __restrict__ Yb, int do_relu) {
    constexpr int KC = 16;
    constexpr int AST = 24;
    constexpr int MI = BR / 64;
    constexpr int NCW = NCOLS / 4;
    constexpr int NT = NCW / 8;
    constexpr int APT = BR * KC / 512;   // halves staged per thread (4 or 2)
    __shared__ __half As[2][BR][AST];
    __shared__ __half Ws[2][NCOLS][AST];

    const __half* w1 = blockIdx.y ? Wt1b : Wt1;
    const __half* w2 = blockIdx.y ? Wt2b : Wt2;
    const float* bs  = blockIdx.y ? biasb : bias;
    __half* y        = blockIdx.y ? Yb : Y;

    const int t = threadIdx.x;
    const int lane = t & 31;
    const int wid = t >> 5;
    const int warp_m = wid >> 2;
    const int warp_n = wid & 3;
    const int grp = lane >> 2;
    const int qid = lane & 3;
    const int row0 = blockIdx.x * BR;
    const int lr = (BR == 128) ? (t >> 2) : (t >> 3);
    const int lk = (BR == 128) ? ((t & 3) * 4) : ((t & 7) * 2);
    const int grow = row0 + lr;
    const int wn = (NCOLS == 128) ? (t >> 2) : (t >> 3);
    const int wk = (NCOLS == 128) ? ((t & 3) * 4) : ((t & 7) * 2);

    const int n1 = K1 / KC;
    const int n2 = (B != nullptr) ? (K2 / KC) : 0;
    const int nch = n1 + n2;

    uint2 pa, pw;

    auto loadX = [&](int cc) {
        const __half* Xp; int stride, k0;
        if (cc < n1) { Xp = A; stride = K1; k0 = cc * KC; }
        else         { Xp = B; stride = K2; k0 = (cc - n1) * KC; }
        pa = make_uint2(0u, 0u);
        if (grow < M) {
            const __half* base = Xp + (size_t)grow * stride + k0 + lk;
            if (APT == 4) pa = *(const uint2*)base;
            else          pa.x = *(const unsigned*)base;
        }
    };
    auto loadW = [&](int cc) {
        const __half* Wp; int stride, k0;
        if (cc < n1) { Wp = w1; stride = K1; k0 = cc * KC; }
        else         { Wp = w2; stride = K2; k0 = (cc - n1) * KC; }
        const __half* base = Wp + (size_t)wn * stride + k0 + wk;
        if (NCOLS == 128) pw = *(const uint2*)base;
        else              pw.x = *(const unsigned*)base;
    };
    auto stage = [&](int buf) {
        if (APT == 4) *(uint2*)&As[buf][lr][lk] = pa;
        else          *(unsigned*)&As[buf][lr][lk] = pa.x;
        if (NCOLS == 128) *(uint2*)&Ws[buf][wn][wk] = pw;
        else              *(unsigned*)&Ws[buf][wn][wk] = pw.x;
    };

    float acc[MI][NT][4];
#pragma unroll
    for (int mi = 0; mi < MI; mi++)
#pragma unroll
        for (int ni = 0; ni < NT; ni++)
#pragma unroll
            for (int c = 0; c < 4; c++) acc[mi][ni][c] = 0.f;

    loadX(0); loadW(0); stage(0);

    for (int cc = 0; cc < nch; ++cc) {
        const int buf = cc & 1;
        __syncthreads();
        if (cc + 1 < nch) { loadX(cc + 1); loadW(cc + 1); }
        unsigned af[MI][4];
#pragma unroll
        for (int mi = 0; mi < MI; mi++) {
            int r = warp_m * (16 * MI) + mi * 16 + grp;
            af[mi][0] = *(const unsigned*)&As[buf][r    ][2 * qid];
            af[mi][1] = *(const unsigned*)&As[buf][r + 8][2 * qid];
            af[mi][2] = *(const unsigned*)&As[buf][r    ][2 * qid + 8];
            af[mi][3] = *(const unsigned*)&As[buf][r + 8][2 * qid + 8];
        }
#pragma unroll
        for (int ni = 0; ni < NT; ni++) {
            int c = warp_n * NCW + ni * 8 + grp;
            unsigned b0 = *(const unsigned*)&Ws[buf][c][2 * qid];
            unsigned b1 = *(const unsigned*)&Ws[buf][c][2 * qid + 8];
#pragma unroll
            for (int mi = 0; mi < MI; mi++) MMA_F16(acc[mi][ni], af[mi], b0, b1);
        }
        if (cc + 1 < nch) stage(buf ^ 1);
    }

    // epilogue: bias + act + half2 stores
#pragma unroll
    for (int ni = 0; ni < NT; ni++) {
        int cb = warp_n * NCW + ni * 8 + 2 * qid;
        float2 bv = make_float2(0.f, 0.f);
        if (bs != nullptr) bv = *(const float2*)(bs + cb);
#pragma unroll
        for (int mi = 0; mi < MI; mi++) {
            int r0 = row0 + warp_m * (16 * MI) + mi * 16 + grp;
            float v0 = acc[mi][ni][0] + bv.x;
            float v1 = acc[mi][ni][1] + bv.y;
            float v2 = acc[mi][ni][2] + bv.x;
            float v3 = acc[mi][ni][3] + bv.y;
            if (do_relu) {
                v0 = fmaxf(v0, 0.f); v1 = fmaxf(v1, 0.f);
                v2 = fmaxf(v2, 0.f); v3 = fmaxf(v3, 0.f);
            }
            __half2 h0 = __floats2half2_rn(v0, v1);
            __half2 h1 = __floats2half2_rn(v2, v3);
            if (r0 < M)     *(__half2*)(y + (size_t)r0 * NCOLS + cb) = h0;
            if (r0 + 8 < M) *(__half2*)(y + (size_t)(r0 + 8) * NCOLS + cb) = h1;
        }
    }
}

// ---------------- fused edge decoder (fp16 mma) --------------------------------
__global__ __launch_bounds__(512, 2)
void dec_h(int M, const __half* __restrict__ zod, const __half* __restrict__ zdt,
           const int* __restrict__ esrc, const int* __restrict__ edst,
           const __half* __restrict__ Wt, const float* __restrict__ b1,
           const float* __restrict__ w2, const float* __restrict__ b2p,
           float* __restrict__ out) {
    constexpr int NC = 64;
    constexpr int BR = 128;
    constexpr int K = 128;
    constexpr int KC = 16;
    constexpr int AST = 24;
    constexpr int NCW = 16;
    constexpr int NT = 2;
    constexpr int NCH = K / KC;
    __shared__ __half As[2][BR][AST];
    __shared__ __half Ws[2][NC][AST];
    __shared__ float Red[BR][17];

    const int t = threadIdx.x;
    const int lane = t & 31;
    const int wid = t >> 5;
    const int warp_m = wid >> 2;
    const int warp_n = wid & 3;
    const int grp = lane >> 2;
    const int qid = lane & 3;
    const int row0 = blockIdx.x * BR;
    const int lr = t >> 2;
    const int lk = (t & 3) * 4;
    const int grow = row0 + lr;
    const int wn = t >> 3;
    const int wk = (t & 7) * 2;

    int si = 0, di = 0;
    if (grow < M) { si = __ldg(esrc + grow); di = __ldg(edst + grow); }

    uint2 pa;
    unsigned pwv;

    auto loadX = [&](int cc) {
        pa = make_uint2(0u, 0u);
        if (grow < M) {
            int k = cc * KC + lk;
            const __half* base = (k < 64) ? (zod + (size_t)si * 64 + k)
                                          : (zdt + (size_t)di * 64 + (k - 64));
            pa = *(const uint2*)base;
        }
    };
    auto loadW = [&](int cc) {
        pwv = *(const unsigned*)(Wt + (size_t)wn * K + cc * KC + wk);
    };
    auto stage = [&](int buf) {
        *(uint2*)&As[buf][lr][lk] = pa;
        *(unsigned*)&Ws[buf][wn][wk] = pwv;
    };

    float acc[2][NT][4];
#pragma unroll
    for (int mi = 0; mi < 2; mi++)
#pragma unroll
        for (int ni = 0; ni < NT; ni++)
#pragma unroll
            for (int c = 0; c < 4; c++) acc[mi][ni][c] = 0.f;

    loadX(0); loadW(0); stage(0);

#pragma unroll 1
    for (int cc = 0; cc < NCH; ++cc) {
        const int buf = cc & 1;
        __syncthreads();
        if (cc + 1 < NCH) { loadX(cc + 1); loadW(cc + 1); }
        unsigned af[2][4];
#pragma unroll
        for (int mi = 0; mi < 2; mi++) {
            int r = warp_m * 32 + mi * 16 + grp;
            af[mi][0] = *(const unsigned*)&As[buf][r    ][2 * qid];
            af[mi][1] = *(const unsigned*)&As[buf][r + 8][2 * qid];
            af[mi][2] = *(const unsigned*)&As[buf][r    ][2 * qid + 8];
            af[mi][3] = *(const unsigned*)&As[buf][r + 8][2 * qid + 8];
        }
#pragma unroll
        for (int ni = 0; ni < NT; ni++) {
            int c = warp_n * NCW + ni * 8 + grp;
            unsigned b0 = *(const unsigned*)&Ws[buf][c][2 * qid];
            unsigned b1 = *(const unsigned*)&Ws[buf][c][2 * qid + 8];
            MMA_F16(acc[0][ni], af[0], b0, b1);
            MMA_F16(acc[1][ni], af[1], b0, b1);
        }
        if (cc + 1 < NCH) stage(buf ^ 1);
    }

    float p[2][2] = {{0.f, 0.f}, {0.f, 0.f}};
#pragma unroll
    for (int ni = 0; ni < NT; ni++) {
        int cb = warp_n * NCW + ni * 8 + 2 * qid;
        float2 bv = *(const float2*)(b1 + cb);
        float2 wv = *(const float2*)(w2 + cb);
#pragma unroll
        for (int mi = 0; mi < 2; mi++) {
            p[mi][0] += fmaxf(acc[mi][ni][0] + bv.x, 0.f) * wv.x
                      + fmaxf(acc[mi][ni][1] + bv.y, 0.f) * wv.y;
            p[mi][1] += fmaxf(acc[mi][ni][2] + bv.x, 0.f) * wv.x
                      + fmaxf(acc[mi][ni][3] + bv.y, 0.f) * wv.y;
        }
    }
    __syncthreads();
#pragma unroll
    for (int mi = 0; mi < 2; mi++) {
        Red[warp_m * 32 + mi * 16 + grp    ][warp_n * 4 + qid] = p[mi][0];
        Red[warp_m * 32 + mi * 16 + grp + 8][warp_n * 4 + qid] = p[mi][1];
    }
    __syncthreads();
    if (t < BR) {
        int r = row0 + t;
        if (r < M) {
            float s = 0.f;
#pragma unroll
            for (int j = 0; j < 16; j++) s += Red[t][j];
            out[r] = 1.f / (1.f + expf(-(s + b2p[0])));
        }
    }
}

// ---------------- host orchestration ------------------------------------------
extern "C" void kernel_launch(void* const* d_in, const int* in_sizes, int n_in,
                              void* d_out, int out_size) {
    const float* x_dt   = (const float*)d_in[0];
    const float* x_od   = (const float*)d_in[1];
    const int*   ei_dt  = (const int*)  d_in[2];
    const int*   rsrc   = (const int*)  d_in[3];
    const int*   rdst   = (const int*)  d_in[4];
    const int*   elsrc  = (const int*)  d_in[5];
    const int*   eldst  = (const int*)  d_in[6];
    const float* od1_wl = (const float*)d_in[7];
    const float* od1_wr = (const float*)d_in[8];
    const float* od1_b  = (const float*)d_in[9];
    const float* od2_wl = (const float*)d_in[10];
    const float* od2_wr = (const float*)d_in[11];
    const float* od2_b  = (const float*)d_in[12];
    const float* od3_wl = (const float*)d_in[13];
    const float* od3_wr = (const float*)d_in[14];
    const float* od3_b  = (const float*)d_in[15];
    const float* od_lw  = (const float*)d_in[16];
    const float* od_lb  = (const float*)d_in[17];
    const float* dt1_wl = (const float*)d_in[18];
    const float* dt1_wr = (const float*)d_in[19];
    const float* dt1_b  = (const float*)d_in[20];
    const float* dt2_wl = (const float*)d_in[21];
    const float* dt2_wr = (const float*)d_in[22];
    const float* dt2_b  = (const float*)d_in[23];
    const float* dt_lw  = (const float*)d_in[24];
    const float* dt_lb  = (const float*)d_in[25];
    const float* dec_w1 = (const float*)d_in[26];
    const float* dec_b1 = (const float*)d_in[27];
    const float* dec_w2 = (const float*)d_in[28];
    const float* dec_b2 = (const float*)d_in[29];
    float* out = (float*)d_out;

    const int E1 = in_sizes[2] / 2;
    const int E2 = in_sizes[3];
    const int EL = in_sizes[5];
    const int* r1 = ei_dt;
    const int* c1 = ei_dt + E1;

    __half *xdth, *xodh, *acc1, *acc2, *acc3, *h, *d1, *od2b, *od3b, *d2;
    __half *zodh, *zdth, *wh;
    int *deg1, *rp1, *fill1, *es1, *deg2, *rp2, *fill2, *es2;
    cudaGetSymbolAddress((void**)&xdth, g_xdth);
    cudaGetSymbolAddress((void**)&xodh, g_xodh);
    cudaGetSymbolAddress((void**)&acc1, g_acc1);
    cudaGetSymbolAddress((void**)&acc2, g_acc2);
    cudaGetSymbolAddress((void**)&acc3, g_acc3);
    cudaGetSymbolAddress((void**)&h,   g_h);
    cudaGetSymbolAddress((void**)&d1,  g_d1);
    cudaGetSymbolAddress((void**)&od2b, g_od2);
    cudaGetSymbolAddress((void**)&od3b, g_od3);
    cudaGetSymbolAddress((void**)&d2,  g_d2);
    cudaGetSymbolAddress((void**)&zodh, g_zodh);
    cudaGetSymbolAddress((void**)&zdth, g_zdth);
    cudaGetSymbolAddress((void**)&wh,  g_wh);
    cudaGetSymbolAddress((void**)&deg1, g_deg1);
    cudaGetSymbolAddress((void**)&rp1, g_rp1);
    cudaGetSymbolAddress((void**)&fill1, g_fill1);
    cudaGetSymbolAddress((void**)&es1, g_es1);
    cudaGetSymbolAddress((void**)&deg2, g_deg2);
    cudaGetSymbolAddress((void**)&rp2, g_rp2);
    cudaGetSymbolAddress((void**)&fill2, g_fill2);
    cudaGetSymbolAddress((void**)&es2, g_es2);

    const int TB = 256;

    // ---- weight transpose/convert + input convert ----
    WTList L;
    const float* ws[13] = {od1_wl, od1_wr, dt1_wl, dt1_wr, od2_wl, od2_wr,
                           od3_wl, od3_wr, od_lw, dt2_wl, dt2_wr, dt_lw, dec_w1};
    int Ks[13] = {128, 128, 128, 128, 128, 64, 128, 128, 128, 128, 128, 128, 128};
    int Ns[13] = {128, 128, 128, 128, 128, 128, 128, 128, 64, 128, 128, 64, 64};
    for (int i = 0; i < 13; i++) { L.src[i] = ws[i]; L.K[i] = Ks[i]; L.N[i] = Ns[i]; }
    k_wt<<<dim3(8, 13), 256>>>(L, wh);
    k_cvt<<<cdiv(NDT * 32 + NOD * 16, TB), TB>>>(x_dt, xdth, x_od, xodh);
#define WT(i) (wh + (size_t)(i) * WSLOT)

    // ---- CSR build (E1 CSR reused twice) ----
    cudaMemsetAsync(deg1, 0, NDT * sizeof(int));
    cudaMemsetAsync(deg2, 0, NOD * sizeof(int));
    k_degree2<<<cdiv(E1 + E2, TB), TB>>>(c1, E1, deg1, rdst, E2, deg2);
    k_scan2<<<2, 1024>>>(deg1, NDT, rp1, fill1, deg2, NOD, rp2, fill2);
    k_reorder2<<<cdiv(E1 + E2, TB), TB>>>(r1, c1, E1, rp1, fill1, es1,
                                          rsrc, rdst, E2, rp2, fill2, es2);

    // ---- pipeline ----
    k_aggh<<<cdiv((long long)NDT * 32, TB), TB>>>(xdth, es1, rp1, acc1, NDT);
    gemm_h<128, 128><<<dim3(cdiv(NDT, 128), 2), 512>>>(
        NDT, acc1, 128, xdth, 128, WT(0), WT(1), WT(2), WT(3),
        od1_b, dt1_b, h, d1, 1);

    k_aggh<<<cdiv((long long)NOD * 32, TB), TB>>>(h, es2, rp2, acc2, NOD);
    gemm_h<128, 64><<<dim3(cdiv(NOD, 64), 1), 512>>>(
        NOD, acc2, 128, xodh, 64, WT(4), WT(5), nullptr, nullptr,
        od2_b, nullptr, od2b, nullptr, 1);
    gemm_h<128, 64><<<dim3(cdiv(NOD, 64), 1), 512>>>(
        NOD, acc2, 128, od2b, 128, WT(6), WT(7), nullptr, nullptr,
        od3_b, nullptr, od3b, nullptr, 1);
    gemm_h<64, 64><<<dim3(cdiv(NOD, 64), 1), 512>>>(
        NOD, od3b, 128, nullptr, 0, WT(8), nullptr, nullptr, nullptr,
        od_lb, nullptr, zodh, nullptr, 0);

    k_aggh<<<cdiv((long long)NDT * 32, TB), TB>>>(d1, es1, rp1, acc3, NDT);
    gemm_h<128, 128><<<dim3(cdiv(NDT, 128), 1), 512>>>(
        NDT, acc3, 128, d1, 128, WT(9), WT(10), nullptr, nullptr,
        dt2_b, nullptr, d2, nullptr, 1);
    gemm_h<64, 128><<<dim3(cdiv(NDT, 128), 1), 512>>>(
        NDT, d2, 128, nullptr, 0, WT(11), nullptr, nullptr, nullptr,
        dt_lb, nullptr, zdth, nullptr, 0);

    dec_h<<<cdiv(EL, 128), 512>>>(EL, zodh, zdth, elsrc, eldst,
                                  WT(12), dec_b1, dec_w2, dec_b2, out);
}

// round 8
// speedup vs baseline: 3.6570x; 1.1427x over previous
#include <cuda_runtime.h>
#include <cuda_fp16.h>
#include <math.h>

#define NDT 30000
#define NOD 10000
#define WSLOT 16384
#define TILE 1024

static inline int cdiv(long long a, long long b) { return (int)((a + b - 1) / b); }

// ---------------- fp16 mma helper ----------------------------------------------
#define MMA_F16(d, a, b0, b1)                                              \
    asm volatile("mma.sync.aligned.m16n8k16.row.col.f32.f16.f16.f32 "      \
                 "{%0,%1,%2,%3}, {%4,%5,%6,%7}, {%8,%9}, {%0,%1,%2,%3};"   \
                 : "+f"((d)[0]), "+f"((d)[1]), "+f"((d)[2]), "+f"((d)[3])  \
                 : "r"((a)[0]), "r"((a)[1]), "r"((a)[2]), "r"((a)[3]),     \
                   "r"(b0), "r"(b1))

// ---------------- device scratch ------------------------------------------------
__device__ __half g_xdth[NDT * 128];
__device__ __half g_xodh[NOD * 64];
__device__ __half g_acc1[NDT * 128];
__device__ __half g_acc2[NOD * 128];
__device__ __half g_acc3[NDT * 128];
__device__ __half g_h [NDT * 128];
__device__ __half g_d1[NDT * 128];
__device__ __half g_od2[NOD * 128];
__device__ __half g_od3[NOD * 128];
__device__ __half g_d2[NDT * 128];
__device__ __half g_zodh[NOD * 64];
__device__ __half g_zdth[NDT * 64];
__device__ __half g_wh[13 * WSLOT];
// CSR scratch
__device__ int g_deg1[NDT];
__device__ int g_rp1[NDT + 1];
__device__ int g_fill1[NDT];
__device__ int g_es1[500000];
__device__ int g_deg2[NOD];
__device__ int g_rp2[NOD + 1];
__device__ int g_fill2[NOD];
__device__ int g_es2[300000];
__device__ int g_part1[64];
__device__ int g_part2[64];

// ---------------- input convert -------------------------------------------------
__global__ void k_cvt(const float* __restrict__ x_dt, __half* __restrict__ xdh,
                      const float* __restrict__ x_od, __half* __restrict__ xoh) {
    const int n1 = NDT * 128 / 4, n2 = NOD * 64 / 4;
    int i = blockIdx.x * blockDim.x + threadIdx.x;
    if (i < n1) {
        float4 v = *(const float4*)(x_dt + i * 4);
        __half2 h0 = __floats2half2_rn(v.x, v.y);
        __half2 h1 = __floats2half2_rn(v.z, v.w);
        *(uint2*)(xdh + i * 4) = make_uint2(*(unsigned*)&h0, *(unsigned*)&h1);
    } else if (i < n1 + n2) {
        int j = i - n1;
        float4 v = *(const float4*)(x_od + j * 4);
        __half2 h0 = __floats2half2_rn(v.x, v.y);
        __half2 h1 = __floats2half2_rn(v.z, v.w);
        *(uint2*)(xoh + j * 4) = make_uint2(*(unsigned*)&h0, *(unsigned*)&h1);
    }
}

// ---------------- weight transpose+convert: W[K][N] f32 -> Wt[N][K] f16 ---------
struct WTList {
    const float* src[13];
    int K[13];
    int N[13];
};
__global__ void k_wt(WTList L, __half* __restrict__ dst) {
    int w = blockIdx.y;
    int K = L.K[w], N = L.N[w];
    const float* s = L.src[w];
    __half* d = dst + (size_t)w * WSLOT;
    int total = K * N;
    for (int i = blockIdx.x * blockDim.x + threadIdx.x; i < total;
         i += gridDim.x * blockDim.x) {
        int n = i / K, k = i - n * K;
        d[i] = __float2half(s[k * N + n]);
    }
}

// ---------------- CSR build ------------------------------------------------------
__global__ void k_degree2(const int* __restrict__ c1, int E1, int* __restrict__ deg1,
                          const int* __restrict__ rdst, int E2, int* __restrict__ deg2) {
    int i = blockIdx.x * blockDim.x + threadIdx.x;
    if (i < E1) atomicAdd(deg1 + __ldg(c1 + i), 1);
    else if (i < E1 + E2) atomicAdd(deg2 + __ldg(rdst + (i - E1)), 1);
}

// pass A: per-1024-tile sums (wide grid). block=256, 4 elems/thread.
__global__ void k_scanA(const int* __restrict__ deg1, int n1, int* __restrict__ part1,
                        int tiles1,
                        const int* __restrict__ deg2, int n2, int* __restrict__ part2) {
    int b = blockIdx.x;
    const int* deg; int n; int* part; int tt;
    if (b < tiles1) { deg = deg1; n = n1; part = part1; tt = b; }
    else            { deg = deg2; n = n2; part = part2; tt = b - tiles1; }
    int t = threadIdx.x, lane = t & 31, w = t >> 5;
    int base = tt * TILE + t * 4;
    int tot = 0;
#pragma unroll
    for (int j = 0; j < 4; j++) tot += (base + j < n) ? deg[base + j] : 0;
    __shared__ int wsum[8];
#pragma unroll
    for (int o = 16; o; o >>= 1) tot += __shfl_xor_sync(0xffffffffu, tot, o);
    if (lane == 0) wsum[w] = tot;
    __syncthreads();
    if (t == 0) {
        int s = 0;
#pragma unroll
        for (int j = 0; j < 8; j++) s += wsum[j];
        part[tt] = s;
    }
}

// pass B: tile exclusive scan + global offset from partials; writes rp, fill, rp[n].
__global__ void k_scanB(const int* __restrict__ deg1, int n1, int* __restrict__ rp1,
                        int* __restrict__ fill1, const int* __restrict__ part1, int tiles1,
                        const int* __restrict__ deg2, int n2, int* __restrict__ rp2,
                        int* __restrict__ fill2, const int* __restrict__ part2, int tiles2) {
    int b = blockIdx.x;
    const int* deg; int n; int* rp; int* fill; const int* part; int tt, tiles;
    if (b < tiles1) { deg = deg1; n = n1; rp = rp1; fill = fill1; part = part1; tt = b; tiles = tiles1; }
    else { deg = deg2; n = n2; rp = rp2; fill = fill2; part = part2; tt = b - tiles1; tiles = tiles2; }
    __shared__ int s_off;
    __shared__ int wsum[8];
    int t = threadIdx.x, lane = t & 31, w = t >> 5;
    if (t < 32) {                      // tiles <= 32 guaranteed (n <= 32768)
        int v = (t < tt) ? part[t] : 0;
#pragma unroll
        for (int o = 16; o; o >>= 1) v += __shfl_xor_sync(0xffffffffu, v, o);
        if (t == 0) s_off = v;
    }
    int base = tt * TILE + t * 4;
    int d[4]; int tot = 0;
#pragma unroll
    for (int j = 0; j < 4; j++) { d[j] = (base + j < n) ? deg[base + j] : 0; tot += d[j]; }
    int inc = tot;
#pragma unroll
    for (int o = 1; o < 32; o <<= 1) {
        int u = __shfl_up_sync(0xffffffffu, inc, o);
        if (lane >= o) inc += u;
    }
    if (lane == 31) wsum[w] = inc;
    __syncthreads();
    int woff = 0;
#pragma unroll
    for (int j = 0; j < 8; j++) if (j < w) woff += wsum[j];
    int run = s_off + woff + inc - tot;
#pragma unroll
    for (int j = 0; j < 4; j++) {
        if (base + j < n) { rp[base + j] = run; fill[base + j] = 0; run += d[j]; }
    }
    if (tt == tiles - 1 && t == blockDim.x - 1) rp[n] = run;
}

__global__ void k_reorder2(const int* __restrict__ s1, const int* __restrict__ t1, int E1,
                           const int* __restrict__ rp1, int* __restrict__ f1,
                           int* __restrict__ e1,
                           const int* __restrict__ s2, const int* __restrict__ t2, int E2,
                           const int* __restrict__ rp2, int* __restrict__ f2,
                           int* __restrict__ e2) {
    int i = blockIdx.x * blockDim.x + threadIdx.x;
    if (i < E1) {
        int d = __ldg(t1 + i);
        int pos = atomicAdd(f1 + d, 1);
        e1[rp1[d] + pos] = __ldg(s1 + i);
    } else if (i < E1 + E2) {
        int j = i - E1;
        int d = __ldg(t2 + j);
        int pos = atomicAdd(f2 + d, 1);
        e2[rp2[d] + pos] = __ldg(s2 + j);
    }
}

// ---------------- mean aggregation, 2 problems in one launch --------------------
__global__ __launch_bounds__(256)
void k_aggh2(const __half* __restrict__ X1, const int* __restrict__ es1,
             const int* __restrict__ rp1, __half* __restrict__ acc1, int n1,
             const __half* __restrict__ X2, const int* __restrict__ es2,
             const int* __restrict__ rp2, __half* __restrict__ acc2, int n2) {
    int w = (blockIdx.x * blockDim.x + threadIdx.x) >> 5;
    const __half* X; const int* es; const int* rowptr; __half* acc;
    if (w < n1) { X = X1; es = es1; rowptr = rp1; acc = acc1; }
    else if (w < n1 + n2) { X = X2; es = es2; rowptr = rp2; acc = acc2; w -= n1; }
    else return;
    int lane = threadIdx.x & 31;
    int beg = __ldg(rowptr + w);
    int end = __ldg(rowptr + w + 1);
    float4 s = make_float4(0.f, 0.f, 0.f, 0.f);
    for (int base = beg; base < end; base += 32) {
        int p = 0;
        if (base + lane < end) p = __ldg(es + base + lane);
        int cnt = min(32, end - base);
        for (int j = 0; j < cnt; j++) {
            int sr = __shfl_sync(0xffffffffu, p, j);
            uint2 v = *(const uint2*)(X + (size_t)sr * 128 + lane * 4);
            float2 f0 = __half22float2(*(__half2*)&v.x);
            float2 f1 = __half22float2(*(__half2*)&v.y);
            s.x += f0.x; s.y += f0.y; s.z += f1.x; s.w += f1.y;
        }
    }
    float inv = 1.f / fmaxf((float)(end - beg), 1.f);
    __half2 h0 = __floats2half2_rn(s.x * inv, s.y * inv);
    __half2 h1 = __floats2half2_rn(s.z * inv, s.w * inv);
    *(uint2*)(acc + (size_t)w * 128 + lane * 4) = make_uint2(*(unsigned*)&h0, *(unsigned*)&h1);
}

// ---------------- generic 2-problem fp16 GEMM -----------------------------------
struct GemmProb {
    const __half* A; int K1;
    const __half* B; int K2;            // optional second input (nullptr = none)
    const __half* W1; const __half* W2; // pre-transposed [N][K] f16
    const float* bias;
    __half* Y;
    int M;
    int relu;
};

template <int NCOLS, int BR>
__global__ __launch_bounds__(512, 2)
void gemm_h(GemmProb p0, GemmProb p1) {
    constexpr int KC = 16;
    constexpr int AST = 24;
    constexpr int MI = BR / 64;
    constexpr int NCW = NCOLS / 4;
    constexpr int NT = NCW / 8;
    constexpr int APT = BR * KC / 512;
    const GemmProb& p = blockIdx.y ? p1 : p0;
    const int row0 = blockIdx.x * BR;
    if (row0 >= p.M) return;

    __shared__ __half As[2][BR][AST];
    __shared__ __half Ws[2][NCOLS][AST];

    const int M = p.M;
    const int K1 = p.K1, K2 = p.K2;
    const __half* A = p.A;
    const __half* B = p.B;

    const int t = threadIdx.x;
    const int lane = t & 31;
    const int wid = t >> 5;
    const int warp_m = wid >> 2;
    const int warp_n = wid & 3;
    const int grp = lane >> 2;
    const int qid = lane & 3;
    const int lr = (BR == 128) ? (t >> 2) : (t >> 3);
    const int lk = (BR == 128) ? ((t & 3) * 4) : ((t & 7) * 2);
    const int grow = row0 + lr;
    const int wn = (NCOLS == 128) ? (t >> 2) : (t >> 3);
    const int wk = (NCOLS == 128) ? ((t & 3) * 4) : ((t & 7) * 2);

    const int n1 = K1 / KC;
    const int n2 = (B != nullptr) ? (K2 / KC) : 0;
    const int nch = n1 + n2;

    uint2 pa, pw;

    auto loadX = [&](int cc) {
        const __half* Xp; int stride, k0;
        if (cc < n1) { Xp = A; stride = K1; k0 = cc * KC; }
        else         { Xp = B; stride = K2; k0 = (cc - n1) * KC; }
        pa = make_uint2(0u, 0u);
        if (grow < M) {
            const __half* base = Xp + (size_t)grow * stride + k0 + lk;
            if (APT == 4) pa = *(const uint2*)base;
            else          pa.x = *(const unsigned*)base;
        }
    };
    auto loadW = [&](int cc) {
        const __half* Wp; int stride, k0;
        if (cc < n1) { Wp = p.W1; stride = K1; k0 = cc * KC; }
        else         { Wp = p.W2; stride = K2; k0 = (cc - n1) * KC; }
        const __half* base = Wp + (size_t)wn * stride + k0 + wk;
        if (NCOLS == 128) pw = *(const uint2*)base;
        else              pw.x = *(const unsigned*)base;
    };
    auto stage = [&](int buf) {
        if (APT == 4) *(uint2*)&As[buf][lr][lk] = pa;
        else          *(unsigned*)&As[buf][lr][lk] = pa.x;
        if (NCOLS == 128) *(uint2*)&Ws[buf][wn][wk] = pw;
        else              *(unsigned*)&Ws[buf][wn][wk] = pw.x;
    };

    float acc[MI][NT][4];
#pragma unroll
    for (int mi = 0; mi < MI; mi++)
#pragma unroll
        for (int ni = 0; ni < NT; ni++)
#pragma unroll
            for (int c = 0; c < 4; c++) acc[mi][ni][c] = 0.f;

    loadX(0); loadW(0); stage(0);

    for (int cc = 0; cc < nch; ++cc) {
        const int buf = cc & 1;
        __syncthreads();
        if (cc + 1 < nch) { loadX(cc + 1); loadW(cc + 1); }
        unsigned af[MI][4];
#pragma unroll
        for (int mi = 0; mi < MI; mi++) {
            int r = warp_m * (16 * MI) + mi * 16 + grp;
            af[mi][0] = *(const unsigned*)&As[buf][r    ][2 * qid];
            af[mi][1] = *(const unsigned*)&As[buf][r + 8][2 * qid];
            af[mi][2] = *(const unsigned*)&As[buf][r    ][2 * qid + 8];
            af[mi][3] = *(const unsigned*)&As[buf][r + 8][2 * qid + 8];
        }
#pragma unroll
        for (int ni = 0; ni < NT; ni++) {
            int c = warp_n * NCW + ni * 8 + grp;
            unsigned b0 = *(const unsigned*)&Ws[buf][c][2 * qid];
            unsigned b1 = *(const unsigned*)&Ws[buf][c][2 * qid + 8];
#pragma unroll
            for (int mi = 0; mi < MI; mi++) MMA_F16(acc[mi][ni], af[mi], b0, b1);
        }
        if (cc + 1 < nch) stage(buf ^ 1);
    }

#pragma unroll
    for (int ni = 0; ni < NT; ni++) {
        int cb = warp_n * NCW + ni * 8 + 2 * qid;
        float2 bv = make_float2(0.f, 0.f);
        if (p.bias != nullptr) bv = *(const float2*)(p.bias + cb);
#pragma unroll
        for (int mi = 0; mi < MI; mi++) {
            int r0 = row0 + warp_m * (16 * MI) + mi * 16 + grp;
            float v0 = acc[mi][ni][0] + bv.x;
            float v1 = acc[mi][ni][1] + bv.y;
            float v2 = acc[mi][ni][2] + bv.x;
            float v3 = acc[mi][ni][3] + bv.y;
            if (p.relu) {
                v0 = fmaxf(v0, 0.f); v1 = fmaxf(v1, 0.f);
                v2 = fmaxf(v2, 0.f); v3 = fmaxf(v3, 0.f);
            }
            __half2 h0 = __floats2half2_rn(v0, v1);
            __half2 h1 = __floats2half2_rn(v2, v3);
            if (r0 < M)     *(__half2*)(p.Y + (size_t)r0 * NCOLS + cb) = h0;
            if (r0 + 8 < M) *(__half2*)(p.Y + (size_t)(r0 + 8) * NCOLS + cb) = h1;
        }
    }
}

// ---------------- fused edge decoder (fp16 mma) ---------------------------------
__global__ __launch_bounds__(512, 2)
void dec_h(int M, const __half* __restrict__ zod, const __half* __restrict__ zdt,
           const int* __restrict__ esrc, const int* __restrict__ edst,
           const __half* __restrict__ Wt, const float* __restrict__ b1,
           const float* __restrict__ w2, const float* __restrict__ b2p,
           float* __restrict__ out) {
    constexpr int NC = 64;
    constexpr int BR = 128;
    constexpr int K = 128;
    constexpr int KC = 16;
    constexpr int AST = 24;
    constexpr int NCW = 16;
    constexpr int NT = 2;
    constexpr int NCH = K / KC;
    __shared__ __half As[2][BR][AST];
    __shared__ __half Ws[2][NC][AST];
    __shared__ float Red[BR][17];

    const int t = threadIdx.x;
    const int lane = t & 31;
    const int wid = t >> 5;
    const int warp_m = wid >> 2;
    const int warp_n = wid & 3;
    const int grp = lane >> 2;
    const int qid = lane & 3;
    const int row0 = blockIdx.x * BR;
    const int lr = t >> 2;
    const int lk = (t & 3) * 4;
    const int grow = row0 + lr;
    const int wn = t >> 3;
    const int wk = (t & 7) * 2;

    int si = 0, di = 0;
    if (grow < M) { si = __ldg(esrc + grow); di = __ldg(edst + grow); }

    uint2 pa;
    unsigned pwv;

    auto loadX = [&](int cc) {
        pa = make_uint2(0u, 0u);
        if (grow < M) {
            int k = cc * KC + lk;
            const __half* base = (k < 64) ? (zod + (size_t)si * 64 + k)
                                          : (zdt + (size_t)di * 64 + (k - 64));
            pa = *(const uint2*)base;
        }
    };
    auto loadW = [&](int cc) {
        pwv = *(const unsigned*)(Wt + (size_t)wn * K + cc * KC + wk);
    };
    auto stage = [&](int buf) {
        *(uint2*)&As[buf][lr][lk] = pa;
        *(unsigned*)&Ws[buf][wn][wk] = pwv;
    };

    float acc[2][NT][4];
#pragma unroll
    for (int mi = 0; mi < 2; mi++)
#pragma unroll
        for (int ni = 0; ni < NT; ni++)
#pragma unroll
            for (int c = 0; c < 4; c++) acc[mi][ni][c] = 0.f;

    loadX(0); loadW(0); stage(0);

#pragma unroll 1
    for (int cc = 0; cc < NCH; ++cc) {
        const int buf = cc & 1;
        __syncthreads();
        if (cc + 1 < NCH) { loadX(cc + 1); loadW(cc + 1); }
        unsigned af[2][4];
#pragma unroll
        for (int mi = 0; mi < 2; mi++) {
            int r = warp_m * 32 + mi * 16 + grp;
            af[mi][0] = *(const unsigned*)&As[buf][r    ][2 * qid];
            af[mi][1] = *(const unsigned*)&As[buf][r + 8][2 * qid];
            af[mi][2] = *(const unsigned*)&As[buf][r    ][2 * qid + 8];
            af[mi][3] = *(const unsigned*)&As[buf][r + 8][2 * qid + 8];
        }
#pragma unroll
        for (int ni = 0; ni < NT; ni++) {
            int c = warp_n * NCW + ni * 8 + grp;
            unsigned b0 = *(const unsigned*)&Ws[buf][c][2 * qid];
            unsigned b1 = *(const unsigned*)&Ws[buf][c][2 * qid + 8];
            MMA_F16(acc[0][ni], af[0], b0, b1);
            MMA_F16(acc[1][ni], af[1], b0, b1);
        }
        if (cc + 1 < NCH) stage(buf ^ 1);
    }

    float p[2][2] = {{0.f, 0.f}, {0.f, 0.f}};
#pragma unroll
    for (int ni = 0; ni < NT; ni++) {
        int cb = warp_n * NCW + ni * 8 + 2 * qid;
        float2 bv = *(const float2*)(b1 + cb);
        float2 wv = *(const float2*)(w2 + cb);
#pragma unroll
        for (int mi = 0; mi < 2; mi++) {
            p[mi][0] += fmaxf(acc[mi][ni][0] + bv.x, 0.f) * wv.x
                      + fmaxf(acc[mi][ni][1] + bv.y, 0.f) * wv.y;
            p[mi][1] += fmaxf(acc[mi][ni][2] + bv.x, 0.f) * wv.x
                      + fmaxf(acc[mi][ni][3] + bv.y, 0.f) * wv.y;
        }
    }
    __syncthreads();
#pragma unroll
    for (int mi = 0; mi < 2; mi++) {
        Red[warp_m * 32 + mi * 16 + grp    ][warp_n * 4 + qid] = p[mi][0];
        Red[warp_m * 32 + mi * 16 + grp + 8][warp_n * 4 + qid] = p[mi][1];
    }
    __syncthreads();
    if (t < BR) {
        int r = row0 + t;
        if (r < M) {
            float s = 0.f;
#pragma unroll
            for (int j = 0; j < 16; j++) s += Red[t][j];
            out[r] = 1.f / (1.f + expf(-(s + b2p[0])));
        }
    }
}

// ---------------- host orchestration --------------------------------------------
extern "C" void kernel_launch(void* const* d_in, const int* in_sizes, int n_in,
                              void* d_out, int out_size) {
    const float* x_dt   = (const float*)d_in[0];
    const float* x_od   = (const float*)d_in[1];
    const int*   ei_dt  = (const int*)  d_in[2];
    const int*   rsrc   = (const int*)  d_in[3];
    const int*   rdst   = (const int*)  d_in[4];
    const int*   elsrc  = (const int*)  d_in[5];
    const int*   eldst  = (const int*)  d_in[6];
    const float* od1_wl = (const float*)d_in[7];
    const float* od1_wr = (const float*)d_in[8];
    const float* od1_b  = (const float*)d_in[9];
    const float* od2_wl = (const float*)d_in[10];
    const float* od2_wr = (const float*)d_in[11];
    const float* od2_b  = (const float*)d_in[12];
    const float* od3_wl = (const float*)d_in[13];
    const float* od3_wr = (const float*)d_in[14];
    const float* od3_b  = (const float*)d_in[15];
    const float* od_lw  = (const float*)d_in[16];
    const float* od_lb  = (const float*)d_in[17];
    const float* dt1_wl = (const float*)d_in[18];
    const float* dt1_wr = (const float*)d_in[19];
    const float* dt1_b  = (const float*)d_in[20];
    const float* dt2_wl = (const float*)d_in[21];
    const float* dt2_wr = (const float*)d_in[22];
    const float* dt2_b  = (const float*)d_in[23];
    const float* dt_lw  = (const float*)d_in[24];
    const float* dt_lb  = (const float*)d_in[25];
    const float* dec_w1 = (const float*)d_in[26];
    const float* dec_b1 = (const float*)d_in[27];
    const float* dec_w2 = (const float*)d_in[28];
    const float* dec_b2 = (const float*)d_in[29];
    float* out = (float*)d_out;

    const int E1 = in_sizes[2] / 2;
    const int E2 = in_sizes[3];
    const int EL = in_sizes[5];
    const int* r1 = ei_dt;
    const int* c1 = ei_dt + E1;

    __half *xdth, *xodh, *acc1, *acc2, *acc3, *h, *d1, *od2b, *od3b, *d2;
    __half *zodh, *zdth, *wh;
    int *deg1, *rp1, *fill1, *es1, *deg2, *rp2, *fill2, *es2, *part1, *part2;
    cudaGetSymbolAddress((void**)&xdth, g_xdth);
    cudaGetSymbolAddress((void**)&xodh, g_xodh);
    cudaGetSymbolAddress((void**)&acc1, g_acc1);
    cudaGetSymbolAddress((void**)&acc2, g_acc2);
    cudaGetSymbolAddress((void**)&acc3, g_acc3);
    cudaGetSymbolAddress((void**)&h,   g_h);
    cudaGetSymbolAddress((void**)&d1,  g_d1);
    cudaGetSymbolAddress((void**)&od2b, g_od2);
    cudaGetSymbolAddress((void**)&od3b, g_od3);
    cudaGetSymbolAddress((void**)&d2,  g_d2);
    cudaGetSymbolAddress((void**)&zodh, g_zodh);
    cudaGetSymbolAddress((void**)&zdth, g_zdth);
    cudaGetSymbolAddress((void**)&wh,  g_wh);
    cudaGetSymbolAddress((void**)&deg1, g_deg1);
    cudaGetSymbolAddress((void**)&rp1, g_rp1);
    cudaGetSymbolAddress((void**)&fill1, g_fill1);
    cudaGetSymbolAddress((void**)&es1, g_es1);
    cudaGetSymbolAddress((void**)&deg2, g_deg2);
    cudaGetSymbolAddress((void**)&rp2, g_rp2);
    cudaGetSymbolAddress((void**)&fill2, g_fill2);
    cudaGetSymbolAddress((void**)&es2, g_es2);
    cudaGetSymbolAddress((void**)&part1, g_part1);
    cudaGetSymbolAddress((void**)&part2, g_part2);

    const int TB = 256;
    const int tiles1 = cdiv(NDT, TILE);   // 30
    const int tiles2 = cdiv(NOD, TILE);   // 10

    // ---- weight transpose/convert + input convert ----
    WTList L;
    const float* ws[13] = {od1_wl, od1_wr, dt1_wl, dt1_wr, od2_wl, od2_wr,
                           od3_wl, od3_wr, od_lw, dt2_wl, dt2_wr, dt_lw, dec_w1};
    int Ks[13] = {128, 128, 128, 128, 128, 64, 128, 128, 128, 128, 128, 128, 128};
    int Ns[13] = {128, 128, 128, 128, 128, 128, 128, 128, 64, 128, 128, 64, 64};
    for (int i = 0; i < 13; i++) { L.src[i] = ws[i]; L.K[i] = Ks[i]; L.N[i] = Ns[i]; }
    k_wt<<<dim3(8, 13), 256>>>(L, wh);
    k_cvt<<<cdiv(NDT * 32 + NOD * 16, TB), TB>>>(x_dt, xdth, x_od, xodh);
#define WT(i) (wh + (size_t)(i) * WSLOT)

    // ---- CSR build (wide two-pass scan) ----
    cudaMemsetAsync(deg1, 0, NDT * sizeof(int));
    cudaMemsetAsync(deg2, 0, NOD * sizeof(int));
    k_degree2<<<cdiv(E1 + E2, TB), TB>>>(c1, E1, deg1, rdst, E2, deg2);
    k_scanA<<<tiles1 + tiles2, TB>>>(deg1, NDT, part1, tiles1, deg2, NOD, part2);
    k_scanB<<<tiles1 + tiles2, TB>>>(deg1, NDT, rp1, fill1, part1, tiles1,
                                     deg2, NOD, rp2, fill2, part2, tiles2);
    k_reorder2<<<cdiv(E1 + E2, TB), TB>>>(r1, c1, E1, rp1, fill1, es1,
                                          rsrc, rdst, E2, rp2, fill2, es2);

    // ---- pipeline ----
    k_aggh2<<<cdiv((long long)NDT * 32, TB), TB>>>(
        xdth, es1, rp1, acc1, NDT, nullptr, nullptr, nullptr, nullptr, 0);

    GemmProb ph  = {acc1, 128, xdth, 128, WT(0), WT(1), od1_b, h,  NDT, 1};
    GemmProb pd1 = {acc1, 128, xdth, 128, WT(2), WT(3), dt1_b, d1, NDT, 1};
    gemm_h<128, 128><<<dim3(cdiv(NDT, 128), 2), 512>>>(ph, pd1);

    // agg2 (NOD <- h over rev) + agg3 (NDT <- d1 over dt) in one launch
    k_aggh2<<<cdiv((long long)(NOD + NDT) * 32, TB), TB>>>(
        h, es2, rp2, acc2, NOD, d1, es1, rp1, acc3, NDT);

    // od2 (M=NOD) + dt2 (M=NDT) merged, NCOLS=128
    GemmProb pod2 = {acc2, 128, xodh, 64, WT(4), WT(5), od2_b, od2b, NOD, 1};
    GemmProb pdt2 = {acc3, 128, d1, 128, WT(9), WT(10), dt2_b, d2, NDT, 1};
    gemm_h<128, 128><<<dim3(cdiv(NDT, 128), 2), 512>>>(pod2, pdt2);

    // od3 alone (M=NOD), BR=64
    GemmProb pod3 = {acc2, 128, od2b, 128, WT(6), WT(7), od3_b, od3b, NOD, 1};
    gemm_h<128, 64><<<dim3(cdiv(NOD, 64), 1), 512>>>(pod3, pod3);

    // zod (M=NOD) + zdt (M=NDT) merged, NCOLS=64, BR=64
    GemmProb pzod = {od3b, 128, nullptr, 0, WT(8), nullptr, od_lb, zodh, NOD, 0};
    GemmProb pzdt = {d2, 128, nullptr, 0, WT(11), nullptr, dt_lb, zdth, NDT, 0};
    gemm_h<64, 64><<<dim3(cdiv(NDT, 64), 2), 512>>>(pzod, pzdt);

    dec_h<<<cdiv(EL, 128), 512>>>(EL, zodh, zdth, elsrc, eldst,
                                  WT(12), dec_b1, dec_w2, dec_b2, out);
}

// round 9
// speedup vs baseline: 3.7716x; 1.0313x over previous
#include <cuda_runtime.h>
#include <cuda_fp16.h>
#include <math.h>

#define NDT 30000
#define NOD 10000
#define WSLOT 16384
#define TILE 1024

static inline int cdiv(long long a, long long b) { return (int)((a + b - 1) / b); }

// ---------------- fp16 mma / ldmatrix helpers -----------------------------------
#define MMA_F16(d, a, b0, b1)                                              \
    asm volatile("mma.sync.aligned.m16n8k16.row.col.f32.f16.f16.f32 "      \
                 "{%0,%1,%2,%3}, {%4,%5,%6,%7}, {%8,%9}, {%0,%1,%2,%3};"   \
                 : "+f"((d)[0]), "+f"((d)[1]), "+f"((d)[2]), "+f"((d)[3])  \
                 : "r"((a)[0]), "r"((a)[1]), "r"((a)[2]), "r"((a)[3]),     \
                   "r"(b0), "r"(b1))

#define LDSM_X4(r0, r1, r2, r3, addr)                                      \
    asm volatile("ldmatrix.sync.aligned.m8n8.x4.shared.b16 "               \
                 "{%0,%1,%2,%3}, [%4];"                                    \
                 : "=r"(r0), "=r"(r1), "=r"(r2), "=r"(r3) : "r"(addr))

__device__ __forceinline__ unsigned smem_u32(const void* p) {
    return (unsigned)__cvta_generic_to_shared(p);
}

// ---------------- device scratch ------------------------------------------------
__device__ __half g_xdth[NDT * 128];
__device__ __half g_xodh[NOD * 64];
__device__ __half g_acc1[NDT * 128];
__device__ __half g_acc2[NOD * 128];
__device__ __half g_acc3[NDT * 128];
__device__ __half g_h [NDT * 128];
__device__ __half g_d1[NDT * 128];
__device__ __half g_od2[NOD * 128];
__device__ __half g_od3[NOD * 128];
__device__ __half g_d2[NDT * 128];
__device__ __half g_zodh[NOD * 64];
__device__ __half g_zdth[NDT * 64];
__device__ __half g_wh[13 * WSLOT];
// CSR scratch
__device__ int g_deg1[NDT];
__device__ int g_rp1[NDT + 1];
__device__ int g_fill1[NDT];
__device__ int g_es1[500000];
__device__ int g_deg2[NOD];
__device__ int g_rp2[NOD + 1];
__device__ int g_fill2[NOD];
__device__ int g_es2[300000];
__device__ int g_part1[64];
__device__ int g_part2[64];

// ---------------- input convert -------------------------------------------------
__global__ void k_cvt(const float* __restrict__ x_dt, __half* __restrict__ xdh,
                      const float* __restrict__ x_od, __half* __restrict__ xoh) {
    const int n1 = NDT * 128 / 4, n2 = NOD * 64 / 4;
    int i = blockIdx.x * blockDim.x + threadIdx.x;
    if (i < n1) {
        float4 v = *(const float4*)(x_dt + i * 4);
        __half2 h0 = __floats2half2_rn(v.x, v.y);
        __half2 h1 = __floats2half2_rn(v.z, v.w);
        *(uint2*)(xdh + i * 4) = make_uint2(*(unsigned*)&h0, *(unsigned*)&h1);
    } else if (i < n1 + n2) {
        int j = i - n1;
        float4 v = *(const float4*)(x_od + j * 4);
        __half2 h0 = __floats2half2_rn(v.x, v.y);
        __half2 h1 = __floats2half2_rn(v.z, v.w);
        *(uint2*)(xoh + j * 4) = make_uint2(*(unsigned*)&h0, *(unsigned*)&h1);
    }
}

// ---------------- weight transpose+convert: W[K][N] f32 -> Wt[N][K] f16 ---------
struct WTList {
    const float* src[13];
    int K[13];
    int N[13];
};
__global__ void k_wt(WTList L, __half* __restrict__ dst) {
    int w = blockIdx.y;
    int K = L.K[w], N = L.N[w];
    const float* s = L.src[w];
    __half* d = dst + (size_t)w * WSLOT;
    int total = K * N;
    for (int i = blockIdx.x * blockDim.x + threadIdx.x; i < total;
         i += gridDim.x * blockDim.x) {
        int n = i / K, k = i - n * K;
        d[i] = __float2half(s[k * N + n]);
    }
}

// ---------------- CSR build ------------------------------------------------------
__global__ void k_degree2(const int* __restrict__ c1, int E1, int* __restrict__ deg1,
                          const int* __restrict__ rdst, int E2, int* __restrict__ deg2) {
    int i = blockIdx.x * blockDim.x + threadIdx.x;
    if (i < E1) atomicAdd(deg1 + __ldg(c1 + i), 1);
    else if (i < E1 + E2) atomicAdd(deg2 + __ldg(rdst + (i - E1)), 1);
}

__global__ void k_scanA(const int* __restrict__ deg1, int n1, int* __restrict__ part1,
                        int tiles1,
                        const int* __restrict__ deg2, int n2, int* __restrict__ part2) {
    int b = blockIdx.x;
    const int* deg; int n; int* part; int tt;
    if (b < tiles1) { deg = deg1; n = n1; part = part1; tt = b; }
    else            { deg = deg2; n = n2; part = part2; tt = b - tiles1; }
    int t = threadIdx.x, lane = t & 31, w = t >> 5;
    int base = tt * TILE + t * 4;
    int tot = 0;
#pragma unroll
    for (int j = 0; j < 4; j++) tot += (base + j < n) ? deg[base + j] : 0;
    __shared__ int wsum[8];
#pragma unroll
    for (int o = 16; o; o >>= 1) tot += __shfl_xor_sync(0xffffffffu, tot, o);
    if (lane == 0) wsum[w] = tot;
    __syncthreads();
    if (t == 0) {
        int s = 0;
#pragma unroll
        for (int j = 0; j < 8; j++) s += wsum[j];
        part[tt] = s;
    }
}

__global__ void k_scanB(const int* __restrict__ deg1, int n1, int* __restrict__ rp1,
                        int* __restrict__ fill1, const int* __restrict__ part1, int tiles1,
                        const int* __restrict__ deg2, int n2, int* __restrict__ rp2,
                        int* __restrict__ fill2, const int* __restrict__ part2, int tiles2) {
    int b = blockIdx.x;
    const int* deg; int n; int* rp; int* fill; const int* part; int tt, tiles;
    if (b < tiles1) { deg = deg1; n = n1; rp = rp1; fill = fill1; part = part1; tt = b; tiles = tiles1; }
    else { deg = deg2; n = n2; rp = rp2; fill = fill2; part = part2; tt = b - tiles1; tiles = tiles2; }
    __shared__ int s_off;
    __shared__ int wsum[8];
    int t = threadIdx.x, lane = t & 31, w = t >> 5;
    if (t < 32) {
        int v = (t < tt) ? part[t] : 0;
#pragma unroll
        for (int o = 16; o; o >>= 1) v += __shfl_xor_sync(0xffffffffu, v, o);
        if (t == 0) s_off = v;
    }
    int base = tt * TILE + t * 4;
    int d[4]; int tot = 0;
#pragma unroll
    for (int j = 0; j < 4; j++) { d[j] = (base + j < n) ? deg[base + j] : 0; tot += d[j]; }
    int inc = tot;
#pragma unroll
    for (int o = 1; o < 32; o <<= 1) {
        int u = __shfl_up_sync(0xffffffffu, inc, o);
        if (lane >= o) inc += u;
    }
    if (lane == 31) wsum[w] = inc;
    __syncthreads();
    int woff = 0;
#pragma unroll
    for (int j = 0; j < 8; j++) if (j < w) woff += wsum[j];
    int run = s_off + woff + inc - tot;
#pragma unroll
    for (int j = 0; j < 4; j++) {
        if (base + j < n) { rp[base + j] = run; fill[base + j] = 0; run += d[j]; }
    }
    if (tt == tiles - 1 && t == blockDim.x - 1) rp[n] = run;
}

__global__ void k_reorder2(const int* __restrict__ s1, const int* __restrict__ t1, int E1,
                           const int* __restrict__ rp1, int* __restrict__ f1,
                           int* __restrict__ e1,
                           const int* __restrict__ s2, const int* __restrict__ t2, int E2,
                           const int* __restrict__ rp2, int* __restrict__ f2,
                           int* __restrict__ e2) {
    int i = blockIdx.x * blockDim.x + threadIdx.x;
    if (i < E1) {
        int d = __ldg(t1 + i);
        int pos = atomicAdd(f1 + d, 1);
        e1[rp1[d] + pos] = __ldg(s1 + i);
    } else if (i < E1 + E2) {
        int j = i - E1;
        int d = __ldg(t2 + j);
        int pos = atomicAdd(f2 + d, 1);
        e2[rp2[d] + pos] = __ldg(s2 + j);
    }
}

// ---------------- mean aggregation, 2 problems in one launch --------------------
__global__ __launch_bounds__(256)
void k_aggh2(const __half* __restrict__ X1, const int* __restrict__ es1,
             const int* __restrict__ rp1, __half* __restrict__ acc1, int n1,
             const __half* __restrict__ X2, const int* __restrict__ es2,
             const int* __restrict__ rp2, __half* __restrict__ acc2, int n2) {
    int w = (blockIdx.x * blockDim.x + threadIdx.x) >> 5;
    const __half* X; const int* es; const int* rowptr; __half* acc;
    if (w < n1) { X = X1; es = es1; rowptr = rp1; acc = acc1; }
    else if (w < n1 + n2) { X = X2; es = es2; rowptr = rp2; acc = acc2; w -= n1; }
    else return;
    int lane = threadIdx.x & 31;
    int beg = __ldg(rowptr + w);
    int end = __ldg(rowptr + w + 1);
    float4 s = make_float4(0.f, 0.f, 0.f, 0.f);
    for (int base = beg; base < end; base += 32) {
        int p = 0;
        if (base + lane < end) p = __ldg(es + base + lane);
        int cnt = min(32, end - base);
        for (int j = 0; j < cnt; j++) {
            int sr = __shfl_sync(0xffffffffu, p, j);
            uint2 v = *(const uint2*)(X + (size_t)sr * 128 + lane * 4);
            float2 f0 = __half22float2(*(__half2*)&v.x);
            float2 f1 = __half22float2(*(__half2*)&v.y);
            s.x += f0.x; s.y += f0.y; s.z += f1.x; s.w += f1.y;
        }
    }
    float inv = 1.f / fmaxf((float)(end - beg), 1.f);
    __half2 h0 = __floats2half2_rn(s.x * inv, s.y * inv);
    __half2 h1 = __floats2half2_rn(s.z * inv, s.w * inv);
    *(uint2*)(acc + (size_t)w * 128 + lane * 4) = make_uint2(*(unsigned*)&h0, *(unsigned*)&h1);
}

// ---------------- generic 2-problem fp16 GEMM (ldmatrix fragments) --------------
struct GemmProb {
    const __half* A; int K1;
    const __half* B; int K2;
    const __half* W1; const __half* W2;   // pre-transposed [N][K] f16
    const float* bias;
    __half* Y;
    int M;
    int relu;
};

template <int NCOLS, int BR>
__global__ __launch_bounds__(512, 2)
void gemm_h(GemmProb p0, GemmProb p1) {
    constexpr int KC = 16;
    constexpr int AST = 24;
    constexpr int MI = BR / 64;
    constexpr int NCW = NCOLS / 4;
    constexpr int NT = NCW / 8;
    constexpr int NG = NT / 2;           // ldmatrix.x4 groups per warp (2 or 1)
    constexpr int APT = BR * KC / 512;
    const GemmProb& p = blockIdx.y ? p1 : p0;
    const int row0 = blockIdx.x * BR;
    if (row0 >= p.M) return;

    __shared__ __half As[2][BR][AST];
    __shared__ __half Ws[2][NCOLS][AST];

    const int M = p.M;
    const int K1 = p.K1, K2 = p.K2;
    const __half* A = p.A;
    const __half* B = p.B;

    const int t = threadIdx.x;
    const int lane = t & 31;
    const int wid = t >> 5;
    const int warp_m = wid >> 2;
    const int warp_n = wid & 3;
    const int grp = lane >> 2;
    const int qid = lane & 3;
    const int lr = (BR == 128) ? (t >> 2) : (t >> 3);
    const int lk = (BR == 128) ? ((t & 3) * 4) : ((t & 7) * 2);
    const int grow = row0 + lr;
    const int wn = (NCOLS == 128) ? (t >> 2) : (t >> 3);
    const int wk = (NCOLS == 128) ? ((t & 3) * 4) : ((t & 7) * 2);
    // ldmatrix per-lane tile coords
    const int lm_r = (lane & 7) + ((lane >> 3) & 1) * 8;  // row within 16-row frag
    const int lm_c = ((lane >> 4) & 1) * 8;               // k-half (0 or 8)

    const int n1 = K1 / KC;
    const int n2 = (B != nullptr) ? (K2 / KC) : 0;
    const int nch = n1 + n2;

    uint2 pa, pw;

    auto loadX = [&](int cc) {
        const __half* Xp; int stride, k0;
        if (cc < n1) { Xp = A; stride = K1; k0 = cc * KC; }
        else         { Xp = B; stride = K2; k0 = (cc - n1) * KC; }
        pa = make_uint2(0u, 0u);
        if (grow < M) {
            const __half* base = Xp + (size_t)grow * stride + k0 + lk;
            if (APT == 4) pa = *(const uint2*)base;
            else          pa.x = *(const unsigned*)base;
        }
    };
    auto loadW = [&](int cc) {
        const __half* Wp; int stride, k0;
        if (cc < n1) { Wp = p.W1; stride = K1; k0 = cc * KC; }
        else         { Wp = p.W2; stride = K2; k0 = (cc - n1) * KC; }
        const __half* base = Wp + (size_t)wn * stride + k0 + wk;
        if (NCOLS == 128) pw = *(const uint2*)base;
        else              pw.x = *(const unsigned*)base;
    };
    auto stage = [&](int buf) {
        if (APT == 4) *(uint2*)&As[buf][lr][lk] = pa;
        else          *(unsigned*)&As[buf][lr][lk] = pa.x;
        if (NCOLS == 128) *(uint2*)&Ws[buf][wn][wk] = pw;
        else              *(unsigned*)&Ws[buf][wn][wk] = pw.x;
    };

    float acc[MI][NT][4];
#pragma unroll
    for (int mi = 0; mi < MI; mi++)
#pragma unroll
        for (int ni = 0; ni < NT; ni++)
#pragma unroll
            for (int c = 0; c < 4; c++) acc[mi][ni][c] = 0.f;

    loadX(0); loadW(0); stage(0);

    for (int cc = 0; cc < nch; ++cc) {
        const int buf = cc & 1;
        __syncthreads();
        if (cc + 1 < nch) { loadX(cc + 1); loadW(cc + 1); }
        unsigned af[MI][4];
#pragma unroll
        for (int mi = 0; mi < MI; mi++) {
            int r = warp_m * (16 * MI) + mi * 16;
            LDSM_X4(af[mi][0], af[mi][1], af[mi][2], af[mi][3],
                    smem_u32(&As[buf][r + lm_r][lm_c]));
        }
        unsigned bf[NG][4];
#pragma unroll
        for (int g = 0; g < NG; g++) {
            int c = warp_n * NCW + g * 16;
            LDSM_X4(bf[g][0], bf[g][1], bf[g][2], bf[g][3],
                    smem_u32(&Ws[buf][c + lm_r][lm_c]));
        }
#pragma unroll
        for (int g = 0; g < NG; g++) {
#pragma unroll
            for (int half = 0; half < 2; half++) {
                unsigned b0 = bf[g][half];       // (n8 tile, k0-7)
                unsigned b1 = bf[g][half + 2];   // (n8 tile, k8-15)
#pragma unroll
                for (int mi = 0; mi < MI; mi++)
                    MMA_F16(acc[mi][g * 2 + half], af[mi], b0, b1);
            }
        }
        if (cc + 1 < nch) stage(buf ^ 1);
    }

#pragma unroll
    for (int ni = 0; ni < NT; ni++) {
        int cb = warp_n * NCW + ni * 8 + 2 * qid;
        float2 bv = make_float2(0.f, 0.f);
        if (p.bias != nullptr) bv = *(const float2*)(p.bias + cb);
#pragma unroll
        for (int mi = 0; mi < MI; mi++) {
            int r0 = row0 + warp_m * (16 * MI) + mi * 16 + grp;
            float v0 = acc[mi][ni][0] + bv.x;
            float v1 = acc[mi][ni][1] + bv.y;
            float v2 = acc[mi][ni][2] + bv.x;
            float v3 = acc[mi][ni][3] + bv.y;
            if (p.relu) {
                v0 = fmaxf(v0, 0.f); v1 = fmaxf(v1, 0.f);
                v2 = fmaxf(v2, 0.f); v3 = fmaxf(v3, 0.f);
            }
            __half2 h0 = __floats2half2_rn(v0, v1);
            __half2 h1 = __floats2half2_rn(v2, v3);
            if (r0 < M)     *(__half2*)(p.Y + (size_t)r0 * NCOLS + cb) = h0;
            if (r0 + 8 < M) *(__half2*)(p.Y + (size_t)(r0 + 8) * NCOLS + cb) = h1;
        }
    }
}

// ---------------- fused edge decoder (fp16 mma + ldmatrix) ----------------------
__global__ __launch_bounds__(512, 2)
void dec_h(int M, const __half* __restrict__ zod, const __half* __restrict__ zdt,
           const int* __restrict__ esrc, const int* __restrict__ edst,
           const __half* __restrict__ Wt, const float* __restrict__ b1,
           const float* __restrict__ w2, const float* __restrict__ b2p,
           float* __restrict__ out) {
    constexpr int NC = 64;
    constexpr int BR = 128;
    constexpr int K = 128;
    constexpr int KC = 16;
    constexpr int AST = 24;
    constexpr int NCW = 16;
    constexpr int NT = 2;
    constexpr int NCH = K / KC;
    __shared__ __half As[2][BR][AST];
    __shared__ __half Ws[2][NC][AST];
    __shared__ float Red[BR][17];

    const int t = threadIdx.x;
    const int lane = t & 31;
    const int wid = t >> 5;
    const int warp_m = wid >> 2;
    const int warp_n = wid & 3;
    const int grp = lane >> 2;
    const int qid = lane & 3;
    const int row0 = blockIdx.x * BR;
    const int lr = t >> 2;
    const int lk = (t & 3) * 4;
    const int grow = row0 + lr;
    const int wn = t >> 3;
    const int wk = (t & 7) * 2;
    const int lm_r = (lane & 7) + ((lane >> 3) & 1) * 8;
    const int lm_c = ((lane >> 4) & 1) * 8;

    int si = 0, di = 0;
    if (grow < M) { si = __ldg(esrc + grow); di = __ldg(edst + grow); }

    uint2 pa;
    unsigned pwv;

    auto loadX = [&](int cc) {
        pa = make_uint2(0u, 0u);
        if (grow < M) {
            int k = cc * KC + lk;
            const __half* base = (k < 64) ? (zod + (size_t)si * 64 + k)
                                          : (zdt + (size_t)di * 64 + (k - 64));
            pa = *(const uint2*)base;
        }
    };
    auto loadW = [&](int cc) {
        pwv = *(const unsigned*)(Wt + (size_t)wn * K + cc * KC + wk);
    };
    auto stage = [&](int buf) {
        *(uint2*)&As[buf][lr][lk] = pa;
        *(unsigned*)&Ws[buf][wn][wk] = pwv;
    };

    float acc[2][NT][4];
#pragma unroll
    for (int mi = 0; mi < 2; mi++)
#pragma unroll
        for (int ni = 0; ni < NT; ni++)
#pragma unroll
            for (int c = 0; c < 4; c++) acc[mi][ni][c] = 0.f;

    loadX(0); loadW(0); stage(0);

#pragma unroll 1
    for (int cc = 0; cc < NCH; ++cc) {
        const int buf = cc & 1;
        __syncthreads();
        if (cc + 1 < NCH) { loadX(cc + 1); loadW(cc + 1); }
        unsigned af[2][4];
#pragma unroll
        for (int mi = 0; mi < 2; mi++) {
            int r = warp_m * 32 + mi * 16;
            LDSM_X4(af[mi][0], af[mi][1], af[mi][2], af[mi][3],
                    smem_u32(&As[buf][r + lm_r][lm_c]));
        }
        unsigned bf[4];
        {
            int c = warp_n * NCW;
            LDSM_X4(bf[0], bf[1], bf[2], bf[3],
                    smem_u32(&Ws[buf][c + lm_r][lm_c]));
        }
#pragma unroll
        for (int half = 0; half < 2; half++) {
            unsigned b0 = bf[half];
            unsigned b1 = bf[half + 2];
            MMA_F16(acc[0][half], af[0], b0, b1);
            MMA_F16(acc[1][half], af[1], b0, b1);
        }
        if (cc + 1 < NCH) stage(buf ^ 1);
    }

    float p[2][2] = {{0.f, 0.f}, {0.f, 0.f}};
#pragma unroll
    for (int ni = 0; ni < NT; ni++) {
        int cb = warp_n * NCW + ni * 8 + 2 * qid;
        float2 bv = *(const float2*)(b1 + cb);
        float2 wv = *(const float2*)(w2 + cb);
#pragma unroll
        for (int mi = 0; mi < 2; mi++) {
            p[mi][0] += fmaxf(acc[mi][ni][0] + bv.x, 0.f) * wv.x
                      + fmaxf(acc[mi][ni][1] + bv.y, 0.f) * wv.y;
            p[mi][1] += fmaxf(acc[mi][ni][2] + bv.x, 0.f) * wv.x
                      + fmaxf(acc[mi][ni][3] + bv.y, 0.f) * wv.y;
        }
    }
    __syncthreads();
#pragma unroll
    for (int mi = 0; mi < 2; mi++) {
        Red[warp_m * 32 + mi * 16 + grp    ][warp_n * 4 + qid] = p[mi][0];
        Red[warp_m * 32 + mi * 16 + grp + 8][warp_n * 4 + qid] = p[mi][1];
    }
    __syncthreads();
    if (t < BR) {
        int r = row0 + t;
        if (r < M) {
            float s = 0.f;
#pragma unroll
            for (int j = 0; j < 16; j++) s += Red[t][j];
            out[r] = 1.f / (1.f + expf(-(s + b2p[0])));
        }
    }
}

// ---------------- host orchestration --------------------------------------------
extern "C" void kernel_launch(void* const* d_in, const int* in_sizes, int n_in,
                              void* d_out, int out_size) {
    const float* x_dt   = (const float*)d_in[0];
    const float* x_od   = (const float*)d_in[1];
    const int*   ei_dt  = (const int*)  d_in[2];
    const int*   rsrc   = (const int*)  d_in[3];
    const int*   rdst   = (const int*)  d_in[4];
    const int*   elsrc  = (const int*)  d_in[5];
    const int*   eldst  = (const int*)  d_in[6];
    const float* od1_wl = (const float*)d_in[7];
    const float* od1_wr = (const float*)d_in[8];
    const float* od1_b  = (const float*)d_in[9];
    const float* od2_wl = (const float*)d_in[10];
    const float* od2_wr = (const float*)d_in[11];
    const float* od2_b  = (const float*)d_in[12];
    const float* od3_wl = (const float*)d_in[13];
    const float* od3_wr = (const float*)d_in[14];
    const float* od3_b  = (const float*)d_in[15];
    const float* od_lw  = (const float*)d_in[16];
    const float* od_lb  = (const float*)d_in[17];
    const float* dt1_wl = (const float*)d_in[18];
    const float* dt1_wr = (const float*)d_in[19];
    const float* dt1_b  = (const float*)d_in[20];
    const float* dt2_wl = (const float*)d_in[21];
    const float* dt2_wr = (const float*)d_in[22];
    const float* dt2_b  = (const float*)d_in[23];
    const float* dt_lw  = (const float*)d_in[24];
    const float* dt_lb  = (const float*)d_in[25];
    const float* dec_w1 = (const float*)d_in[26];
    const float* dec_b1 = (const float*)d_in[27];
    const float* dec_w2 = (const float*)d_in[28];
    const float* dec_b2 = (const float*)d_in[29];
    float* out = (float*)d_out;

    const int E1 = in_sizes[2] / 2;
    const int E2 = in_sizes[3];
    const int EL = in_sizes[5];
    const int* r1 = ei_dt;
    const int* c1 = ei_dt + E1;

    __half *xdth, *xodh, *acc1, *acc2, *acc3, *h, *d1, *od2b, *od3b, *d2;
    __half *zodh, *zdth, *wh;
    int *deg1, *rp1, *fill1, *es1, *deg2, *rp2, *fill2, *es2, *part1, *part2;
    cudaGetSymbolAddress((void**)&xdth, g_xdth);
    cudaGetSymbolAddress((void**)&xodh, g_xodh);
    cudaGetSymbolAddress((void**)&acc1, g_acc1);
    cudaGetSymbolAddress((void**)&acc2, g_acc2);
    cudaGetSymbolAddress((void**)&acc3, g_acc3);
    cudaGetSymbolAddress((void**)&h,   g_h);
    cudaGetSymbolAddress((void**)&d1,  g_d1);
    cudaGetSymbolAddress((void**)&od2b, g_od2);
    cudaGetSymbolAddress((void**)&od3b, g_od3);
    cudaGetSymbolAddress((void**)&d2,  g_d2);
    cudaGetSymbolAddress((void**)&zodh, g_zodh);
    cudaGetSymbolAddress((void**)&zdth, g_zdth);
    cudaGetSymbolAddress((void**)&wh,  g_wh);
    cudaGetSymbolAddress((void**)&deg1, g_deg1);
    cudaGetSymbolAddress((void**)&rp1, g_rp1);
    cudaGetSymbolAddress((void**)&fill1, g_fill1);
    cudaGetSymbolAddress((void**)&es1, g_es1);
    cudaGetSymbolAddress((void**)&deg2, g_deg2);
    cudaGetSymbolAddress((void**)&rp2, g_rp2);
    cudaGetSymbolAddress((void**)&fill2, g_fill2);
    cudaGetSymbolAddress((void**)&es2, g_es2);
    cudaGetSymbolAddress((void**)&part1, g_part1);
    cudaGetSymbolAddress((void**)&part2, g_part2);

    const int TB = 256;
    const int tiles1 = cdiv(NDT, TILE);
    const int tiles2 = cdiv(NOD, TILE);

    // ---- weight transpose/convert + input convert ----
    WTList L;
    const float* ws[13] = {od1_wl, od1_wr, dt1_wl, dt1_wr, od2_wl, od2_wr,
                           od3_wl, od3_wr, od_lw, dt2_wl, dt2_wr, dt_lw, dec_w1};
    int Ks[13] = {128, 128, 128, 128, 128, 64, 128, 128, 128, 128, 128, 128, 128};
    int Ns[13] = {128, 128, 128, 128, 128, 128, 128, 128, 64, 128, 128, 64, 64};
    for (int i = 0; i < 13; i++) { L.src[i] = ws[i]; L.K[i] = Ks[i]; L.N[i] = Ns[i]; }
    k_wt<<<dim3(8, 13), 256>>>(L, wh);
    k_cvt<<<cdiv(NDT * 32 + NOD * 16, TB), TB>>>(x_dt, xdth, x_od, xodh);
#define WT(i) (wh + (size_t)(i) * WSLOT)

    // ---- CSR build (wide two-pass scan) ----
    cudaMemsetAsync(deg1, 0, NDT * sizeof(int));
    cudaMemsetAsync(deg2, 0, NOD * sizeof(int));
    k_degree2<<<cdiv(E1 + E2, TB), TB>>>(c1, E1, deg1, rdst, E2, deg2);
    k_scanA<<<tiles1 + tiles2, TB>>>(deg1, NDT, part1, tiles1, deg2, NOD, part2);
    k_scanB<<<tiles1 + tiles2, TB>>>(deg1, NDT, rp1, fill1, part1, tiles1,
                                     deg2, NOD, rp2, fill2, part2, tiles2);
    k_reorder2<<<cdiv(E1 + E2, TB), TB>>>(r1, c1, E1, rp1, fill1, es1,
                                          rsrc, rdst, E2, rp2, fill2, es2);

    // ---- pipeline ----
    k_aggh2<<<cdiv((long long)NDT * 32, TB), TB>>>(
        xdth, es1, rp1, acc1, NDT, nullptr, nullptr, nullptr, nullptr, 0);

    GemmProb ph  = {acc1, 128, xdth, 128, WT(0), WT(1), od1_b, h,  NDT, 1};
    GemmProb pd1 = {acc1, 128, xdth, 128, WT(2), WT(3), dt1_b, d1, NDT, 1};
    gemm_h<128, 128><<<dim3(cdiv(NDT, 128), 2), 512>>>(ph, pd1);

    k_aggh2<<<cdiv((long long)(NOD + NDT) * 32, TB), TB>>>(
        h, es2, rp2, acc2, NOD, d1, es1, rp1, acc3, NDT);

    GemmProb pod2 = {acc2, 128, xodh, 64, WT(4), WT(5), od2_b, od2b, NOD, 1};
    GemmProb pdt2 = {acc3, 128, d1, 128, WT(9), WT(10), dt2_b, d2, NDT, 1};
    gemm_h<128, 128><<<dim3(cdiv(NDT, 128), 2), 512>>>(pod2, pdt2);

    GemmProb pod3 = {acc2, 128, od2b, 128, WT(6), WT(7), od3_b, od3b, NOD, 1};
    gemm_h<128, 64><<<dim3(cdiv(NOD, 64), 1), 512>>>(pod3, pod3);

    GemmProb pzod = {od3b, 128, nullptr, 0, WT(8), nullptr, od_lb, zodh, NOD, 0};
    GemmProb pzdt = {d2, 128, nullptr, 0, WT(11), nullptr, dt_lb, zdth, NDT, 0};
    gemm_h<64, 64><<<dim3(cdiv(NDT, 64), 2), 512>>>(pzod, pzdt);

    dec_h<<<cdiv(EL, 128), 512>>>(EL, zodh, zdth, elsrc, eldst,
                                  WT(12), dec_b1, dec_w2, dec_b2, out);
}

// round 10
// speedup vs baseline: 4.2358x; 1.1231x over previous
#include <cuda_runtime.h>
#include <cuda_fp16.h>
#include <math.h>

#define NDT 30000
#define NOD 10000
#define WSLOT 16384
#define TILE 1024

static inline int cdiv(long long a, long long b) { return (int)((a + b - 1) / b); }

// ---------------- fp16 mma / ldmatrix helpers -----------------------------------
#define MMA_F16(d, a, b0, b1)                                              \
    asm volatile("mma.sync.aligned.m16n8k16.row.col.f32.f16.f16.f32 "      \
                 "{%0,%1,%2,%3}, {%4,%5,%6,%7}, {%8,%9}, {%0,%1,%2,%3};"   \
                 : "+f"((d)[0]), "+f"((d)[1]), "+f"((d)[2]), "+f"((d)[3])  \
                 : "r"((a)[0]), "r"((a)[1]), "r"((a)[2]), "r"((a)[3]),     \
                   "r"(b0), "r"(b1))

#define LDSM_X4(r0, r1, r2, r3, addr)                                      \
    asm volatile("ldmatrix.sync.aligned.m8n8.x4.shared.b16 "               \
                 "{%0,%1,%2,%3}, [%4];"                                    \
                 : "=r"(r0), "=r"(r1), "=r"(r2), "=r"(r3) : "r"(addr))

__device__ __forceinline__ unsigned smem_u32(const void* p) {
    return (unsigned)__cvta_generic_to_shared(p);
}

// ---------------- device scratch ------------------------------------------------
__device__ __half g_xdth[NDT * 128];
__device__ __half g_xodh[NOD * 64];
__device__ __half g_acc1[NDT * 128];
__device__ __half g_acc2[NOD * 128];
__device__ __half g_acc3[NDT * 128];
__device__ __half g_h [NDT * 128];
__device__ __half g_d1[NDT * 128];
__device__ __half g_od2[NOD * 128];
__device__ __half g_od3[NOD * 128];
__device__ __half g_d2[NDT * 128];
__device__ __half g_zodh[NOD * 64];
__device__ __half g_zdth[NDT * 64];
__device__ __half g_wh[13 * WSLOT];
// CSR scratch
__device__ int g_deg1[NDT];
__device__ int g_rp1[NDT + 1];
__device__ int g_fill1[NDT];
__device__ int g_es1[500000];
__device__ int g_deg2[NOD];
__device__ int g_rp2[NOD + 1];
__device__ int g_fill2[NOD];
__device__ int g_es2[300000];
__device__ int g_part1[64];
__device__ int g_part2[64];

// ---------------- input convert -------------------------------------------------
__global__ void k_cvt(const float* __restrict__ x_dt, __half* __restrict__ xdh,
                      const float* __restrict__ x_od, __half* __restrict__ xoh) {
    const int n1 = NDT * 128 / 4, n2 = NOD * 64 / 4;
    int i = blockIdx.x * blockDim.x + threadIdx.x;
    if (i < n1) {
        float4 v = *(const float4*)(x_dt + i * 4);
        __half2 h0 = __floats2half2_rn(v.x, v.y);
        __half2 h1 = __floats2half2_rn(v.z, v.w);
        *(uint2*)(xdh + i * 4) = make_uint2(*(unsigned*)&h0, *(unsigned*)&h1);
    } else if (i < n1 + n2) {
        int j = i - n1;
        float4 v = *(const float4*)(x_od + j * 4);
        __half2 h0 = __floats2half2_rn(v.x, v.y);
        __half2 h1 = __floats2half2_rn(v.z, v.w);
        *(uint2*)(xoh + j * 4) = make_uint2(*(unsigned*)&h0, *(unsigned*)&h1);
    }
}

// ---------------- weight transpose+convert: W[K][N] f32 -> Wt[N][K] f16 ---------
struct WTList {
    const float* src[13];
    int K[13];
    int N[13];
};
__global__ void k_wt(WTList L, __half* __restrict__ dst) {
    int w = blockIdx.y;
    int K = L.K[w], N = L.N[w];
    const float* s = L.src[w];
    __half* d = dst + (size_t)w * WSLOT;
    int total = K * N;
    for (int i = blockIdx.x * blockDim.x + threadIdx.x; i < total;
         i += gridDim.x * blockDim.x) {
        int n = i / K, k = i - n * K;
        d[i] = __float2half(s[k * N + n]);
    }
}

// ---------------- CSR build ------------------------------------------------------
__global__ void k_degree2(const int* __restrict__ c1, int E1, int* __restrict__ deg1,
                          const int* __restrict__ rdst, int E2, int* __restrict__ deg2) {
    int i = blockIdx.x * blockDim.x + threadIdx.x;
    if (i < E1) atomicAdd(deg1 + __ldg(c1 + i), 1);
    else if (i < E1 + E2) atomicAdd(deg2 + __ldg(rdst + (i - E1)), 1);
}

__global__ void k_scanA(const int* __restrict__ deg1, int n1, int* __restrict__ part1,
                        int tiles1,
                        const int* __restrict__ deg2, int n2, int* __restrict__ part2) {
    int b = blockIdx.x;
    const int* deg; int n; int* part; int tt;
    if (b < tiles1) { deg = deg1; n = n1; part = part1; tt = b; }
    else            { deg = deg2; n = n2; part = part2; tt = b - tiles1; }
    int t = threadIdx.x, lane = t & 31, w = t >> 5;
    int base = tt * TILE + t * 4;
    int tot = 0;
#pragma unroll
    for (int j = 0; j < 4; j++) tot += (base + j < n) ? deg[base + j] : 0;
    __shared__ int wsum[8];
#pragma unroll
    for (int o = 16; o; o >>= 1) tot += __shfl_xor_sync(0xffffffffu, tot, o);
    if (lane == 0) wsum[w] = tot;
    __syncthreads();
    if (t == 0) {
        int s = 0;
#pragma unroll
        for (int j = 0; j < 8; j++) s += wsum[j];
        part[tt] = s;
    }
}

__global__ void k_scanB(const int* __restrict__ deg1, int n1, int* __restrict__ rp1,
                        int* __restrict__ fill1, const int* __restrict__ part1, int tiles1,
                        const int* __restrict__ deg2, int n2, int* __restrict__ rp2,
                        int* __restrict__ fill2, const int* __restrict__ part2, int tiles2) {
    int b = blockIdx.x;
    const int* deg; int n; int* rp; int* fill; const int* part; int tt, tiles;
    if (b < tiles1) { deg = deg1; n = n1; rp = rp1; fill = fill1; part = part1; tt = b; tiles = tiles1; }
    else { deg = deg2; n = n2; rp = rp2; fill = fill2; part = part2; tt = b - tiles1; tiles = tiles2; }
    __shared__ int s_off;
    __shared__ int wsum[8];
    int t = threadIdx.x, lane = t & 31, w = t >> 5;
    if (t < 32) {
        int v = (t < tt) ? part[t] : 0;
#pragma unroll
        for (int o = 16; o; o >>= 1) v += __shfl_xor_sync(0xffffffffu, v, o);
        if (t == 0) s_off = v;
    }
    int base = tt * TILE + t * 4;
    int d[4]; int tot = 0;
#pragma unroll
    for (int j = 0; j < 4; j++) { d[j] = (base + j < n) ? deg[base + j] : 0; tot += d[j]; }
    int inc = tot;
#pragma unroll
    for (int o = 1; o < 32; o <<= 1) {
        int u = __shfl_up_sync(0xffffffffu, inc, o);
        if (lane >= o) inc += u;
    }
    if (lane == 31) wsum[w] = inc;
    __syncthreads();
    int woff = 0;
#pragma unroll
    for (int j = 0; j < 8; j++) if (j < w) woff += wsum[j];
    int run = s_off + woff + inc - tot;
#pragma unroll
    for (int j = 0; j < 4; j++) {
        if (base + j < n) { rp[base + j] = run; fill[base + j] = 0; run += d[j]; }
    }
    if (tt == tiles - 1 && t == blockDim.x - 1) rp[n] = run;
}

__global__ void k_reorder2(const int* __restrict__ s1, const int* __restrict__ t1, int E1,
                           const int* __restrict__ rp1, int* __restrict__ f1,
                           int* __restrict__ e1,
                           const int* __restrict__ s2, const int* __restrict__ t2, int E2,
                           const int* __restrict__ rp2, int* __restrict__ f2,
                           int* __restrict__ e2) {
    int i = blockIdx.x * blockDim.x + threadIdx.x;
    if (i < E1) {
        int d = __ldg(t1 + i);
        int pos = atomicAdd(f1 + d, 1);
        e1[rp1[d] + pos] = __ldg(s1 + i);
    } else if (i < E1 + E2) {
        int j = i - E1;
        int d = __ldg(t2 + j);
        int pos = atomicAdd(f2 + d, 1);
        e2[rp2[d] + pos] = __ldg(s2 + j);
    }
}

// ---------------- mean aggregation: warp per dst, 4 edges in flight -------------
// lane = (grp4: which of 4 concurrent edges) x (sub: 32B chunk of the 256B row)
__global__ __launch_bounds__(256)
void k_aggh2(const __half* __restrict__ X1, const int* __restrict__ es1,
             const int* __restrict__ rp1, __half* __restrict__ acc1, int n1,
             const __half* __restrict__ X2, const int* __restrict__ es2,
             const int* __restrict__ rp2, __half* __restrict__ acc2, int n2) {
    int w = (blockIdx.x * blockDim.x + threadIdx.x) >> 5;
    const __half* X; const int* es; const int* rowptr; __half* acc;
    if (w < n1) { X = X1; es = es1; rowptr = rp1; acc = acc1; }
    else if (w < n1 + n2) { X = X2; es = es2; rowptr = rp2; acc = acc2; w -= n1; }
    else return;
    int lane = threadIdx.x & 31;
    int grp4 = lane >> 3;    // 0..3: concurrent edge slot
    int sub = lane & 7;      // 0..7: 16-half (32B) chunk of the row
    int beg = __ldg(rowptr + w);
    int end = __ldg(rowptr + w + 1);
    float s[16];
#pragma unroll
    for (int k = 0; k < 16; k++) s[k] = 0.f;
    for (int base = beg; base < end; base += 32) {
        int p = 0;
        if (base + lane < end) p = __ldg(es + base + lane);
        int cnt = min(32, end - base);
        for (int j = 0; j < cnt; j += 4) {
            int e = j + grp4;
            int sr = __shfl_sync(0xffffffffu, p, e);
            if (e < cnt) {
                const uint4* row = (const uint4*)(X + (size_t)sr * 128 + sub * 16);
                uint4 v0 = __ldg(row);
                uint4 v1 = __ldg(row + 1);
                unsigned vv[8] = {v0.x, v0.y, v0.z, v0.w, v1.x, v1.y, v1.z, v1.w};
#pragma unroll
                for (int k = 0; k < 8; k++) {
                    float2 f = __half22float2(*(__half2*)&vv[k]);
                    s[2 * k] += f.x;
                    s[2 * k + 1] += f.y;
                }
            }
        }
    }
    // combine the 4 edge slots (lanes differing in bits 3,4)
#pragma unroll
    for (int k = 0; k < 16; k++) {
        s[k] += __shfl_xor_sync(0xffffffffu, s[k], 8);
        s[k] += __shfl_xor_sync(0xffffffffu, s[k], 16);
    }
    if (grp4 == 0) {
        float inv = 1.f / fmaxf((float)(end - beg), 1.f);
        unsigned o[8];
#pragma unroll
        for (int k = 0; k < 8; k++) {
            __half2 hv = __floats2half2_rn(s[2 * k] * inv, s[2 * k + 1] * inv);
            o[k] = *(unsigned*)&hv;
        }
        uint4* dst = (uint4*)(acc + (size_t)w * 128 + sub * 16);
        dst[0] = make_uint4(o[0], o[1], o[2], o[3]);
        dst[1] = make_uint4(o[4], o[5], o[6], o[7]);
    }
}

// ---------------- generic 2-problem fp16 GEMM (KC=32, ldmatrix) -----------------
struct GemmProb {
    const __half* A; int K1;
    const __half* B; int K2;
    const __half* W1; const __half* W2;   // pre-transposed [N][K] f16
    const float* bias;
    __half* Y;
    int M;
    int relu;
};

template <int NCOLS, int BR>
__global__ __launch_bounds__(512, 2)
void gemm_h(GemmProb p0, GemmProb p1) {
    constexpr int KC = 32;
    constexpr int AST = 40;              // 32 + 8 pad: ldmatrix conflict-free
    constexpr int MI = BR / 64;
    constexpr int NCW = NCOLS / 4;
    constexpr int NT = NCW / 8;
    constexpr int NG = NT / 2;
    constexpr int APT = BR * KC / 512;   // halves/thread: 8 (uint4) or 4 (uint2)
    constexpr int WPT = NCOLS * KC / 512;
    const GemmProb& p = blockIdx.y ? p1 : p0;
    const int row0 = blockIdx.x * BR;
    if (row0 >= p.M) return;

    __shared__ __half As[2][BR][AST];
    __shared__ __half Ws[2][NCOLS][AST];

    const int M = p.M;
    const int K1 = p.K1, K2 = p.K2;
    const __half* A = p.A;
    const __half* B = p.B;

    const int t = threadIdx.x;
    const int lane = t & 31;
    const int wid = t >> 5;
    const int warp_m = wid >> 2;
    const int warp_n = wid & 3;
    const int grp = lane >> 2;
    const int qid = lane & 3;
    const int lr = (BR == 128) ? (t >> 2) : (t >> 3);
    const int lk = (BR == 128) ? ((t & 3) * 8) : ((t & 7) * 4);
    const int grow = row0 + lr;
    const int wn = (NCOLS == 128) ? (t >> 2) : (t >> 3);
    const int wk = (NCOLS == 128) ? ((t & 3) * 8) : ((t & 7) * 4);
    const int lm_r = (lane & 7) + ((lane >> 3) & 1) * 8;
    const int lm_c = ((lane >> 4) & 1) * 8;

    const int n1 = K1 / KC;
    const int n2 = (B != nullptr) ? (K2 / KC) : 0;
    const int nch = n1 + n2;

    uint4 pa = make_uint4(0, 0, 0, 0), pw = make_uint4(0, 0, 0, 0);

    auto loadX = [&](int cc) {
        const __half* Xp; int stride, k0;
        if (cc < n1) { Xp = A; stride = K1; k0 = cc * KC; }
        else         { Xp = B; stride = K2; k0 = (cc - n1) * KC; }
        pa = make_uint4(0, 0, 0, 0);
        if (grow < M) {
            const __half* base = Xp + (size_t)grow * stride + k0 + lk;
            if (APT == 8) pa = *(const uint4*)base;
            else { uint2 v = *(const uint2*)base; pa.x = v.x; pa.y = v.y; }
        }
    };
    auto loadW = [&](int cc) {
        const __half* Wp; int stride, k0;
        if (cc < n1) { Wp = p.W1; stride = K1; k0 = cc * KC; }
        else         { Wp = p.W2; stride = K2; k0 = (cc - n1) * KC; }
        const __half* base = Wp + (size_t)wn * stride + k0 + wk;
        if (WPT == 8) pw = *(const uint4*)base;
        else { uint2 v = *(const uint2*)base; pw.x = v.x; pw.y = v.y; }
    };
    auto stage = [&](int buf) {
        if (APT == 8) *(uint4*)&As[buf][lr][lk] = pa;
        else          *(uint2*)&As[buf][lr][lk] = make_uint2(pa.x, pa.y);
        if (WPT == 8) *(uint4*)&Ws[buf][wn][wk] = pw;
        else          *(uint2*)&Ws[buf][wn][wk] = make_uint2(pw.x, pw.y);
    };

    float acc[MI][NT][4];
#pragma unroll
    for (int mi = 0; mi < MI; mi++)
#pragma unroll
        for (int ni = 0; ni < NT; ni++)
#pragma unroll
            for (int c = 0; c < 4; c++) acc[mi][ni][c] = 0.f;

    loadX(0); loadW(0); stage(0);

    for (int cc = 0; cc < nch; ++cc) {
        const int buf = cc & 1;
        __syncthreads();
        if (cc + 1 < nch) { loadX(cc + 1); loadW(cc + 1); }
#pragma unroll
        for (int ks = 0; ks < KC; ks += 16) {
            unsigned af[MI][4];
#pragma unroll
            for (int mi = 0; mi < MI; mi++) {
                int r = warp_m * (16 * MI) + mi * 16;
                LDSM_X4(af[mi][0], af[mi][1], af[mi][2], af[mi][3],
                        smem_u32(&As[buf][r + lm_r][ks + lm_c]));
            }
            unsigned bf[NG][4];
#pragma unroll
            for (int g = 0; g < NG; g++) {
                int c = warp_n * NCW + g * 16;
                LDSM_X4(bf[g][0], bf[g][1], bf[g][2], bf[g][3],
                        smem_u32(&Ws[buf][c + lm_r][ks + lm_c]));
            }
#pragma unroll
            for (int g = 0; g < NG; g++) {
#pragma unroll
                for (int half = 0; half < 2; half++) {
                    unsigned b0 = bf[g][half];
                    unsigned b1 = bf[g][half + 2];
#pragma unroll
                    for (int mi = 0; mi < MI; mi++)
                        MMA_F16(acc[mi][g * 2 + half], af[mi], b0, b1);
                }
            }
        }
        if (cc + 1 < nch) stage(buf ^ 1);
    }

#pragma unroll
    for (int ni = 0; ni < NT; ni++) {
        int cb = warp_n * NCW + ni * 8 + 2 * qid;
        float2 bv = make_float2(0.f, 0.f);
        if (p.bias != nullptr) bv = *(const float2*)(p.bias + cb);
#pragma unroll
        for (int mi = 0; mi < MI; mi++) {
            int r0 = row0 + warp_m * (16 * MI) + mi * 16 + grp;
            float v0 = acc[mi][ni][0] + bv.x;
            float v1 = acc[mi][ni][1] + bv.y;
            float v2 = acc[mi][ni][2] + bv.x;
            float v3 = acc[mi][ni][3] + bv.y;
            if (p.relu) {
                v0 = fmaxf(v0, 0.f); v1 = fmaxf(v1, 0.f);
                v2 = fmaxf(v2, 0.f); v3 = fmaxf(v3, 0.f);
            }
            __half2 h0 = __floats2half2_rn(v0, v1);
            __half2 h1 = __floats2half2_rn(v2, v3);
            if (r0 < M)     *(__half2*)(p.Y + (size_t)r0 * NCOLS + cb) = h0;
            if (r0 + 8 < M) *(__half2*)(p.Y + (size_t)(r0 + 8) * NCOLS + cb) = h1;
        }
    }
}

// ---------------- fused edge decoder (fp16 mma + ldmatrix, KC=32) ---------------
__global__ __launch_bounds__(512, 2)
void dec_h(int M, const __half* __restrict__ zod, const __half* __restrict__ zdt,
           const int* __restrict__ esrc, const int* __restrict__ edst,
           const __half* __restrict__ Wt, const float* __restrict__ b1,
           const float* __restrict__ w2, const float* __restrict__ b2p,
           float* __restrict__ out) {
    constexpr int NC = 64;
    constexpr int BR = 128;
    constexpr int K = 128;
    constexpr int KC = 32;
    constexpr int AST = 40;
    constexpr int NCW = 16;
    constexpr int NT = 2;
    constexpr int NCH = K / KC;   // 4
    __shared__ __half As[2][BR][AST];
    __shared__ __half Ws[2][NC][AST];
    __shared__ float Red[BR][17];

    const int t = threadIdx.x;
    const int lane = t & 31;
    const int wid = t >> 5;
    const int warp_m = wid >> 2;
    const int warp_n = wid & 3;
    const int grp = lane >> 2;
    const int qid = lane & 3;
    const int row0 = blockIdx.x * BR;
    const int lr = t >> 2;
    const int lk = (t & 3) * 8;
    const int grow = row0 + lr;
    const int wn = t >> 3;
    const int wk = (t & 7) * 4;
    const int lm_r = (lane & 7) + ((lane >> 3) & 1) * 8;
    const int lm_c = ((lane >> 4) & 1) * 8;

    int si = 0, di = 0;
    if (grow < M) { si = __ldg(esrc + grow); di = __ldg(edst + grow); }

    uint4 pa = make_uint4(0, 0, 0, 0);
    uint2 pwv = make_uint2(0, 0);

    auto loadX = [&](int cc) {
        pa = make_uint4(0, 0, 0, 0);
        if (grow < M) {
            int k = cc * KC + lk;
            const __half* base = (k < 64) ? (zod + (size_t)si * 64 + k)
                                          : (zdt + (size_t)di * 64 + (k - 64));
            pa = *(const uint4*)base;
        }
    };
    auto loadW = [&](int cc) {
        pwv = *(const uint2*)(Wt + (size_t)wn * K + cc * KC + wk);
    };
    auto stage = [&](int buf) {
        *(uint4*)&As[buf][lr][lk] = pa;
        *(uint2*)&Ws[buf][wn][wk] = pwv;
    };

    float acc[2][NT][4];
#pragma unroll
    for (int mi = 0; mi < 2; mi++)
#pragma unroll
        for (int ni = 0; ni < NT; ni++)
#pragma unroll
            for (int c = 0; c < 4; c++) acc[mi][ni][c] = 0.f;

    loadX(0); loadW(0); stage(0);

#pragma unroll 1
    for (int cc = 0; cc < NCH; ++cc) {
        const int buf = cc & 1;
        __syncthreads();
        if (cc + 1 < NCH) { loadX(cc + 1); loadW(cc + 1); }
#pragma unroll
        for (int ks = 0; ks < KC; ks += 16) {
            unsigned af[2][4];
#pragma unroll
            for (int mi = 0; mi < 2; mi++) {
                int r = warp_m * 32 + mi * 16;
                LDSM_X4(af[mi][0], af[mi][1], af[mi][2], af[mi][3],
                        smem_u32(&As[buf][r + lm_r][ks + lm_c]));
            }
            unsigned bf[4];
            {
                int c = warp_n * NCW;
                LDSM_X4(bf[0], bf[1], bf[2], bf[3],
                        smem_u32(&Ws[buf][c + lm_r][ks + lm_c]));
            }
#pragma unroll
            for (int half = 0; half < 2; half++) {
                unsigned b0 = bf[half];
                unsigned b1 = bf[half + 2];
                MMA_F16(acc[0][half], af[0], b0, b1);
                MMA_F16(acc[1][half], af[1], b0, b1);
            }
        }
        if (cc + 1 < NCH) stage(buf ^ 1);
    }

    float p[2][2] = {{0.f, 0.f}, {0.f, 0.f}};
#pragma unroll
    for (int ni = 0; ni < NT; ni++) {
        int cb = warp_n * NCW + ni * 8 + 2 * qid;
        float2 bv = *(const float2*)(b1 + cb);
        float2 wv = *(const float2*)(w2 + cb);
#pragma unroll
        for (int mi = 0; mi < 2; mi++) {
            p[mi][0] += fmaxf(acc[mi][ni][0] + bv.x, 0.f) * wv.x
                      + fmaxf(acc[mi][ni][1] + bv.y, 0.f) * wv.y;
            p[mi][1] += fmaxf(acc[mi][ni][2] + bv.x, 0.f) * wv.x
                      + fmaxf(acc[mi][ni][3] + bv.y, 0.f) * wv.y;
        }
    }
    __syncthreads();
#pragma unroll
    for (int mi = 0; mi < 2; mi++) {
        Red[warp_m * 32 + mi * 16 + grp    ][warp_n * 4 + qid] = p[mi][0];
        Red[warp_m * 32 + mi * 16 + grp + 8][warp_n * 4 + qid] = p[mi][1];
    }
    __syncthreads();
    if (t < BR) {
        int r = row0 + t;
        if (r < M) {
            float s = 0.f;
#pragma unroll
            for (int j = 0; j < 16; j++) s += Red[t][j];
            out[r] = 1.f / (1.f + expf(-(s + b2p[0])));
        }
    }
}

// ---------------- host orchestration --------------------------------------------
extern "C" void kernel_launch(void* const* d_in, const int* in_sizes, int n_in,
                              void* d_out, int out_size) {
    const float* x_dt   = (const float*)d_in[0];
    const float* x_od   = (const float*)d_in[1];
    const int*   ei_dt  = (const int*)  d_in[2];
    const int*   rsrc   = (const int*)  d_in[3];
    const int*   rdst   = (const int*)  d_in[4];
    const int*   elsrc  = (const int*)  d_in[5];
    const int*   eldst  = (const int*)  d_in[6];
    const float* od1_wl = (const float*)d_in[7];
    const float* od1_wr = (const float*)d_in[8];
    const float* od1_b  = (const float*)d_in[9];
    const float* od2_wl = (const float*)d_in[10];
    const float* od2_wr = (const float*)d_in[11];
    const float* od2_b  = (const float*)d_in[12];
    const float* od3_wl = (const float*)d_in[13];
    const float* od3_wr = (const float*)d_in[14];
    const float* od3_b  = (const float*)d_in[15];
    const float* od_lw  = (const float*)d_in[16];
    const float* od_lb  = (const float*)d_in[17];
    const float* dt1_wl = (const float*)d_in[18];
    const float* dt1_wr = (const float*)d_in[19];
    const float* dt1_b  = (const float*)d_in[20];
    const float* dt2_wl = (const float*)d_in[21];
    const float* dt2_wr = (const float*)d_in[22];
    const float* dt2_b  = (const float*)d_in[23];
    const float* dt_lw  = (const float*)d_in[24];
    const float* dt_lb  = (const float*)d_in[25];
    const float* dec_w1 = (const float*)d_in[26];
    const float* dec_b1 = (const float*)d_in[27];
    const float* dec_w2 = (const float*)d_in[28];
    const float* dec_b2 = (const float*)d_in[29];
    float* out = (float*)d_out;

    const int E1 = in_sizes[2] / 2;
    const int E2 = in_sizes[3];
    const int EL = in_sizes[5];
    const int* r1 = ei_dt;
    const int* c1 = ei_dt + E1;

    __half *xdth, *xodh, *acc1, *acc2, *acc3, *h, *d1, *od2b, *od3b, *d2;
    __half *zodh, *zdth, *wh;
    int *deg1, *rp1, *fill1, *es1, *deg2, *rp2, *fill2, *es2, *part1, *part2;
    cudaGetSymbolAddress((void**)&xdth, g_xdth);
    cudaGetSymbolAddress((void**)&xodh, g_xodh);
    cudaGetSymbolAddress((void**)&acc1, g_acc1);
    cudaGetSymbolAddress((void**)&acc2, g_acc2);
    cudaGetSymbolAddress((void**)&acc3, g_acc3);
    cudaGetSymbolAddress((void**)&h,   g_h);
    cudaGetSymbolAddress((void**)&d1,  g_d1);
    cudaGetSymbolAddress((void**)&od2b, g_od2);
    cudaGetSymbolAddress((void**)&od3b, g_od3);
    cudaGetSymbolAddress((void**)&d2,  g_d2);
    cudaGetSymbolAddress((void**)&zodh, g_zodh);
    cudaGetSymbolAddress((void**)&zdth, g_zdth);
    cudaGetSymbolAddress((void**)&wh,  g_wh);
    cudaGetSymbolAddress((void**)&deg1, g_deg1);
    cudaGetSymbolAddress((void**)&rp1, g_rp1);
    cudaGetSymbolAddress((void**)&fill1, g_fill1);
    cudaGetSymbolAddress((void**)&es1, g_es1);
    cudaGetSymbolAddress((void**)&deg2, g_deg2);
    cudaGetSymbolAddress((void**)&rp2, g_rp2);
    cudaGetSymbolAddress((void**)&fill2, g_fill2);
    cudaGetSymbolAddress((void**)&es2, g_es2);
    cudaGetSymbolAddress((void**)&part1, g_part1);
    cudaGetSymbolAddress((void**)&part2, g_part2);

    const int TB = 256;
    const int tiles1 = cdiv(NDT, TILE);
    const int tiles2 = cdiv(NOD, TILE);

    // ---- weight transpose/convert + input convert ----
    WTList L;
    const float* ws[13] = {od1_wl, od1_wr, dt1_wl, dt1_wr, od2_wl, od2_wr,
                           od3_wl, od3_wr, od_lw, dt2_wl, dt2_wr, dt_lw, dec_w1};
    int Ks[13] = {128, 128, 128, 128, 128, 64, 128, 128, 128, 128, 128, 128, 128};
    int Ns[13] = {128, 128, 128, 128, 128, 128, 128, 128, 64, 128, 128, 64, 64};
    for (int i = 0; i < 13; i++) { L.src[i] = ws[i]; L.K[i] = Ks[i]; L.N[i] = Ns[i]; }
    k_wt<<<dim3(8, 13), 256>>>(L, wh);
    k_cvt<<<cdiv(NDT * 32 + NOD * 16, TB), TB>>>(x_dt, xdth, x_od, xodh);
#define WT(i) (wh + (size_t)(i) * WSLOT)

    // ---- CSR build (wide two-pass scan) ----
    cudaMemsetAsync(deg1, 0, NDT * sizeof(int));
    cudaMemsetAsync(deg2, 0, NOD * sizeof(int));
    k_degree2<<<cdiv(E1 + E2, TB), TB>>>(c1, E1, deg1, rdst, E2, deg2);
    k_scanA<<<tiles1 + tiles2, TB>>>(deg1, NDT, part1, tiles1, deg2, NOD, part2);
    k_scanB<<<tiles1 + tiles2, TB>>>(deg1, NDT, rp1, fill1, part1, tiles1,
                                     deg2, NOD, rp2, fill2, part2, tiles2);
    k_reorder2<<<cdiv(E1 + E2, TB), TB>>>(r1, c1, E1, rp1, fill1, es1,
                                          rsrc, rdst, E2, rp2, fill2, es2);

    // ---- pipeline ----
    k_aggh2<<<cdiv((long long)NDT * 32, TB), TB>>>(
        xdth, es1, rp1, acc1, NDT, nullptr, nullptr, nullptr, nullptr, 0);

    GemmProb ph  = {acc1, 128, xdth, 128, WT(0), WT(1), od1_b, h,  NDT, 1};
    GemmProb pd1 = {acc1, 128, xdth, 128, WT(2), WT(3), dt1_b, d1, NDT, 1};
    gemm_h<128, 128><<<dim3(cdiv(NDT, 128), 2), 512>>>(ph, pd1);

    k_aggh2<<<cdiv((long long)(NOD + NDT) * 32, TB), TB>>>(
        h, es2, rp2, acc2, NOD, d1, es1, rp1, acc3, NDT);

    GemmProb pod2 = {acc2, 128, xodh, 64, WT(4), WT(5), od2_b, od2b, NOD, 1};
    GemmProb pdt2 = {acc3, 128, d1, 128, WT(9), WT(10), dt2_b, d2, NDT, 1};
    gemm_h<128, 128><<<dim3(cdiv(NDT, 128), 2), 512>>>(pod2, pdt2);

    GemmProb pod3 = {acc2, 128, od2b, 128, WT(6), WT(7), od3_b, od3b, NOD, 1};
    gemm_h<128, 64><<<dim3(cdiv(NOD, 64), 1), 512>>>(pod3, pod3);

    GemmProb pzod = {od3b, 128, nullptr, 0, WT(8), nullptr, od_lb, zodh, NOD, 0};
    GemmProb pzdt = {d2, 128, nullptr, 0, WT(11), nullptr, dt_lb, zdth, NDT, 0};
    gemm_h<64, 64><<<dim3(cdiv(NDT, 64), 2), 512>>>(pzod, pzdt);

    dec_h<<<cdiv(EL, 128), 512>>>(EL, zodh, zdth, elsrc, eldst,
                                  WT(12), dec_b1, dec_w2, dec_b2, out);
}

// round 11
// speedup vs baseline: 4.3839x; 1.0350x over previous
#include <cuda_runtime.h>
#include <cuda_fp16.h>
#include <math.h>

#define NDT 30000
#define NOD 10000
#define WSLOT 16384
#define TILE 1024

static inline int cdiv(long long a, long long b) { return (int)((a + b - 1) / b); }

// ---------------- fp16 mma / ldmatrix helpers -----------------------------------
#define MMA_F16(d, a, b0, b1)                                              \
    asm volatile("mma.sync.aligned.m16n8k16.row.col.f32.f16.f16.f32 "      \
                 "{%0,%1,%2,%3}, {%4,%5,%6,%7}, {%8,%9}, {%0,%1,%2,%3};"   \
                 : "+f"((d)[0]), "+f"((d)[1]), "+f"((d)[2]), "+f"((d)[3])  \
                 : "r"((a)[0]), "r"((a)[1]), "r"((a)[2]), "r"((a)[3]),     \
                   "r"(b0), "r"(b1))

#define LDSM_X4(r0, r1, r2, r3, addr)                                      \
    asm volatile("ldmatrix.sync.aligned.m8n8.x4.shared.b16 "               \
                 "{%0,%1,%2,%3}, [%4];"                                    \
                 : "=r"(r0), "=r"(r1), "=r"(r2), "=r"(r3) : "r"(addr))

__device__ __forceinline__ unsigned smem_u32(const void* p) {
    return (unsigned)__cvta_generic_to_shared(p);
}

// ---------------- device scratch ------------------------------------------------
__device__ __half g_xdth[NDT * 128];
__device__ __half g_xodh[NOD * 64];
__device__ __half g_acc1[NDT * 128];
__device__ __half g_acc2[NOD * 128];
__device__ __half g_acc3[NDT * 128];
__device__ __half g_h [NDT * 128];
__device__ __half g_d1[NDT * 128];
__device__ __half g_od2[NOD * 128];
__device__ __half g_zodh[NOD * 64];
__device__ __half g_zdth[NDT * 64];
__device__ __half g_wh[13 * WSLOT];
// CSR scratch
__device__ int g_deg1[NDT];
__device__ int g_rp1[NDT + 1];
__device__ int g_fill1[NDT];
__device__ int g_es1[500000];
__device__ int g_deg2[NOD];
__device__ int g_rp2[NOD + 1];
__device__ int g_fill2[NOD];
__device__ int g_es2[300000];
__device__ int g_part1[64];
__device__ int g_part2[64];
__device__ int g_scan_cnt;

// ---------------- input convert + scratch zeroing (one launch) ------------------
__global__ void k_cvt(const float* __restrict__ x_dt, __half* __restrict__ xdh,
                      const float* __restrict__ x_od, __half* __restrict__ xoh,
                      int* __restrict__ deg1, int* __restrict__ deg2,
                      int* __restrict__ cnt) {
    const int n1 = NDT * 128 / 4, n2 = NOD * 64 / 4;
    const int z1 = NDT / 4, z2 = NOD / 4;
    int i = blockIdx.x * blockDim.x + threadIdx.x;
    if (i < n1) {
        float4 v = *(const float4*)(x_dt + i * 4);
        __half2 h0 = __floats2half2_rn(v.x, v.y);
        __half2 h1 = __floats2half2_rn(v.z, v.w);
        *(uint2*)(xdh + i * 4) = make_uint2(*(unsigned*)&h0, *(unsigned*)&h1);
    } else if (i < n1 + n2) {
        int j = i - n1;
        float4 v = *(const float4*)(x_od + j * 4);
        __half2 h0 = __floats2half2_rn(v.x, v.y);
        __half2 h1 = __floats2half2_rn(v.z, v.w);
        *(uint2*)(xoh + j * 4) = make_uint2(*(unsigned*)&h0, *(unsigned*)&h1);
    } else if (i < n1 + n2 + z1) {
        ((int4*)deg1)[i - (n1 + n2)] = make_int4(0, 0, 0, 0);
    } else if (i < n1 + n2 + z1 + z2) {
        ((int4*)deg2)[i - (n1 + n2 + z1)] = make_int4(0, 0, 0, 0);
    } else if (i == n1 + n2 + z1 + z2) {
        *cnt = 0;
    }
}

// ---------------- weight transpose+convert: W[K][N] f32 -> Wt[N][K] f16 ---------
struct WTList {
    const float* src[13];
    int K[13];
    int N[13];
};
__global__ void k_wt(WTList L, __half* __restrict__ dst) {
    int w = blockIdx.y;
    int K = L.K[w], N = L.N[w];
    const float* s = L.src[w];
    __half* d = dst + (size_t)w * WSLOT;
    int total = K * N;
    for (int i = blockIdx.x * blockDim.x + threadIdx.x; i < total;
         i += gridDim.x * blockDim.x) {
        int n = i / K, k = i - n * K;
        d[i] = __float2half(s[k * N + n]);
    }
}

// ---------------- CSR build ------------------------------------------------------
__global__ void k_degree2(const int* __restrict__ c1, int E1, int* __restrict__ deg1,
                          const int* __restrict__ rdst, int E2, int* __restrict__ deg2) {
    int i = blockIdx.x * blockDim.x + threadIdx.x;
    if (i < E1) atomicAdd(deg1 + __ldg(c1 + i), 1);
    else if (i < E1 + E2) atomicAdd(deg2 + __ldg(rdst + (i - E1)), 1);
}

// fused two-phase scan with device-wide spin barrier (40 blocks, all resident)
__global__ void k_scan(const int* __restrict__ deg1, int n1, int* __restrict__ rp1,
                       int* __restrict__ fill1, int* __restrict__ part1, int tiles1,
                       const int* __restrict__ deg2, int n2, int* __restrict__ rp2,
                       int* __restrict__ fill2, int* __restrict__ part2, int tiles2,
                       int* __restrict__ cnt) {
    int b = blockIdx.x;
    const int* deg; int n; int* rp; int* fill; int* part; int tt, tiles;
    if (b < tiles1) { deg = deg1; n = n1; rp = rp1; fill = fill1; part = part1; tt = b; tiles = tiles1; }
    else { deg = deg2; n = n2; rp = rp2; fill = fill2; part = part2; tt = b - tiles1; tiles = tiles2; }
    __shared__ int wsum[8];
    __shared__ int s_off;
    int t = threadIdx.x, lane = t & 31, w = t >> 5;
    int base = tt * TILE + t * 4;
    int d[4]; int tot = 0;
#pragma unroll
    for (int j = 0; j < 4; j++) { d[j] = (base + j < n) ? deg[base + j] : 0; tot += d[j]; }
    int inc = tot;
#pragma unroll
    for (int o = 1; o < 32; o <<= 1) {
        int u = __shfl_up_sync(0xffffffffu, inc, o);
        if (lane >= o) inc += u;
    }
    if (lane == 31) wsum[w] = inc;
    __syncthreads();
    if (t == 0) {
        int s = 0;
#pragma unroll
        for (int j = 0; j < 8; j++) s += wsum[j];
        part[tt] = s;
        __threadfence();
        atomicAdd(cnt, 1);
        while (atomicAdd(cnt, 0) < tiles1 + tiles2) {}
        __threadfence();
    }
    __syncthreads();
    if (t < 32) {
        int v = (t < tt) ? atomicAdd(part + t, 0) : 0;
#pragma unroll
        for (int o = 16; o; o >>= 1) v += __shfl_xor_sync(0xffffffffu, v, o);
        if (t == 0) s_off = v;
    }
    __syncthreads();
    int woff = 0;
#pragma unroll
    for (int j = 0; j < 8; j++) if (j < w) woff += wsum[j];
    int run = s_off + woff + inc - tot;
#pragma unroll
    for (int j = 0; j < 4; j++) {
        if (base + j < n) { rp[base + j] = run; fill[base + j] = 0; run += d[j]; }
    }
    if (tt == tiles - 1 && t == blockDim.x - 1) rp[n] = run;
}

__global__ void k_reorder2(const int* __restrict__ s1, const int* __restrict__ t1, int E1,
                           const int* __restrict__ rp1, int* __restrict__ f1,
                           int* __restrict__ e1,
                           const int* __restrict__ s2, const int* __restrict__ t2, int E2,
                           const int* __restrict__ rp2, int* __restrict__ f2,
                           int* __restrict__ e2) {
    int i = blockIdx.x * blockDim.x + threadIdx.x;
    if (i < E1) {
        int d = __ldg(t1 + i);
        int pos = atomicAdd(f1 + d, 1);
        e1[rp1[d] + pos] = __ldg(s1 + i);
    } else if (i < E1 + E2) {
        int j = i - E1;
        int d = __ldg(t2 + j);
        int pos = atomicAdd(f2 + d, 1);
        e2[rp2[d] + pos] = __ldg(s2 + j);
    }
}

// ---------------- mean aggregation: warp per dst, 4 edges in flight -------------
__global__ __launch_bounds__(256)
void k_aggh2(const __half* __restrict__ X1, const int* __restrict__ es1,
             const int* __restrict__ rp1, __half* __restrict__ acc1, int n1,
             const __half* __restrict__ X2, const int* __restrict__ es2,
             const int* __restrict__ rp2, __half* __restrict__ acc2, int n2) {
    int w = (blockIdx.x * blockDim.x + threadIdx.x) >> 5;
    const __half* X; const int* es; const int* rowptr; __half* acc;
    if (w < n1) { X = X1; es = es1; rowptr = rp1; acc = acc1; }
    else if (w < n1 + n2) { X = X2; es = es2; rowptr = rp2; acc = acc2; w -= n1; }
    else return;
    int lane = threadIdx.x & 31;
    int grp4 = lane >> 3;
    int sub = lane & 7;
    int beg = __ldg(rowptr + w);
    int end = __ldg(rowptr + w + 1);
    float s[16];
#pragma unroll
    for (int k = 0; k < 16; k++) s[k] = 0.f;
    for (int base = beg; base < end; base += 32) {
        int p = 0;
        if (base + lane < end) p = __ldg(es + base + lane);
        int cnt = min(32, end - base);
        for (int j = 0; j < cnt; j += 4) {
            int e = j + grp4;
            int sr = __shfl_sync(0xffffffffu, p, e);
            if (e < cnt) {
                const uint4* row = (const uint4*)(X + (size_t)sr * 128 + sub * 16);
                uint4 v0 = __ldg(row);
                uint4 v1 = __ldg(row + 1);
                unsigned vv[8] = {v0.x, v0.y, v0.z, v0.w, v1.x, v1.y, v1.z, v1.w};
#pragma unroll
                for (int k = 0; k < 8; k++) {
                    float2 f = __half22float2(*(__half2*)&vv[k]);
                    s[2 * k] += f.x;
                    s[2 * k + 1] += f.y;
                }
            }
        }
    }
#pragma unroll
    for (int k = 0; k < 16; k++) {
        s[k] += __shfl_xor_sync(0xffffffffu, s[k], 8);
        s[k] += __shfl_xor_sync(0xffffffffu, s[k], 16);
    }
    if (grp4 == 0) {
        float inv = 1.f / fmaxf((float)(end - beg), 1.f);
        unsigned o[8];
#pragma unroll
        for (int k = 0; k < 8; k++) {
            __half2 hv = __floats2half2_rn(s[2 * k] * inv, s[2 * k + 1] * inv);
            o[k] = *(unsigned*)&hv;
        }
        uint4* dst = (uint4*)(acc + (size_t)w * 128 + sub * 16);
        dst[0] = make_uint4(o[0], o[1], o[2], o[3]);
        dst[1] = make_uint4(o[4], o[5], o[6], o[7]);
    }
}

// ---------------- generic 2-problem fp16 GEMM (KC=32, ldmatrix) -----------------
struct GemmProb {
    const __half* A; int K1;
    const __half* B; int K2;
    const __half* W1; const __half* W2;
    const float* bias;
    __half* Y;
    int M;
    int relu;
};

template <int NCOLS, int BR>
__global__ __launch_bounds__(512, 2)
void gemm_h(GemmProb p0, GemmProb p1) {
    constexpr int KC = 32;
    constexpr int AST = 40;
    constexpr int MI = BR / 64;
    constexpr int NCW = NCOLS / 4;
    constexpr int NT = NCW / 8;
    constexpr int NG = NT / 2;
    constexpr int APT = BR * KC / 512;
    constexpr int WPT = NCOLS * KC / 512;
    const GemmProb& p = blockIdx.y ? p1 : p0;
    const int row0 = blockIdx.x * BR;
    if (row0 >= p.M) return;

    __shared__ __half As[2][BR][AST];
    __shared__ __half Ws[2][NCOLS][AST];

    const int M = p.M;
    const int K1 = p.K1, K2 = p.K2;
    const __half* A = p.A;
    const __half* B = p.B;

    const int t = threadIdx.x;
    const int lane = t & 31;
    const int wid = t >> 5;
    const int warp_m = wid >> 2;
    const int warp_n = wid & 3;
    const int grp = lane >> 2;
    const int qid = lane & 3;
    const int lr = (BR == 128) ? (t >> 2) : (t >> 3);
    const int lk = (BR == 128) ? ((t & 3) * 8) : ((t & 7) * 4);
    const int grow = row0 + lr;
    const int wn = (NCOLS == 128) ? (t >> 2) : (t >> 3);
    const int wk = (NCOLS == 128) ? ((t & 3) * 8) : ((t & 7) * 4);
    const int lm_r = (lane & 7) + ((lane >> 3) & 1) * 8;
    const int lm_c = ((lane >> 4) & 1) * 8;

    const int n1 = K1 / KC;
    const int n2 = (B != nullptr) ? (K2 / KC) : 0;
    const int nch = n1 + n2;

    uint4 pa = make_uint4(0, 0, 0, 0), pw = make_uint4(0, 0, 0, 0);

    auto loadX = [&](int cc) {
        const __half* Xp; int stride, k0;
        if (cc < n1) { Xp = A; stride = K1; k0 = cc * KC; }
        else         { Xp = B; stride = K2; k0 = (cc - n1) * KC; }
        pa = make_uint4(0, 0, 0, 0);
        if (grow < M) {
            const __half* base = Xp + (size_t)grow * stride + k0 + lk;
            if (APT == 8) pa = *(const uint4*)base;
            else { uint2 v = *(const uint2*)base; pa.x = v.x; pa.y = v.y; }
        }
    };
    auto loadW = [&](int cc) {
        const __half* Wp; int stride, k0;
        if (cc < n1) { Wp = p.W1; stride = K1; k0 = cc * KC; }
        else         { Wp = p.W2; stride = K2; k0 = (cc - n1) * KC; }
        const __half* base = Wp + (size_t)wn * stride + k0 + wk;
        if (WPT == 8) pw = *(const uint4*)base;
        else { uint2 v = *(const uint2*)base; pw.x = v.x; pw.y = v.y; }
    };
    auto stage = [&](int buf) {
        if (APT == 8) *(uint4*)&As[buf][lr][lk] = pa;
        else          *(uint2*)&As[buf][lr][lk] = make_uint2(pa.x, pa.y);
        if (WPT == 8) *(uint4*)&Ws[buf][wn][wk] = pw;
        else          *(uint2*)&Ws[buf][wn][wk] = make_uint2(pw.x, pw.y);
    };

    float acc[MI][NT][4];
#pragma unroll
    for (int mi = 0; mi < MI; mi++)
#pragma unroll
        for (int ni = 0; ni < NT; ni++)
#pragma unroll
            for (int c = 0; c < 4; c++) acc[mi][ni][c] = 0.f;

    loadX(0); loadW(0); stage(0);

    for (int cc = 0; cc < nch; ++cc) {
        const int buf = cc & 1;
        __syncthreads();
        if (cc + 1 < nch) { loadX(cc + 1); loadW(cc + 1); }
#pragma unroll
        for (int ks = 0; ks < KC; ks += 16) {
            unsigned af[MI][4];
#pragma unroll
            for (int mi = 0; mi < MI; mi++) {
                int r = warp_m * (16 * MI) + mi * 16;
                LDSM_X4(af[mi][0], af[mi][1], af[mi][2], af[mi][3],
                        smem_u32(&As[buf][r + lm_r][ks + lm_c]));
            }
            unsigned bf[NG][4];
#pragma unroll
            for (int g = 0; g < NG; g++) {
                int c = warp_n * NCW + g * 16;
                LDSM_X4(bf[g][0], bf[g][1], bf[g][2], bf[g][3],
                        smem_u32(&Ws[buf][c + lm_r][ks + lm_c]));
            }
#pragma unroll
            for (int g = 0; g < NG; g++) {
#pragma unroll
                for (int half = 0; half < 2; half++) {
                    unsigned b0 = bf[g][half];
                    unsigned b1 = bf[g][half + 2];
#pragma unroll
                    for (int mi = 0; mi < MI; mi++)
                        MMA_F16(acc[mi][g * 2 + half], af[mi], b0, b1);
                }
            }
        }
        if (cc + 1 < nch) stage(buf ^ 1);
    }

#pragma unroll
    for (int ni = 0; ni < NT; ni++) {
        int cb = warp_n * NCW + ni * 8 + 2 * qid;
        float2 bv = make_float2(0.f, 0.f);
        if (p.bias != nullptr) bv = *(const float2*)(p.bias + cb);
#pragma unroll
        for (int mi = 0; mi < MI; mi++) {
            int r0 = row0 + warp_m * (16 * MI) + mi * 16 + grp;
            float v0 = acc[mi][ni][0] + bv.x;
            float v1 = acc[mi][ni][1] + bv.y;
            float v2 = acc[mi][ni][2] + bv.x;
            float v3 = acc[mi][ni][3] + bv.y;
            if (p.relu) {
                v0 = fmaxf(v0, 0.f); v1 = fmaxf(v1, 0.f);
                v2 = fmaxf(v2, 0.f); v3 = fmaxf(v3, 0.f);
            }
            __half2 h0 = __floats2half2_rn(v0, v1);
            __half2 h1 = __floats2half2_rn(v2, v3);
            if (r0 < M)     *(__half2*)(p.Y + (size_t)r0 * NCOLS + cb) = h0;
            if (r0 + 8 < M) *(__half2*)(p.Y + (size_t)(r0 + 8) * NCOLS + cb) = h1;
        }
    }
}

// ---------------- chained GEMM: Y2 = (relu(A@W1 + B@W2 + b)) @ W3 + b3 ----------
// Stage 1 identical to gemm_h<128,128>; Y1 never touches gmem — re-staged into
// the same smem buffers 32 cols/chunk, second MMA loop vs W3 [64][128].
struct ChainProb {
    const __half* A; int K1;
    const __half* B; int K2;
    const __half* W1; const __half* W2;   // [128][K]
    const float* bias;                    // stage-1 bias (relu)
    const __half* W3;                     // [64][128]
    const float* bias3;                   // [64]
    __half* Y2;                           // [M][64]
    int M;
};

__global__ __launch_bounds__(512, 1)
void chain_h(ChainProb p0, ChainProb p1) {
    constexpr int KC = 32;
    constexpr int AST = 40;
    constexpr int BR = 128;
    constexpr int NCOLS = 128;
    constexpr int NCW = 32;
    constexpr int NT = 4;
    constexpr int NG = 2;
    const ChainProb& p = blockIdx.y ? p1 : p0;
    const int row0 = blockIdx.x * BR;
    if (row0 >= p.M) return;

    __shared__ __half As[2][BR][AST];
    __shared__ __half Ws[2][NCOLS][AST];

    const int M = p.M;
    const int K1 = p.K1, K2 = p.K2;

    const int t = threadIdx.x;
    const int lane = t & 31;
    const int wid = t >> 5;
    const int warp_m = wid >> 2;
    const int warp_n = wid & 3;
    const int grp = lane >> 2;
    const int qid = lane & 3;
    const int lr = t >> 2;
    const int lk = (t & 3) * 8;
    const int grow = row0 + lr;
    const int wn = t >> 2;
    const int wk = (t & 3) * 8;
    const int lm_r = (lane & 7) + ((lane >> 3) & 1) * 8;
    const int lm_c = ((lane >> 4) & 1) * 8;

    const int n1 = K1 / KC;
    const int n2 = K2 / KC;
    const int nch = n1 + n2;

    uint4 pa = make_uint4(0, 0, 0, 0), pw = make_uint4(0, 0, 0, 0);

    auto loadX = [&](int cc) {
        const __half* Xp; int stride, k0;
        if (cc < n1) { Xp = p.A; stride = K1; k0 = cc * KC; }
        else         { Xp = p.B; stride = K2; k0 = (cc - n1) * KC; }
        pa = make_uint4(0, 0, 0, 0);
        if (grow < M) pa = *(const uint4*)(Xp + (size_t)grow * stride + k0 + lk);
    };
    auto loadW = [&](int cc) {
        const __half* Wp; int stride, k0;
        if (cc < n1) { Wp = p.W1; stride = K1; k0 = cc * KC; }
        else         { Wp = p.W2; stride = K2; k0 = (cc - n1) * KC; }
        pw = *(const uint4*)(Wp + (size_t)wn * stride + k0 + wk);
    };
    auto stage = [&](int buf) {
        *(uint4*)&As[buf][lr][lk] = pa;
        *(uint4*)&Ws[buf][wn][wk] = pw;
    };

    float acc[2][NT][4];
#pragma unroll
    for (int mi = 0; mi < 2; mi++)
#pragma unroll
        for (int ni = 0; ni < NT; ni++)
#pragma unroll
            for (int c = 0; c < 4; c++) acc[mi][ni][c] = 0.f;

    loadX(0); loadW(0); stage(0);

    for (int cc = 0; cc < nch; ++cc) {
        const int buf = cc & 1;
        __syncthreads();
        if (cc + 1 < nch) { loadX(cc + 1); loadW(cc + 1); }
#pragma unroll
        for (int ks = 0; ks < KC; ks += 16) {
            unsigned af[2][4];
#pragma unroll
            for (int mi = 0; mi < 2; mi++) {
                int r = warp_m * 32 + mi * 16;
                LDSM_X4(af[mi][0], af[mi][1], af[mi][2], af[mi][3],
                        smem_u32(&As[buf][r + lm_r][ks + lm_c]));
            }
            unsigned bf[NG][4];
#pragma unroll
            for (int g = 0; g < NG; g++) {
                int c = warp_n * NCW + g * 16;
                LDSM_X4(bf[g][0], bf[g][1], bf[g][2], bf[g][3],
                        smem_u32(&Ws[buf][c + lm_r][ks + lm_c]));
            }
#pragma unroll
            for (int g = 0; g < NG; g++) {
#pragma unroll
                for (int half = 0; half < 2; half++) {
#pragma unroll
                    for (int mi = 0; mi < 2; mi++)
                        MMA_F16(acc[mi][g * 2 + half], af[mi], bf[g][half], bf[g][half + 2]);
                }
            }
        }
        if (cc + 1 < nch) stage(buf ^ 1);
    }

    // ---- stage 2: z = relu(Y1) @ W3 + b3, 4 chunks of 32 K-cols ----
    float acc2[2][2][4];
#pragma unroll
    for (int mi = 0; mi < 2; mi++)
#pragma unroll
        for (int ni = 0; ni < 2; ni++)
#pragma unroll
            for (int c = 0; c < 4; c++) acc2[mi][ni][c] = 0.f;

#pragma unroll 1
    for (int cc2 = 0; cc2 < 4; ++cc2) {
        const int buf = cc2 & 1;
        __syncthreads();   // previous chunk's (or stage-1's) reads complete
        if (warp_n == cc2) {
            // this warp owns Y1 cols [cc2*32, cc2*32+32): bias+relu, stage as half
#pragma unroll
            for (int mi = 0; mi < 2; mi++)
#pragma unroll
                for (int ni = 0; ni < NT; ni++) {
                    int cl = ni * 8 + 2 * qid;
                    float2 bv = *(const float2*)(p.bias + warp_n * 32 + cl);
                    float v0 = fmaxf(acc[mi][ni][0] + bv.x, 0.f);
                    float v1 = fmaxf(acc[mi][ni][1] + bv.y, 0.f);
                    float v2 = fmaxf(acc[mi][ni][2] + bv.x, 0.f);
                    float v3 = fmaxf(acc[mi][ni][3] + bv.y, 0.f);
                    __half2 h0 = __floats2half2_rn(v0, v1);
                    __half2 h1 = __floats2half2_rn(v2, v3);
                    int r = warp_m * 32 + mi * 16 + grp;
                    *(__half2*)&As[buf][r][cl] = h0;
                    *(__half2*)&As[buf][r + 8][cl] = h1;
                }
        }
        {   // stage W3 chunk: [64][32]
            int wn2 = t >> 3;
            int wk2 = (t & 7) * 4;
            *(uint2*)&Ws[buf][wn2][wk2] =
                *(const uint2*)(p.W3 + (size_t)wn2 * 128 + cc2 * 32 + wk2);
        }
        __syncthreads();
#pragma unroll
        for (int ks = 0; ks < KC; ks += 16) {
            unsigned af2[2][4];
#pragma unroll
            for (int mi = 0; mi < 2; mi++) {
                int r = warp_m * 32 + mi * 16;
                LDSM_X4(af2[mi][0], af2[mi][1], af2[mi][2], af2[mi][3],
                        smem_u32(&As[buf][r + lm_r][ks + lm_c]));
            }
            unsigned bf2[4];
            LDSM_X4(bf2[0], bf2[1], bf2[2], bf2[3],
                    smem_u32(&Ws[buf][warp_n * 16 + lm_r][ks + lm_c]));
#pragma unroll
            for (int half = 0; half < 2; half++) {
                MMA_F16(acc2[0][half], af2[0], bf2[half], bf2[half + 2]);
                MMA_F16(acc2[1][half], af2[1], bf2[half], bf2[half + 2]);
            }
        }
    }

    // epilogue: Y2 [M][64]
#pragma unroll
    for (int ni = 0; ni < 2; ni++) {
        int cb = warp_n * 16 + ni * 8 + 2 * qid;
        float2 bv = *(const float2*)(p.bias3 + cb);
#pragma unroll
        for (int mi = 0; mi < 2; mi++) {
            int r0 = row0 + warp_m * 32 + mi * 16 + grp;
            __half2 h0 = __floats2half2_rn(acc2[mi][ni][0] + bv.x, acc2[mi][ni][1] + bv.y);
            __half2 h1 = __floats2half2_rn(acc2[mi][ni][2] + bv.x, acc2[mi][ni][3] + bv.y);
            if (r0 < M)     *(__half2*)(p.Y2 + (size_t)r0 * 64 + cb) = h0;
            if (r0 + 8 < M) *(__half2*)(p.Y2 + (size_t)(r0 + 8) * 64 + cb) = h1;
        }
    }
}

// ---------------- fused edge decoder (fp16 mma + ldmatrix, KC=32) ---------------
__global__ __launch_bounds__(512, 2)
void dec_h(int M, const __half* __restrict__ zod, const __half* __restrict__ zdt,
           const int* __restrict__ esrc, const int* __restrict__ edst,
           const __half* __restrict__ Wt, const float* __restrict__ b1,
           const float* __restrict__ w2, const float* __restrict__ b2p,
           float* __restrict__ out) {
    constexpr int NC = 64;
    constexpr int BR = 128;
    constexpr int K = 128;
    constexpr int KC = 32;
    constexpr int AST = 40;
    constexpr int NCW = 16;
    constexpr int NT = 2;
    constexpr int NCH = K / KC;
    __shared__ __half As[2][BR][AST];
    __shared__ __half Ws[2][NC][AST];
    __shared__ float Red[BR][17];

    const int t = threadIdx.x;
    const int lane = t & 31;
    const int wid = t >> 5;
    const int warp_m = wid >> 2;
    const int warp_n = wid & 3;
    const int grp = lane >> 2;
    const int qid = lane & 3;
    const int row0 = blockIdx.x * BR;
    const int lr = t >> 2;
    const int lk = (t & 3) * 8;
    const int grow = row0 + lr;
    const int wn = t >> 3;
    const int wk = (t & 7) * 4;
    const int lm_r = (lane & 7) + ((lane >> 3) & 1) * 8;
    const int lm_c = ((lane >> 4) & 1) * 8;

    int si = 0, di = 0;
    if (grow < M) { si = __ldg(esrc + grow); di = __ldg(edst + grow); }

    uint4 pa = make_uint4(0, 0, 0, 0);
    uint2 pwv = make_uint2(0, 0);

    auto loadX = [&](int cc) {
        pa = make_uint4(0, 0, 0, 0);
        if (grow < M) {
            int k = cc * KC + lk;
            const __half* base = (k < 64) ? (zod + (size_t)si * 64 + k)
                                          : (zdt + (size_t)di * 64 + (k - 64));
            pa = *(const uint4*)base;
        }
    };
    auto loadW = [&](int cc) {
        pwv = *(const uint2*)(Wt + (size_t)wn * K + cc * KC + wk);
    };
    auto stage = [&](int buf) {
        *(uint4*)&As[buf][lr][lk] = pa;
        *(uint2*)&Ws[buf][wn][wk] = pwv;
    };

    float acc[2][NT][4];
#pragma unroll
    for (int mi = 0; mi < 2; mi++)
#pragma unroll
        for (int ni = 0; ni < NT; ni++)
#pragma unroll
            for (int c = 0; c < 4; c++) acc[mi][ni][c] = 0.f;

    loadX(0); loadW(0); stage(0);

#pragma unroll 1
    for (int cc = 0; cc < NCH; ++cc) {
        const int buf = cc & 1;
        __syncthreads();
        if (cc + 1 < NCH) { loadX(cc + 1); loadW(cc + 1); }
#pragma unroll
        for (int ks = 0; ks < KC; ks += 16) {
            unsigned af[2][4];
#pragma unroll
            for (int mi = 0; mi < 2; mi++) {
                int r = warp_m * 32 + mi * 16;
                LDSM_X4(af[mi][0], af[mi][1], af[mi][2], af[mi][3],
                        smem_u32(&As[buf][r + lm_r][ks + lm_c]));
            }
            unsigned bf[4];
            {
                int c = warp_n * NCW;
                LDSM_X4(bf[0], bf[1], bf[2], bf[3],
                        smem_u32(&Ws[buf][c + lm_r][ks + lm_c]));
            }
#pragma unroll
            for (int half = 0; half < 2; half++) {
                unsigned b0 = bf[half];
                unsigned b1 = bf[half + 2];
                MMA_F16(acc[0][half], af[0], b0, b1);
                MMA_F16(acc[1][half], af[1], b0, b1);
            }
        }
        if (cc + 1 < NCH) stage(buf ^ 1);
    }

    float p[2][2] = {{0.f, 0.f}, {0.f, 0.f}};
#pragma unroll
    for (int ni = 0; ni < NT; ni++) {
        int cb = warp_n * NCW + ni * 8 + 2 * qid;
        float2 bv = *(const float2*)(b1 + cb);
        float2 wv = *(const float2*)(w2 + cb);
#pragma unroll
        for (int mi = 0; mi < 2; mi++) {
            p[mi][0] += fmaxf(acc[mi][ni][0] + bv.x, 0.f) * wv.x
                      + fmaxf(acc[mi][ni][1] + bv.y, 0.f) * wv.y;
            p[mi][1] += fmaxf(acc[mi][ni][2] + bv.x, 0.f) * wv.x
                      + fmaxf(acc[mi][ni][3] + bv.y, 0.f) * wv.y;
        }
    }
    __syncthreads();
#pragma unroll
    for (int mi = 0; mi < 2; mi++) {
        Red[warp_m * 32 + mi * 16 + grp    ][warp_n * 4 + qid] = p[mi][0];
        Red[warp_m * 32 + mi * 16 + grp + 8][warp_n * 4 + qid] = p[mi][1];
    }
    __syncthreads();
    if (t < BR) {
        int r = row0 + t;
        if (r < M) {
            float s = 0.f;
#pragma unroll
            for (int j = 0; j < 16; j++) s += Red[t][j];
            out[r] = 1.f / (1.f + expf(-(s + b2p[0])));
        }
    }
}

// ---------------- host orchestration --------------------------------------------
extern "C" void kernel_launch(void* const* d_in, const int* in_sizes, int n_in,
                              void* d_out, int out_size) {
    const float* x_dt   = (const float*)d_in[0];
    const float* x_od   = (const float*)d_in[1];
    const int*   ei_dt  = (const int*)  d_in[2];
    const int*   rsrc   = (const int*)  d_in[3];
    const int*   rdst   = (const int*)  d_in[4];
    const int*   elsrc  = (const int*)  d_in[5];
    const int*   eldst  = (const int*)  d_in[6];
    const float* od1_wl = (const float*)d_in[7];
    const float* od1_wr = (const float*)d_in[8];
    const float* od1_b  = (const float*)d_in[9];
    const float* od2_wl = (const float*)d_in[10];
    const float* od2_wr = (const float*)d_in[11];
    const float* od2_b  = (const float*)d_in[12];
    const float* od3_wl = (const float*)d_in[13];
    const float* od3_wr = (const float*)d_in[14];
    const float* od3_b  = (const float*)d_in[15];
    const float* od_lw  = (const float*)d_in[16];
    const float* od_lb  = (const float*)d_in[17];
    const float* dt1_wl = (const float*)d_in[18];
    const float* dt1_wr = (const float*)d_in[19];
    const float* dt1_b  = (const float*)d_in[20];
    const float* dt2_wl = (const float*)d_in[21];
    const float* dt2_wr = (const float*)d_in[22];
    const float* dt2_b  = (const float*)d_in[23];
    const float* dt_lw  = (const float*)d_in[24];
    const float* dt_lb  = (const float*)d_in[25];
    const float* dec_w1 = (const float*)d_in[26];
    const float* dec_b1 = (const float*)d_in[27];
    const float* dec_w2 = (const float*)d_in[28];
    const float* dec_b2 = (const float*)d_in[29];
    float* out = (float*)d_out;

    const int E1 = in_sizes[2] / 2;
    const int E2 = in_sizes[3];
    const int EL = in_sizes[5];
    const int* r1 = ei_dt;
    const int* c1 = ei_dt + E1;

    __half *xdth, *xodh, *acc1, *acc2, *acc3, *h, *d1, *od2b, *zodh, *zdth, *wh;
    int *deg1, *rp1, *fill1, *es1, *deg2, *rp2, *fill2, *es2, *part1, *part2, *scnt;
    cudaGetSymbolAddress((void**)&xdth, g_xdth);
    cudaGetSymbolAddress((void**)&xodh, g_xodh);
    cudaGetSymbolAddress((void**)&acc1, g_acc1);
    cudaGetSymbolAddress((void**)&acc2, g_acc2);
    cudaGetSymbolAddress((void**)&acc3, g_acc3);
    cudaGetSymbolAddress((void**)&h,   g_h);
    cudaGetSymbolAddress((void**)&d1,  g_d1);
    cudaGetSymbolAddress((void**)&od2b, g_od2);
    cudaGetSymbolAddress((void**)&zodh, g_zodh);
    cudaGetSymbolAddress((void**)&zdth, g_zdth);
    cudaGetSymbolAddress((void**)&wh,  g_wh);
    cudaGetSymbolAddress((void**)&deg1, g_deg1);
    cudaGetSymbolAddress((void**)&rp1, g_rp1);
    cudaGetSymbolAddress((void**)&fill1, g_fill1);
    cudaGetSymbolAddress((void**)&es1, g_es1);
    cudaGetSymbolAddress((void**)&deg2, g_deg2);
    cudaGetSymbolAddress((void**)&rp2, g_rp2);
    cudaGetSymbolAddress((void**)&fill2, g_fill2);
    cudaGetSymbolAddress((void**)&es2, g_es2);
    cudaGetSymbolAddress((void**)&part1, g_part1);
    cudaGetSymbolAddress((void**)&part2, g_part2);
    cudaGetSymbolAddress((void**)&scnt, g_scan_cnt);

    const int TB = 256;
    const int tiles1 = cdiv(NDT, TILE);
    const int tiles2 = cdiv(NOD, TILE);

    // ---- prep: weights transpose/convert; inputs convert + zero deg/cnt ----
    WTList L;
    const float* ws[13] = {od1_wl, od1_wr, dt1_wl, dt1_wr, od2_wl, od2_wr,
                           od3_wl, od3_wr, od_lw, dt2_wl, dt2_wr, dt_lw, dec_w1};
    int Ks[13] = {128, 128, 128, 128, 128, 64, 128, 128, 128, 128, 128, 128, 128};
    int Ns[13] = {128, 128, 128, 128, 128, 128, 128, 128, 64, 128, 128, 64, 64};
    for (int i = 0; i < 13; i++) { L.src[i] = ws[i]; L.K[i] = Ks[i]; L.N[i] = Ns[i]; }
    k_wt<<<dim3(8, 13), 256>>>(L, wh);
    k_cvt<<<cdiv(NDT * 32 + NOD * 16 + NDT / 4 + NOD / 4 + 1, TB), TB>>>(
        x_dt, xdth, x_od, xodh, deg1, deg2, scnt);
#define WT(i) (wh + (size_t)(i) * WSLOT)

    // ---- CSR build ----
    k_degree2<<<cdiv(E1 + E2, TB), TB>>>(c1, E1, deg1, rdst, E2, deg2);
    k_scan<<<tiles1 + tiles2, TB>>>(deg1, NDT, rp1, fill1, part1, tiles1,
                                    deg2, NOD, rp2, fill2, part2, tiles2, scnt);
    k_reorder2<<<cdiv(E1 + E2, TB), TB>>>(r1, c1, E1, rp1, fill1, es1,
                                          rsrc, rdst, E2, rp2, fill2, es2);

    // ---- pipeline ----
    k_aggh2<<<cdiv((long long)NDT * 32, TB), TB>>>(
        xdth, es1, rp1, acc1, NDT, nullptr, nullptr, nullptr, nullptr, 0);

    GemmProb ph  = {acc1, 128, xdth, 128, WT(0), WT(1), od1_b, h,  NDT, 1};
    GemmProb pd1 = {acc1, 128, xdth, 128, WT(2), WT(3), dt1_b, d1, NDT, 1};
    gemm_h<128, 128><<<dim3(cdiv(NDT, 128), 2), 512>>>(ph, pd1);

    k_aggh2<<<cdiv((long long)(NOD + NDT) * 32, TB), TB>>>(
        h, es2, rp2, acc2, NOD, d1, es1, rp1, acc3, NDT);

    // od2 = relu(acc2@od2_wl + xod@od2_wr + b)  (NOD only, BR=64)
    GemmProb pod2 = {acc2, 128, xodh, 64, WT(4), WT(5), od2_b, od2b, NOD, 1};
    gemm_h<128, 64><<<dim3(cdiv(NOD, 64), 1), 512>>>(pod2, pod2);

    // chained: zod = relu(acc2@od3_wl + od2b@od3_wr + b3)@od_lw + od_lb
    //          zdt = relu(acc3@dt2_wl + d1@dt2_wr + b2)@dt_lw + dt_lb
    ChainProb cod = {acc2, 128, od2b, 128, WT(6), WT(7), od3_b, WT(8), od_lb, zodh, NOD};
    ChainProb cdt = {acc3, 128, d1, 128, WT(9), WT(10), dt2_b, WT(11), dt_lb, zdth, NDT};
    chain_h<<<dim3(cdiv(NDT, 128), 2), 512>>>(cdt, cod);

    dec_h<<<cdiv(EL, 128), 512>>>(EL, zodh, zdth, elsrc, eldst,
                                  WT(12), dec_b1, dec_w2, dec_b2, out);
}

// round 12
// speedup vs baseline: 4.5420x; 1.0360x over previous
#include <cuda_runtime.h>
#include <cuda_fp16.h>
#include <math.h>

#define NDT 30000
#define NOD 10000
#define WSLOT 16384
#define TILE 1024

static inline int cdiv(long long a, long long b) { return (int)((a + b - 1) / b); }

// ---------------- fp16 mma / ldmatrix helpers -----------------------------------
#define MMA_F16(d, a, b0, b1)                                              \
    asm volatile("mma.sync.aligned.m16n8k16.row.col.f32.f16.f16.f32 "      \
                 "{%0,%1,%2,%3}, {%4,%5,%6,%7}, {%8,%9}, {%0,%1,%2,%3};"   \
                 : "+f"((d)[0]), "+f"((d)[1]), "+f"((d)[2]), "+f"((d)[3])  \
                 : "r"((a)[0]), "r"((a)[1]), "r"((a)[2]), "r"((a)[3]),     \
                   "r"(b0), "r"(b1))

#define LDSM_X4(r0, r1, r2, r3, addr)                                      \
    asm volatile("ldmatrix.sync.aligned.m8n8.x4.shared.b16 "               \
                 "{%0,%1,%2,%3}, [%4];"                                    \
                 : "=r"(r0), "=r"(r1), "=r"(r2), "=r"(r3) : "r"(addr))

__device__ __forceinline__ unsigned smem_u32(const void* p) {
    return (unsigned)__cvta_generic_to_shared(p);
}

// ---------------- device scratch ------------------------------------------------
__device__ __half g_xdth[NDT * 128];
__device__ __half g_xodh[NOD * 64];
__device__ __half g_acc1[NDT * 128];
__device__ __half g_acc2[NOD * 128];
__device__ __half g_acc3[NDT * 128];
__device__ __half g_h [NDT * 128];
__device__ __half g_d1[NDT * 128];
__device__ __half g_od2[NOD * 128];
__device__ __half g_zodh[NOD * 64];
__device__ __half g_zdth[NDT * 64];
__device__ __half g_wh[13 * WSLOT];
// CSR scratch
__device__ int g_deg1[NDT];
__device__ int g_rp1[NDT + 1];
__device__ int g_fill1[NDT];
__device__ int g_es1[500000];
__device__ int g_deg2[NOD];
__device__ int g_rp2[NOD + 1];
__device__ int g_fill2[NOD];
__device__ int g_es2[300000];
__device__ int g_part1[64];
__device__ int g_part2[64];
__device__ int g_scan_cnt;

// ---------------- fused prep: weight transpose + input convert + zeroing --------
struct WTList {
    const float* src[13];
    int K[13];
    int N[13];
};
__global__ void k_prep(WTList L, __half* __restrict__ wdst, int wt_tot,
                       const float* __restrict__ x_dt, __half* __restrict__ xdh,
                       const float* __restrict__ x_od, __half* __restrict__ xoh,
                       int* __restrict__ deg1, int* __restrict__ deg2,
                       int* __restrict__ cnt) {
    int i = blockIdx.x * blockDim.x + threadIdx.x;
    if (i < wt_tot) {
        int s = 0, off = i;
        while (off >= L.K[s] * L.N[s]) { off -= L.K[s] * L.N[s]; s++; }
        int K = L.K[s];
        int n = off / K, k = off - n * K;
        wdst[(size_t)s * WSLOT + off] = __float2half(L.src[s][k * L.N[s] + n]);
        return;
    }
    i -= wt_tot;
    const int n1 = NDT * 128 / 4, n2 = NOD * 64 / 4;
    const int z1 = NDT / 4, z2 = NOD / 4;
    if (i < n1) {
        float4 v = *(const float4*)(x_dt + i * 4);
        __half2 h0 = __floats2half2_rn(v.x, v.y);
        __half2 h1 = __floats2half2_rn(v.z, v.w);
        *(uint2*)(xdh + i * 4) = make_uint2(*(unsigned*)&h0, *(unsigned*)&h1);
    } else if (i < n1 + n2) {
        int j = i - n1;
        float4 v = *(const float4*)(x_od + j * 4);
        __half2 h0 = __floats2half2_rn(v.x, v.y);
        __half2 h1 = __floats2half2_rn(v.z, v.w);
        *(uint2*)(xoh + j * 4) = make_uint2(*(unsigned*)&h0, *(unsigned*)&h1);
    } else if (i < n1 + n2 + z1) {
        ((int4*)deg1)[i - (n1 + n2)] = make_int4(0, 0, 0, 0);
    } else if (i < n1 + n2 + z1 + z2) {
        ((int4*)deg2)[i - (n1 + n2 + z1)] = make_int4(0, 0, 0, 0);
    } else if (i == n1 + n2 + z1 + z2) {
        *cnt = 0;
    }
}

// ---------------- CSR build ------------------------------------------------------
__global__ void k_degree2(const int* __restrict__ c1, int E1, int* __restrict__ deg1,
                          const int* __restrict__ rdst, int E2, int* __restrict__ deg2) {
    int i = blockIdx.x * blockDim.x + threadIdx.x;
    if (i < E1) atomicAdd(deg1 + __ldg(c1 + i), 1);
    else if (i < E1 + E2) atomicAdd(deg2 + __ldg(rdst + (i - E1)), 1);
}

// fused two-phase scan with device-wide spin barrier (40 blocks, all resident)
__global__ void k_scan(const int* __restrict__ deg1, int n1, int* __restrict__ rp1,
                       int* __restrict__ fill1, int* __restrict__ part1, int tiles1,
                       const int* __restrict__ deg2, int n2, int* __restrict__ rp2,
                       int* __restrict__ fill2, int* __restrict__ part2, int tiles2,
                       int* __restrict__ cnt) {
    int b = blockIdx.x;
    const int* deg; int n; int* rp; int* fill; int* part; int tt, tiles;
    if (b < tiles1) { deg = deg1; n = n1; rp = rp1; fill = fill1; part = part1; tt = b; tiles = tiles1; }
    else { deg = deg2; n = n2; rp = rp2; fill = fill2; part = part2; tt = b - tiles1; tiles = tiles2; }
    __shared__ int wsum[8];
    __shared__ int s_off;
    int t = threadIdx.x, lane = t & 31, w = t >> 5;
    int base = tt * TILE + t * 4;
    int d[4]; int tot = 0;
#pragma unroll
    for (int j = 0; j < 4; j++) { d[j] = (base + j < n) ? deg[base + j] : 0; tot += d[j]; }
    int inc = tot;
#pragma unroll
    for (int o = 1; o < 32; o <<= 1) {
        int u = __shfl_up_sync(0xffffffffu, inc, o);
        if (lane >= o) inc += u;
    }
    if (lane == 31) wsum[w] = inc;
    __syncthreads();
    if (t == 0) {
        int s = 0;
#pragma unroll
        for (int j = 0; j < 8; j++) s += wsum[j];
        part[tt] = s;
        __threadfence();
        atomicAdd(cnt, 1);
        while (atomicAdd(cnt, 0) < tiles1 + tiles2) {}
        __threadfence();
    }
    __syncthreads();
    if (t < 32) {
        int v = (t < tt) ? atomicAdd(part + t, 0) : 0;
#pragma unroll
        for (int o = 16; o; o >>= 1) v += __shfl_xor_sync(0xffffffffu, v, o);
        if (t == 0) s_off = v;
    }
    __syncthreads();
    int woff = 0;
#pragma unroll
    for (int j = 0; j < 8; j++) if (j < w) woff += wsum[j];
    int run = s_off + woff + inc - tot;
#pragma unroll
    for (int j = 0; j < 4; j++) {
        if (base + j < n) { rp[base + j] = run; fill[base + j] = 0; run += d[j]; }
    }
    if (tt == tiles - 1 && t == blockDim.x - 1) rp[n] = run;
}

__global__ void k_reorder2(const int* __restrict__ s1, const int* __restrict__ t1, int E1,
                           const int* __restrict__ rp1, int* __restrict__ f1,
                           int* __restrict__ e1,
                           const int* __restrict__ s2, const int* __restrict__ t2, int E2,
                           const int* __restrict__ rp2, int* __restrict__ f2,
                           int* __restrict__ e2) {
    int i = blockIdx.x * blockDim.x + threadIdx.x;
    if (i < E1) {
        int d = __ldg(t1 + i);
        int pos = atomicAdd(f1 + d, 1);
        e1[rp1[d] + pos] = __ldg(s1 + i);
    } else if (i < E1 + E2) {
        int j = i - E1;
        int d = __ldg(t2 + j);
        int pos = atomicAdd(f2 + d, 1);
        e2[rp2[d] + pos] = __ldg(s2 + j);
    }
}

// ---------------- mean aggregation: warp per dst, 4 edges in flight -------------
__global__ __launch_bounds__(256)
void k_aggh2(const __half* __restrict__ X1, const int* __restrict__ es1,
             const int* __restrict__ rp1, __half* __restrict__ acc1, int n1,
             const __half* __restrict__ X2, const int* __restrict__ es2,
             const int* __restrict__ rp2, __half* __restrict__ acc2, int n2) {
    int w = (blockIdx.x * blockDim.x + threadIdx.x) >> 5;
    const __half* X; const int* es; const int* rowptr; __half* acc;
    if (w < n1) { X = X1; es = es1; rowptr = rp1; acc = acc1; }
    else if (w < n1 + n2) { X = X2; es = es2; rowptr = rp2; acc = acc2; w -= n1; }
    else return;
    int lane = threadIdx.x & 31;
    int grp4 = lane >> 3;
    int sub = lane & 7;
    int beg = __ldg(rowptr + w);
    int end = __ldg(rowptr + w + 1);
    float s[16];
#pragma unroll
    for (int k = 0; k < 16; k++) s[k] = 0.f;
    for (int base = beg; base < end; base += 32) {
        int p = 0;
        if (base + lane < end) p = __ldg(es + base + lane);
        int cnt = min(32, end - base);
        for (int j = 0; j < cnt; j += 4) {
            int e = j + grp4;
            int sr = __shfl_sync(0xffffffffu, p, e);
            if (e < cnt) {
                const uint4* row = (const uint4*)(X + (size_t)sr * 128 + sub * 16);
                uint4 v0 = __ldg(row);
                uint4 v1 = __ldg(row + 1);
                unsigned vv[8] = {v0.x, v0.y, v0.z, v0.w, v1.x, v1.y, v1.z, v1.w};
#pragma unroll
                for (int k = 0; k < 8; k++) {
                    float2 f = __half22float2(*(__half2*)&vv[k]);
                    s[2 * k] += f.x;
                    s[2 * k + 1] += f.y;
                }
            }
        }
    }
#pragma unroll
    for (int k = 0; k < 16; k++) {
        s[k] += __shfl_xor_sync(0xffffffffu, s[k], 8);
        s[k] += __shfl_xor_sync(0xffffffffu, s[k], 16);
    }
    if (grp4 == 0) {
        float inv = 1.f / fmaxf((float)(end - beg), 1.f);
        unsigned o[8];
#pragma unroll
        for (int k = 0; k < 8; k++) {
            __half2 hv = __floats2half2_rn(s[2 * k] * inv, s[2 * k + 1] * inv);
            o[k] = *(unsigned*)&hv;
        }
        uint4* dst = (uint4*)(acc + (size_t)w * 128 + sub * 16);
        dst[0] = make_uint4(o[0], o[1], o[2], o[3]);
        dst[1] = make_uint4(o[4], o[5], o[6], o[7]);
    }
}

// ---------------- generic 2-problem fp16 GEMM (256 thr, 2m x 4n warps) ----------
struct GemmProb {
    const __half* A; int K1;
    const __half* B; int K2;
    const __half* W1; const __half* W2;   // pre-transposed [N][K] f16
    const float* bias;
    __half* Y;
    int M;
    int relu;
};

template <int NCOLS, int BR>
__global__ __launch_bounds__(256, 2)
void gemm_h(GemmProb p0, GemmProb p1) {
    constexpr int KC = 32;
    constexpr int AST = 40;
    constexpr int MI = BR / 32;          // 4 (BR=128) or 2 (BR=64)
    constexpr int NCW = NCOLS / 4;
    constexpr int NT = NCW / 8;          // 4 or 2
    constexpr int NG = (NT + 1) / 2;     // 2 or 1
    constexpr int APT = BR * KC / 256;   // halves/thread: 16 or 8
    constexpr int WPT = NCOLS * KC / 256;
    const GemmProb& p = blockIdx.y ? p1 : p0;
    const int row0 = blockIdx.x * BR;
    if (row0 >= p.M) return;

    __shared__ __half As[2][BR][AST];
    __shared__ __half Ws[2][NCOLS][AST];

    const int M = p.M;
    const int K1 = p.K1, K2 = p.K2;
    const __half* A = p.A;
    const __half* B = p.B;

    const int t = threadIdx.x;
    const int lane = t & 31;
    const int wid = t >> 5;                 // 0..7
    const int warp_m = wid >> 2;            // 0..1
    const int warp_n = wid & 3;             // 0..3
    const int grp = lane >> 2;
    const int qid = lane & 3;
    const int lr = (BR == 128) ? (t >> 1) : (t >> 2);
    const int lk = (BR == 128) ? ((t & 1) * 16) : ((t & 3) * 8);
    const int grow = row0 + lr;
    const int wn = (NCOLS == 128) ? (t >> 1) : (t >> 2);
    const int wk = (NCOLS == 128) ? ((t & 1) * 16) : ((t & 3) * 8);
    const int lm_r = (lane & 7) + ((lane >> 3) & 1) * 8;
    const int lm_c = ((lane >> 4) & 1) * 8;

    const int n1 = K1 / KC;
    const int n2 = (B != nullptr) ? (K2 / KC) : 0;
    const int nch = n1 + n2;

    uint4 pa0 = make_uint4(0, 0, 0, 0), pa1 = make_uint4(0, 0, 0, 0);
    uint4 pw0 = make_uint4(0, 0, 0, 0), pw1 = make_uint4(0, 0, 0, 0);

    auto loadX = [&](int cc) {
        const __half* Xp; int stride, k0;
        if (cc < n1) { Xp = A; stride = K1; k0 = cc * KC; }
        else         { Xp = B; stride = K2; k0 = (cc - n1) * KC; }
        pa0 = make_uint4(0, 0, 0, 0); pa1 = pa0;
        if (grow < M) {
            const __half* base = Xp + (size_t)grow * stride + k0 + lk;
            pa0 = *(const uint4*)base;
            if (APT == 16) pa1 = *(const uint4*)(base + 8);
        }
    };
    auto loadW = [&](int cc) {
        const __half* Wp; int stride, k0;
        if (cc < n1) { Wp = p.W1; stride = K1; k0 = cc * KC; }
        else         { Wp = p.W2; stride = K2; k0 = (cc - n1) * KC; }
        const __half* base = Wp + (size_t)wn * stride + k0 + wk;
        pw0 = *(const uint4*)base;
        if (WPT == 16) pw1 = *(const uint4*)(base + 8);
    };
    auto stage = [&](int buf) {
        *(uint4*)&As[buf][lr][lk] = pa0;
        if (APT == 16) *(uint4*)&As[buf][lr][lk + 8] = pa1;
        *(uint4*)&Ws[buf][wn][wk] = pw0;
        if (WPT == 16) *(uint4*)&Ws[buf][wn][wk + 8] = pw1;
    };

    float acc[MI][NT][4];
#pragma unroll
    for (int mi = 0; mi < MI; mi++)
#pragma unroll
        for (int ni = 0; ni < NT; ni++)
#pragma unroll
            for (int c = 0; c < 4; c++) acc[mi][ni][c] = 0.f;

    loadX(0); loadW(0); stage(0);

    for (int cc = 0; cc < nch; ++cc) {
        const int buf = cc & 1;
        __syncthreads();
        if (cc + 1 < nch) { loadX(cc + 1); loadW(cc + 1); }
#pragma unroll
        for (int ks = 0; ks < KC; ks += 16) {
            unsigned bf[NG][4];
#pragma unroll
            for (int g = 0; g < NG; g++) {
                int c = warp_n * NCW + g * 16;
                LDSM_X4(bf[g][0], bf[g][1], bf[g][2], bf[g][3],
                        smem_u32(&Ws[buf][c + lm_r][ks + lm_c]));
            }
#pragma unroll
            for (int mi = 0; mi < MI; mi++) {
                unsigned af[4];
                int r = warp_m * (16 * MI) + mi * 16;
                LDSM_X4(af[0], af[1], af[2], af[3],
                        smem_u32(&As[buf][r + lm_r][ks + lm_c]));
#pragma unroll
                for (int g = 0; g < NG; g++) {
#pragma unroll
                    for (int half = 0; half < 2; half++) {
                        int ni = g * 2 + half;
                        if (ni < NT)
                            MMA_F16(acc[mi][ni], af, bf[g][half], bf[g][half + 2]);
                    }
                }
            }
        }
        if (cc + 1 < nch) stage(buf ^ 1);
    }

#pragma unroll
    for (int ni = 0; ni < NT; ni++) {
        int cb = warp_n * NCW + ni * 8 + 2 * qid;
        float2 bv = make_float2(0.f, 0.f);
        if (p.bias != nullptr) bv = *(const float2*)(p.bias + cb);
#pragma unroll
        for (int mi = 0; mi < MI; mi++) {
            int r0 = row0 + warp_m * (16 * MI) + mi * 16 + grp;
            float v0 = acc[mi][ni][0] + bv.x;
            float v1 = acc[mi][ni][1] + bv.y;
            float v2 = acc[mi][ni][2] + bv.x;
            float v3 = acc[mi][ni][3] + bv.y;
            if (p.relu) {
                v0 = fmaxf(v0, 0.f); v1 = fmaxf(v1, 0.f);
                v2 = fmaxf(v2, 0.f); v3 = fmaxf(v3, 0.f);
            }
            __half2 h0 = __floats2half2_rn(v0, v1);
            __half2 h1 = __floats2half2_rn(v2, v3);
            if (r0 < M)     *(__half2*)(p.Y + (size_t)r0 * NCOLS + cb) = h0;
            if (r0 + 8 < M) *(__half2*)(p.Y + (size_t)(r0 + 8) * NCOLS + cb) = h1;
        }
    }
}

// ---------------- chained GEMM: Y2 = (relu(A@W1 + B@W2 + b)) @ W3 + b3 ----------
struct ChainProb {
    const __half* A; int K1;
    const __half* B; int K2;
    const __half* W1; const __half* W2;   // [128][K]
    const float* bias;                    // stage-1 bias (relu)
    const __half* W3;                     // [64][128]
    const float* bias3;                   // [64]
    __half* Y2;                           // [M][64]
    int M;
};

__global__ __launch_bounds__(512, 1)
void chain_h(ChainProb p0, ChainProb p1) {
    constexpr int KC = 32;
    constexpr int AST = 40;
    constexpr int BR = 128;
    constexpr int NCOLS = 128;
    constexpr int NCW = 32;
    constexpr int NT = 4;
    constexpr int NG = 2;
    const ChainProb& p = blockIdx.y ? p1 : p0;
    const int row0 = blockIdx.x * BR;
    if (row0 >= p.M) return;

    __shared__ __half As[2][BR][AST];
    __shared__ __half Ws[2][NCOLS][AST];

    const int M = p.M;
    const int K1 = p.K1, K2 = p.K2;

    const int t = threadIdx.x;
    const int lane = t & 31;
    const int wid = t >> 5;
    const int warp_m = wid >> 2;
    const int warp_n = wid & 3;
    const int grp = lane >> 2;
    const int qid = lane & 3;
    const int lr = t >> 2;
    const int lk = (t & 3) * 8;
    const int grow = row0 + lr;
    const int wn = t >> 2;
    const int wk = (t & 3) * 8;
    const int lm_r = (lane & 7) + ((lane >> 3) & 1) * 8;
    const int lm_c = ((lane >> 4) & 1) * 8;

    const int n1 = K1 / KC;
    const int n2 = K2 / KC;
    const int nch = n1 + n2;

    uint4 pa = make_uint4(0, 0, 0, 0), pw = make_uint4(0, 0, 0, 0);

    auto loadX = [&](int cc) {
        const __half* Xp; int stride, k0;
        if (cc < n1) { Xp = p.A; stride = K1; k0 = cc * KC; }
        else         { Xp = p.B; stride = K2; k0 = (cc - n1) * KC; }
        pa = make_uint4(0, 0, 0, 0);
        if (grow < M) pa = *(const uint4*)(Xp + (size_t)grow * stride + k0 + lk);
    };
    auto loadW = [&](int cc) {
        const __half* Wp; int stride, k0;
        if (cc < n1) { Wp = p.W1; stride = K1; k0 = cc * KC; }
        else         { Wp = p.W2; stride = K2; k0 = (cc - n1) * KC; }
        pw = *(const uint4*)(Wp + (size_t)wn * stride + k0 + wk);
    };
    auto stage = [&](int buf) {
        *(uint4*)&As[buf][lr][lk] = pa;
        *(uint4*)&Ws[buf][wn][wk] = pw;
    };

    float acc[2][NT][4];
#pragma unroll
    for (int mi = 0; mi < 2; mi++)
#pragma unroll
        for (int ni = 0; ni < NT; ni++)
#pragma unroll
            for (int c = 0; c < 4; c++) acc[mi][ni][c] = 0.f;

    loadX(0); loadW(0); stage(0);

    for (int cc = 0; cc < nch; ++cc) {
        const int buf = cc & 1;
        __syncthreads();
        if (cc + 1 < nch) { loadX(cc + 1); loadW(cc + 1); }
#pragma unroll
        for (int ks = 0; ks < KC; ks += 16) {
            unsigned af[2][4];
#pragma unroll
            for (int mi = 0; mi < 2; mi++) {
                int r = warp_m * 32 + mi * 16;
                LDSM_X4(af[mi][0], af[mi][1], af[mi][2], af[mi][3],
                        smem_u32(&As[buf][r + lm_r][ks + lm_c]));
            }
            unsigned bf[NG][4];
#pragma unroll
            for (int g = 0; g < NG; g++) {
                int c = warp_n * NCW + g * 16;
                LDSM_X4(bf[g][0], bf[g][1], bf[g][2], bf[g][3],
                        smem_u32(&Ws[buf][c + lm_r][ks + lm_c]));
            }
#pragma unroll
            for (int g = 0; g < NG; g++) {
#pragma unroll
                for (int half = 0; half < 2; half++) {
#pragma unroll
                    for (int mi = 0; mi < 2; mi++)
                        MMA_F16(acc[mi][g * 2 + half], af[mi], bf[g][half], bf[g][half + 2]);
                }
            }
        }
        if (cc + 1 < nch) stage(buf ^ 1);
    }

    // ---- stage 2: z = relu(Y1) @ W3 + b3, 4 chunks of 32 K-cols ----
    float acc2[2][2][4];
#pragma unroll
    for (int mi = 0; mi < 2; mi++)
#pragma unroll
        for (int ni = 0; ni < 2; ni++)
#pragma unroll
            for (int c = 0; c < 4; c++) acc2[mi][ni][c] = 0.f;

#pragma unroll 1
    for (int cc2 = 0; cc2 < 4; ++cc2) {
        const int buf = cc2 & 1;
        __syncthreads();
        if (warp_n == cc2) {
#pragma unroll
            for (int mi = 0; mi < 2; mi++)
#pragma unroll
                for (int ni = 0; ni < NT; ni++) {
                    int cl = ni * 8 + 2 * qid;
                    float2 bv = *(const float2*)(p.bias + warp_n * 32 + cl);
                    float v0 = fmaxf(acc[mi][ni][0] + bv.x, 0.f);
                    float v1 = fmaxf(acc[mi][ni][1] + bv.y, 0.f);
                    float v2 = fmaxf(acc[mi][ni][2] + bv.x, 0.f);
                    float v3 = fmaxf(acc[mi][ni][3] + bv.y, 0.f);
                    __half2 h0 = __floats2half2_rn(v0, v1);
                    __half2 h1 = __floats2half2_rn(v2, v3);
                    int r = warp_m * 32 + mi * 16 + grp;
                    *(__half2*)&As[buf][r][cl] = h0;
                    *(__half2*)&As[buf][r + 8][cl] = h1;
                }
        }
        {
            int wn2 = t >> 3;
            int wk2 = (t & 7) * 4;
            *(uint2*)&Ws[buf][wn2][wk2] =
                *(const uint2*)(p.W3 + (size_t)wn2 * 128 + cc2 * 32 + wk2);
        }
        __syncthreads();
#pragma unroll
        for (int ks = 0; ks < KC; ks += 16) {
            unsigned af2[2][4];
#pragma unroll
            for (int mi = 0; mi < 2; mi++) {
                int r = warp_m * 32 + mi * 16;
                LDSM_X4(af2[mi][0], af2[mi][1], af2[mi][2], af2[mi][3],
                        smem_u32(&As[buf][r + lm_r][ks + lm_c]));
            }
            unsigned bf2[4];
            LDSM_X4(bf2[0], bf2[1], bf2[2], bf2[3],
                    smem_u32(&Ws[buf][warp_n * 16 + lm_r][ks + lm_c]));
#pragma unroll
            for (int half = 0; half < 2; half++) {
                MMA_F16(acc2[0][half], af2[0], bf2[half], bf2[half + 2]);
                MMA_F16(acc2[1][half], af2[1], bf2[half], bf2[half + 2]);
            }
        }
    }

#pragma unroll
    for (int ni = 0; ni < 2; ni++) {
        int cb = warp_n * 16 + ni * 8 + 2 * qid;
        float2 bv = *(const float2*)(p.bias3 + cb);
#pragma unroll
        for (int mi = 0; mi < 2; mi++) {
            int r0 = row0 + warp_m * 32 + mi * 16 + grp;
            __half2 h0 = __floats2half2_rn(acc2[mi][ni][0] + bv.x, acc2[mi][ni][1] + bv.y);
            __half2 h1 = __floats2half2_rn(acc2[mi][ni][2] + bv.x, acc2[mi][ni][3] + bv.y);
            if (r0 < M)     *(__half2*)(p.Y2 + (size_t)r0 * 64 + cb) = h0;
            if (r0 + 8 < M) *(__half2*)(p.Y2 + (size_t)(r0 + 8) * 64 + cb) = h1;
        }
    }
}

// ---------------- fused edge decoder (fp16 mma + ldmatrix, KC=32) ---------------
__global__ __launch_bounds__(512, 2)
void dec_h(int M, const __half* __restrict__ zod, const __half* __restrict__ zdt,
           const int* __restrict__ esrc, const int* __restrict__ edst,
           const __half* __restrict__ Wt, const float* __restrict__ b1,
           const float* __restrict__ w2, const float* __restrict__ b2p,
           float* __restrict__ out) {
    constexpr int NC = 64;
    constexpr int BR = 128;
    constexpr int K = 128;
    constexpr int KC = 32;
    constexpr int AST = 40;
    constexpr int NCW = 16;
    constexpr int NT = 2;
    constexpr int NCH = K / KC;
    __shared__ __half As[2][BR][AST];
    __shared__ __half Ws[2][NC][AST];
    __shared__ float Red[BR][17];

    const int t = threadIdx.x;
    const int lane = t & 31;
    const int wid = t >> 5;
    const int warp_m = wid >> 2;
    const int warp_n = wid & 3;
    const int grp = lane >> 2;
    const int qid = lane & 3;
    const int row0 = blockIdx.x * BR;
    const int lr = t >> 2;
    const int lk = (t & 3) * 8;
    const int grow = row0 + lr;
    const int wn = t >> 3;
    const int wk = (t & 7) * 4;
    const int lm_r = (lane & 7) + ((lane >> 3) & 1) * 8;
    const int lm_c = ((lane >> 4) & 1) * 8;

    int si = 0, di = 0;
    if (grow < M) { si = __ldg(esrc + grow); di = __ldg(edst + grow); }

    uint4 pa = make_uint4(0, 0, 0, 0);
    uint2 pwv = make_uint2(0, 0);

    auto loadX = [&](int cc) {
        pa = make_uint4(0, 0, 0, 0);
        if (grow < M) {
            int k = cc * KC + lk;
            const __half* base = (k < 64) ? (zod + (size_t)si * 64 + k)
                                          : (zdt + (size_t)di * 64 + (k - 64));
            pa = *(const uint4*)base;
        }
    };
    auto loadW = [&](int cc) {
        pwv = *(const uint2*)(Wt + (size_t)wn * K + cc * KC + wk);
    };
    auto stage = [&](int buf) {
        *(uint4*)&As[buf][lr][lk] = pa;
        *(uint2*)&Ws[buf][wn][wk] = pwv;
    };

    float acc[2][NT][4];
#pragma unroll
    for (int mi = 0; mi < 2; mi++)
#pragma unroll
        for (int ni = 0; ni < NT; ni++)
#pragma unroll
            for (int c = 0; c < 4; c++) acc[mi][ni][c] = 0.f;

    loadX(0); loadW(0); stage(0);

#pragma unroll 1
    for (int cc = 0; cc < NCH; ++cc) {
        const int buf = cc & 1;
        __syncthreads();
        if (cc + 1 < NCH) { loadX(cc + 1); loadW(cc + 1); }
#pragma unroll
        for (int ks = 0; ks < KC; ks += 16) {
            unsigned af[2][4];
#pragma unroll
            for (int mi = 0; mi < 2; mi++) {
                int r = warp_m * 32 + mi * 16;
                LDSM_X4(af[mi][0], af[mi][1], af[mi][2], af[mi][3],
                        smem_u32(&As[buf][r + lm_r][ks + lm_c]));
            }
            unsigned bf[4];
            {
                int c = warp_n * NCW;
                LDSM_X4(bf[0], bf[1], bf[2], bf[3],
                        smem_u32(&Ws[buf][c + lm_r][ks + lm_c]));
            }
#pragma unroll
            for (int half = 0; half < 2; half++) {
                unsigned b0 = bf[half];
                unsigned b1 = bf[half + 2];
                MMA_F16(acc[0][half], af[0], b0, b1);
                MMA_F16(acc[1][half], af[1], b0, b1);
            }
        }
        if (cc + 1 < NCH) stage(buf ^ 1);
    }

    float p[2][2] = {{0.f, 0.f}, {0.f, 0.f}};
#pragma unroll
    for (int ni = 0; ni < NT; ni++) {
        int cb = warp_n * NCW + ni * 8 + 2 * qid;
        float2 bv = *(const float2*)(b1 + cb);
        float2 wv = *(const float2*)(w2 + cb);
#pragma unroll
        for (int mi = 0; mi < 2; mi++) {
            p[mi][0] += fmaxf(acc[mi][ni][0] + bv.x, 0.f) * wv.x
                      + fmaxf(acc[mi][ni][1] + bv.y, 0.f) * wv.y;
            p[mi][1] += fmaxf(acc[mi][ni][2] + bv.x, 0.f) * wv.x
                      + fmaxf(acc[mi][ni][3] + bv.y, 0.f) * wv.y;
        }
    }
    __syncthreads();
#pragma unroll
    for (int mi = 0; mi < 2; mi++) {
        Red[warp_m * 32 + mi * 16 + grp    ][warp_n * 4 + qid] = p[mi][0];
        Red[warp_m * 32 + mi * 16 + grp + 8][warp_n * 4 + qid] = p[mi][1];
    }
    __syncthreads();
    if (t < BR) {
        int r = row0 + t;
        if (r < M) {
            float s = 0.f;
#pragma unroll
            for (int j = 0; j < 16; j++) s += Red[t][j];
            out[r] = 1.f / (1.f + expf(-(s + b2p[0])));
        }
    }
}

// ---------------- host orchestration --------------------------------------------
extern "C" void kernel_launch(void* const* d_in, const int* in_sizes, int n_in,
                              void* d_out, int out_size) {
    const float* x_dt   = (const float*)d_in[0];
    const float* x_od   = (const float*)d_in[1];
    const int*   ei_dt  = (const int*)  d_in[2];
    const int*   rsrc   = (const int*)  d_in[3];
    const int*   rdst   = (const int*)  d_in[4];
    const int*   elsrc  = (const int*)  d_in[5];
    const int*   eldst  = (const int*)  d_in[6];
    const float* od1_wl = (const float*)d_in[7];
    const float* od1_wr = (const float*)d_in[8];
    const float* od1_b  = (const float*)d_in[9];
    const float* od2_wl = (const float*)d_in[10];
    const float* od2_wr = (const float*)d_in[11];
    const float* od2_b  = (const float*)d_in[12];
    const float* od3_wl = (const float*)d_in[13];
    const float* od3_wr = (const float*)d_in[14];
    const float* od3_b  = (const float*)d_in[15];
    const float* od_lw  = (const float*)d_in[16];
    const float* od_lb  = (const float*)d_in[17];
    const float* dt1_wl = (const float*)d_in[18];
    const float* dt1_wr = (const float*)d_in[19];
    const float* dt1_b  = (const float*)d_in[20];
    const float* dt2_wl = (const float*)d_in[21];
    const float* dt2_wr = (const float*)d_in[22];
    const float* dt2_b  = (const float*)d_in[23];
    const float* dt_lw  = (const float*)d_in[24];
    const float* dt_lb  = (const float*)d_in[25];
    const float* dec_w1 = (const float*)d_in[26];
    const float* dec_b1 = (const float*)d_in[27];
    const float* dec_w2 = (const float*)d_in[28];
    const float* dec_b2 = (const float*)d_in[29];
    float* out = (float*)d_out;

    const int E1 = in_sizes[2] / 2;
    const int E2 = in_sizes[3];
    const int EL = in_sizes[5];
    const int* r1 = ei_dt;
    const int* c1 = ei_dt + E1;

    __half *xdth, *xodh, *acc1, *acc2, *acc3, *h, *d1, *od2b, *zodh, *zdth, *wh;
    int *deg1, *rp1, *fill1, *es1, *deg2, *rp2, *fill2, *es2, *part1, *part2, *scnt;
    cudaGetSymbolAddress((void**)&xdth, g_xdth);
    cudaGetSymbolAddress((void**)&xodh, g_xodh);
    cudaGetSymbolAddress((void**)&acc1, g_acc1);
    cudaGetSymbolAddress((void**)&acc2, g_acc2);
    cudaGetSymbolAddress((void**)&acc3, g_acc3);
    cudaGetSymbolAddress((void**)&h,   g_h);
    cudaGetSymbolAddress((void**)&d1,  g_d1);
    cudaGetSymbolAddress((void**)&od2b, g_od2);
    cudaGetSymbolAddress((void**)&zodh, g_zodh);
    cudaGetSymbolAddress((void**)&zdth, g_zdth);
    cudaGetSymbolAddress((void**)&wh,  g_wh);
    cudaGetSymbolAddress((void**)&deg1, g_deg1);
    cudaGetSymbolAddress((void**)&rp1, g_rp1);
    cudaGetSymbolAddress((void**)&fill1, g_fill1);
    cudaGetSymbolAddress((void**)&es1, g_es1);
    cudaGetSymbolAddress((void**)&deg2, g_deg2);
    cudaGetSymbolAddress((void**)&rp2, g_rp2);
    cudaGetSymbolAddress((void**)&fill2, g_fill2);
    cudaGetSymbolAddress((void**)&es2, g_es2);
    cudaGetSymbolAddress((void**)&part1, g_part1);
    cudaGetSymbolAddress((void**)&part2, g_part2);
    cudaGetSymbolAddress((void**)&scnt, g_scan_cnt);

    const int TB = 256;
    const int tiles1 = cdiv(NDT, TILE);
    const int tiles2 = cdiv(NOD, TILE);

    // ---- fused prep: weights transpose/convert + input convert + zeroing ----
    WTList L;
    const float* ws[13] = {od1_wl, od1_wr, dt1_wl, dt1_wr, od2_wl, od2_wr,
                           od3_wl, od3_wr, od_lw, dt2_wl, dt2_wr, dt_lw, dec_w1};
    int Ks[13] = {128, 128, 128, 128, 128, 64, 128, 128, 128, 128, 128, 128, 128};
    int Ns[13] = {128, 128, 128, 128, 128, 128, 128, 128, 64, 128, 128, 64, 64};
    int wt_tot = 0;
    for (int i = 0; i < 13; i++) {
        L.src[i] = ws[i]; L.K[i] = Ks[i]; L.N[i] = Ns[i];
        wt_tot += Ks[i] * Ns[i];
    }
    int prep_items = wt_tot + NDT * 32 + NOD * 16 + NDT / 4 + NOD / 4 + 1;
    k_prep<<<cdiv(prep_items, TB), TB>>>(L, wh, wt_tot, x_dt, xdth, x_od, xodh,
                                         deg1, deg2, scnt);
#define WT(i) (wh + (size_t)(i) * WSLOT)

    // ---- CSR build ----
    k_degree2<<<cdiv(E1 + E2, TB), TB>>>(c1, E1, deg1, rdst, E2, deg2);
    k_scan<<<tiles1 + tiles2, TB>>>(deg1, NDT, rp1, fill1, part1, tiles1,
                                    deg2, NOD, rp2, fill2, part2, tiles2, scnt);
    k_reorder2<<<cdiv(E1 + E2, TB), TB>>>(r1, c1, E1, rp1, fill1, es1,
                                          rsrc, rdst, E2, rp2, fill2, es2);

    // ---- pipeline ----
    k_aggh2<<<cdiv((long long)NDT * 32, TB), TB>>>(
        xdth, es1, rp1, acc1, NDT, nullptr, nullptr, nullptr, nullptr, 0);

    GemmProb ph  = {acc1, 128, xdth, 128, WT(0), WT(1), od1_b, h,  NDT, 1};
    GemmProb pd1 = {acc1, 128, xdth, 128, WT(2), WT(3), dt1_b, d1, NDT, 1};
    gemm_h<128, 128><<<dim3(cdiv(NDT, 128), 2), 256>>>(ph, pd1);

    k_aggh2<<<cdiv((long long)(NOD + NDT) * 32, TB), TB>>>(
        h, es2, rp2, acc2, NOD, d1, es1, rp1, acc3, NDT);

    GemmProb pod2 = {acc2, 128, xodh, 64, WT(4), WT(5), od2_b, od2b, NOD, 1};
    gemm_h<128, 64><<<dim3(cdiv(NOD, 64), 1), 256>>>(pod2, pod2);

    ChainProb cod = {acc2, 128, od2b, 128, WT(6), WT(7), od3_b, WT(8), od_lb, zodh, NOD};
    ChainProb cdt = {acc3, 128, d1, 128, WT(9), WT(10), dt2_b, WT(11), dt_lb, zdth, NDT};
    chain_h<<<dim3(cdiv(NDT, 128), 2), 512>>>(cdt, cod);

    dec_h<<<cdiv(EL, 128), 512>>>(EL, zodh, zdth, elsrc, eldst,
                                  WT(12), dec_b1, dec_w2, dec_b2, out);
}